// round 3
// baseline (speedup 1.0000x reference)
#include <cuda_runtime.h>
#include <math.h>

#define BB 4
#define NN 8192
#define DD 512
#define HH 8
#define DHH 64
#define MM 256
#define GG 32           // BB*HH
#define TROWS 32768     // BB*NN
#define NSPLIT 16

// ---------------- static device scratch ----------------
__device__ float g_ln[(size_t)TROWS * DD];
__device__ float g_q[(size_t)GG * NN * DHH];
__device__ float g_k[(size_t)GG * NN * DHH];
__device__ float g_v[(size_t)GG * NN * DHH];
__device__ float g_ql[GG * MM * DHH];
__device__ float g_kl[GG * MM * DHH];
__device__ float g_s1[(size_t)GG * NN * MM];   // q @ kl^T
__device__ float g_s3[(size_t)GG * MM * NN];   // ql @ k^T
__device__ float g_s2[GG * MM * MM];
__device__ float g_a2[GG * MM * MM];
__device__ float g_zA[GG * MM * MM];
__device__ float g_zB[GG * MM * MM];
__device__ float g_t1[GG * MM * MM];
__device__ float g_t2[GG * MM * MM];
__device__ float g_t3[GG * MM * MM];
__device__ float g_part[GG * NSPLIT * MM * DHH];
__device__ float g_kv[GG * MM * DHH];
__device__ float g_Dm[GG * MM * DHH];
__device__ float g_o1[(size_t)GG * NN * DHH];
__device__ float g_ao[(size_t)TROWS * DD];
__device__ float2 g_stat1[GG * NN];
__device__ float2 g_stat2[GG * MM];
__device__ float2 g_stat3[GG * MM];
__device__ int    g_scaleI[2];

// ---------------- layernorm ----------------
__global__ void ln_kernel(const float* __restrict__ x, const float* __restrict__ gamma,
                          const float* __restrict__ beta, float* __restrict__ out) {
    int row = blockIdx.x;
    const float* xr = x + (size_t)row * DD;
    int t = threadIdx.x;
    float v0 = xr[t], v1 = xr[t + 256];
    float s = v0 + v1, ss = v0 * v0 + v1 * v1;
    #pragma unroll
    for (int o = 16; o; o >>= 1) {
        s  += __shfl_down_sync(0xffffffffu, s, o);
        ss += __shfl_down_sync(0xffffffffu, ss, o);
    }
    __shared__ float rs[8], rss[8];
    int w = t >> 5, l = t & 31;
    if (l == 0) { rs[w] = s; rss[w] = ss; }
    __syncthreads();
    __shared__ float s_mu, s_rstd;
    if (t == 0) {
        float a = 0.f, b = 0.f;
        #pragma unroll
        for (int i = 0; i < 8; i++) { a += rs[i]; b += rss[i]; }
        float mu = a * (1.f / DD);
        float var = b * (1.f / DD) - mu * mu;
        s_mu = mu; s_rstd = rsqrtf(var + 1e-5f);
    }
    __syncthreads();
    float mu = s_mu, rstd = s_rstd;
    float* orow = out + (size_t)row * DD;
    orow[t]       = (v0 - mu) * rstd * gamma[t]       + beta[t];
    orow[t + 256] = (v1 - mu) * rstd * gamma[t + 256] + beta[t + 256];
}

// ---------------- big SGEMM 128x128x8, 256 thr, 8x8 micro ----------------
// MODE 0: C = A@B scattered into q/k/v head layout (q scaled 0.125)
// MODE 1: out = A@B + xres + bias
template <int MODE>
__global__ void sgemm128_kernel(const float* __restrict__ A, const float* __restrict__ Bm,
                                int Kdim, int Ncols,
                                const float* __restrict__ xres, const float* __restrict__ bias,
                                float* __restrict__ outp,
                                float* __restrict__ oq, float* __restrict__ ok, float* __restrict__ ov) {
    __shared__ float As[8 * 128];
    __shared__ float Bs[8 * 128];
    int tid = threadIdx.x;
    int brow = blockIdx.y * 128, bcol = blockIdx.x * 128;
    int ty = tid >> 4, tx = tid & 15;
    float acc[8][8];
    #pragma unroll
    for (int i = 0; i < 8; i++)
        #pragma unroll
        for (int j = 0; j < 8; j++) acc[i][j] = 0.f;

    int arow = tid >> 1, ak = (tid & 1) * 4;
    int bkr = tid >> 5, bc = (tid & 31) * 4;

    for (int k0 = 0; k0 < Kdim; k0 += 8) {
        float4 av = *(const float4*)&A[(size_t)(brow + arow) * Kdim + k0 + ak];
        As[(ak + 0) * 128 + arow] = av.x;
        As[(ak + 1) * 128 + arow] = av.y;
        As[(ak + 2) * 128 + arow] = av.z;
        As[(ak + 3) * 128 + arow] = av.w;
        float4 bv = *(const float4*)&Bm[(size_t)(k0 + bkr) * Ncols + bcol + bc];
        *(float4*)&Bs[bkr * 128 + bc] = bv;
        __syncthreads();
        #pragma unroll
        for (int kk = 0; kk < 8; kk++) {
            float a[8], b[8];
            *(float4*)(a)     = *(float4*)&As[kk * 128 + ty * 8];
            *(float4*)(a + 4) = *(float4*)&As[kk * 128 + ty * 8 + 4];
            *(float4*)(b)     = *(float4*)&Bs[kk * 128 + tx * 8];
            *(float4*)(b + 4) = *(float4*)&Bs[kk * 128 + tx * 8 + 4];
            #pragma unroll
            for (int i = 0; i < 8; i++)
                #pragma unroll
                for (int j = 0; j < 8; j++) acc[i][j] += a[i] * b[j];
        }
        __syncthreads();
    }

    #pragma unroll
    for (int i = 0; i < 8; i++) {
        int r = brow + ty * 8 + i;
        if (MODE == 0) {
            int bidx = r >> 13, n = r & 8191;
            #pragma unroll
            for (int j = 0; j < 8; j++) {
                int c = bcol + tx * 8 + j;
                int part = c >> 9;
                int h = (c >> 6) & 7;
                int d = c & 63;
                size_t dst = (((size_t)(bidx * HH + h)) * NN + n) * DHH + d;
                float val = acc[i][j];
                if (part == 0)      oq[dst] = val * 0.125f;
                else if (part == 1) ok[dst] = val;
                else                ov[dst] = val;
            }
        } else {
            size_t o = (size_t)r * Ncols + bcol + tx * 8;
            #pragma unroll
            for (int j = 0; j < 8; j++) {
                int c = bcol + tx * 8 + j;
                outp[o + j] = acc[i][j] + xres[o + j] + bias[c];
            }
        }
    }
}

// ---------------- landmark means ----------------
__global__ void landmark_kernel(const float* __restrict__ q, const float* __restrict__ k,
                                float* __restrict__ ql, float* __restrict__ kl) {
    int g = blockIdx.y, m = blockIdx.x, d = threadIdx.x;
    const float* qp = q + ((size_t)g * NN + m * 32) * DHH + d;
    const float* kp = k + ((size_t)g * NN + m * 32) * DHH + d;
    float sq = 0.f, sk = 0.f;
    #pragma unroll
    for (int i = 0; i < 32; i++) { sq += qp[i * DHH]; sk += kp[i * DHH]; }
    ql[(g * MM + m) * DHH + d] = sq * (1.f / 32.f);
    kl[(g * MM + m) * DHH + d] = sk * (1.f / 32.f);
}

// ---------------- NT gemm over dh=64: C[g][r][c] = dot(A[g][r,:], B[g][c,:]) ----
__global__ void gemm_nt_kernel(const float* __restrict__ A, const float* __restrict__ Bm,
                               float* __restrict__ C, int RA, int RB) {
    __shared__ float As[32 * 132];
    __shared__ float Bs[32 * 132];
    int t = threadIdx.x;
    int g = blockIdx.z;
    int gr0 = blockIdx.y * 128, gc0 = blockIdx.x * 128;
    int ty = t >> 4, tx = t & 15;
    float acc[8][8];
    #pragma unroll
    for (int i = 0; i < 8; i++)
        #pragma unroll
        for (int j = 0; j < 8; j++) acc[i][j] = 0.f;

    for (int k0 = 0; k0 < 64; k0 += 32) {
        #pragma unroll
        for (int i = 0; i < 4; i++) {
            int slot = t + i * 256;
            int r = slot >> 3, k4 = (slot & 7) * 4;
            float4 a4 = *(const float4*)&A[((size_t)g * RA + gr0 + r) * DHH + k0 + k4];
            As[(k4 + 0) * 132 + r] = a4.x;
            As[(k4 + 1) * 132 + r] = a4.y;
            As[(k4 + 2) * 132 + r] = a4.z;
            As[(k4 + 3) * 132 + r] = a4.w;
            float4 b4 = *(const float4*)&Bm[((size_t)g * RB + gc0 + r) * DHH + k0 + k4];
            Bs[(k4 + 0) * 132 + r] = b4.x;
            Bs[(k4 + 1) * 132 + r] = b4.y;
            Bs[(k4 + 2) * 132 + r] = b4.z;
            Bs[(k4 + 3) * 132 + r] = b4.w;
        }
        __syncthreads();
        #pragma unroll
        for (int kk = 0; kk < 32; kk++) {
            float a[8], b[8];
            *(float4*)(a)     = *(float4*)&As[kk * 132 + ty * 8];
            *(float4*)(a + 4) = *(float4*)&As[kk * 132 + ty * 8 + 4];
            *(float4*)(b)     = *(float4*)&Bs[kk * 132 + tx * 8];
            *(float4*)(b + 4) = *(float4*)&Bs[kk * 132 + tx * 8 + 4];
            #pragma unroll
            for (int i = 0; i < 8; i++)
                #pragma unroll
                for (int j = 0; j < 8; j++) acc[i][j] += a[i] * b[j];
        }
        __syncthreads();
    }

    #pragma unroll
    for (int i = 0; i < 8; i++) {
        size_t o = ((size_t)g * RA + gr0 + ty * 8 + i) * RB + gc0 + tx * 8;
        *(float4*)&C[o]     = make_float4(acc[i][0], acc[i][1], acc[i][2], acc[i][3]);
        *(float4*)&C[o + 4] = make_float4(acc[i][4], acc[i][5], acc[i][6], acc[i][7]);
    }
}

// ---------------- row softmax stats (online max / sumexp) ----------------
__global__ void rowstat_kernel(const float* __restrict__ S, float2* __restrict__ stat, int NC) {
    long long row = blockIdx.x;
    const float* p = S + row * (long long)NC;
    int t = threadIdx.x;
    float tm = -1e30f, ts = 0.f;
    for (int c = t; c < NC; c += 256) {
        float v = p[c];
        if (v > tm) { ts = ts * __expf(tm - v) + 1.f; tm = v; }
        else ts += __expf(v - tm);
    }
    #pragma unroll
    for (int o = 16; o; o >>= 1) {
        float om = __shfl_down_sync(0xffffffffu, tm, o);
        float os = __shfl_down_sync(0xffffffffu, ts, o);
        float nm = fmaxf(tm, om);
        ts = ts * __expf(tm - nm) + os * __expf(om - nm);
        tm = nm;
    }
    __shared__ float smx[8], ssm[8];
    if ((t & 31) == 0) { smx[t >> 5] = tm; ssm[t >> 5] = ts; }
    __syncthreads();
    if (t == 0) {
        tm = smx[0]; ts = ssm[0];
        #pragma unroll
        for (int w = 1; w < 8; w++) {
            float om = smx[w], os = ssm[w];
            float nm = fmaxf(tm, om);
            ts = ts * __expf(tm - nm) + os * __expf(om - nm);
            tm = nm;
        }
        stat[row] = make_float2(tm, 1.f / ts);
    }
}

// NC=256 only (sim2)
__global__ void apply_softmax_kernel(const float* __restrict__ S, const float2* __restrict__ stat,
                                     float* __restrict__ out) {
    long long i = (long long)blockIdx.x * 256 + threadIdx.x;
    float2 st = stat[i >> 8];
    out[i] = __expf(S[i] - st.x) * st.y;
}

// ---------------- pinv init ----------------
__global__ void zero_scale_kernel() { if (threadIdx.x < 2) g_scaleI[threadIdx.x] = 0; }

__global__ void pinv_reduce_kernel() {
    int g = blockIdx.x, j = threadIdx.x;
    const float* a = g_a2 + (long long)g * MM * MM;
    float rs = 0.f, cs = 0.f;
    for (int c = 0; c < MM; c++) { rs += a[j * MM + c]; cs += a[c * MM + j]; }
    __shared__ float r0[256], r1[256];
    r0[j] = rs; r1[j] = cs;
    __syncthreads();
    for (int o = 128; o; o >>= 1) {
        if (j < o) { r0[j] = fmaxf(r0[j], r0[j + o]); r1[j] = fmaxf(r1[j], r1[j + o]); }
        __syncthreads();
    }
    if (j == 0) {
        atomicMax(&g_scaleI[0], __float_as_int(r0[0]));
        atomicMax(&g_scaleI[1], __float_as_int(r1[0]));
    }
}

__global__ void z_init_kernel() {
    long long i = (long long)blockIdx.x * 256 + threadIdx.x;
    float scale = 1.f / (__int_as_float(g_scaleI[0]) * __int_as_float(g_scaleI[1]));
    int g = (int)(i >> 16), r = (int)((i >> 8) & 255), c = (int)(i & 255);
    g_zA[i] = g_a2[((long long)g << 16) + (c << 8) + r] * scale;
}

// ---------------- batched 256-K gemm, fused diag transforms ----------------
// C = c0*I + c1 * ( A @ (b0*I + b1*B) );  A:[g][256][256], B:[g][256][NC]
__global__ void gemm_b256_kernel(const float* __restrict__ A, const float* __restrict__ Bm,
                                 float* __restrict__ C, int NC,
                                 float b0, float b1, float c0, float c1) {
    __shared__ float As[32 * 132];
    __shared__ float Bs[32 * 68];
    int t = threadIdx.x, g = blockIdx.z;
    int gr0 = blockIdx.y * 128, gc0 = blockIdx.x * 64;
    int ty = t >> 4, tx = t & 15;
    const float* Ag = A + (long long)g * MM * MM;
    const float* Bg = Bm + (long long)g * MM * NC;
    float acc[8][4];
    #pragma unroll
    for (int i = 0; i < 8; i++)
        #pragma unroll
        for (int j = 0; j < 4; j++) acc[i][j] = 0.f;

    for (int k0 = 0; k0 < MM; k0 += 32) {
        #pragma unroll
        for (int i = 0; i < 4; i++) {
            int slot = t + i * 256;
            int r = slot >> 3, k4 = (slot & 7) * 4;
            float4 a4 = *(const float4*)&Ag[(size_t)(gr0 + r) * MM + k0 + k4];
            As[(k4 + 0) * 132 + r] = a4.x;
            As[(k4 + 1) * 132 + r] = a4.y;
            As[(k4 + 2) * 132 + r] = a4.z;
            As[(k4 + 3) * 132 + r] = a4.w;
        }
        #pragma unroll
        for (int i = 0; i < 2; i++) {
            int slot = t + i * 256;
            int kr = slot >> 4, c4 = (slot & 15) * 4;
            float4 b4 = *(const float4*)&Bg[(size_t)(k0 + kr) * NC + gc0 + c4];
            int kg = k0 + kr;
            float vv[4] = {b4.x, b4.y, b4.z, b4.w};
            #pragma unroll
            for (int u = 0; u < 4; u++) {
                int c = gc0 + c4 + u;
                vv[u] = b1 * vv[u] + (kg == c ? b0 : 0.f);
            }
            *(float4*)&Bs[kr * 68 + c4] = make_float4(vv[0], vv[1], vv[2], vv[3]);
        }
        __syncthreads();
        #pragma unroll
        for (int kk = 0; kk < 32; kk++) {
            float a[8], b[4];
            *(float4*)(a)     = *(float4*)&As[kk * 132 + ty * 8];
            *(float4*)(a + 4) = *(float4*)&As[kk * 132 + ty * 8 + 4];
            *(float4*)(b)     = *(float4*)&Bs[kk * 68 + tx * 4];
            #pragma unroll
            for (int i = 0; i < 8; i++)
                #pragma unroll
                for (int j = 0; j < 4; j++) acc[i][j] += a[i] * b[j];
        }
        __syncthreads();
    }
    #pragma unroll
    for (int i = 0; i < 8; i++) {
        int r = gr0 + ty * 8 + i;
        float o[4];
        #pragma unroll
        for (int j = 0; j < 4; j++) {
            int c = gc0 + tx * 4 + j;
            o[j] = c1 * acc[i][j] + (r == c ? c0 : 0.f);
        }
        *(float4*)&C[((long long)g * MM + r) * NC + gc0 + tx * 4] = make_float4(o[0], o[1], o[2], o[3]);
    }
}

// ---------------- exp-on-load gemm: out = softmax(S) @ Bv (split-K) ----------
__global__ void gemm_ns_kernel(const float* __restrict__ S, const float2* __restrict__ stat,
                               const float* __restrict__ Bv, float* __restrict__ out,
                               int RA, int Kfull, int nsplit) {
    __shared__ float As[32 * 132];
    __shared__ float Bs[32 * 68];
    int t = threadIdx.x, g = blockIdx.z;
    int split = blockIdx.x;
    int gr0 = blockIdx.y * 128;
    int klen = Kfull / nsplit;
    int kst = split * klen;
    int ty = t >> 4, tx = t & 15;
    float acc[8][4];
    #pragma unroll
    for (int i = 0; i < 8; i++)
        #pragma unroll
        for (int j = 0; j < 4; j++) acc[i][j] = 0.f;

    for (int k0 = 0; k0 < klen; k0 += 32) {
        #pragma unroll
        for (int i = 0; i < 4; i++) {
            int slot = t + i * 256;
            int r = slot >> 3, k4 = (slot & 7) * 4;
            long long row = (long long)g * RA + gr0 + r;
            float4 a4 = *(const float4*)&S[row * Kfull + kst + k0 + k4];
            float2 st = stat[row];
            As[(k4 + 0) * 132 + r] = __expf(a4.x - st.x) * st.y;
            As[(k4 + 1) * 132 + r] = __expf(a4.y - st.x) * st.y;
            As[(k4 + 2) * 132 + r] = __expf(a4.z - st.x) * st.y;
            As[(k4 + 3) * 132 + r] = __expf(a4.w - st.x) * st.y;
        }
        #pragma unroll
        for (int i = 0; i < 2; i++) {
            int slot = t + i * 256;
            int kr = slot >> 4, c4 = (slot & 15) * 4;
            float4 b4 = *(const float4*)&Bv[((long long)g * Kfull + kst + k0 + kr) * DHH + c4];
            *(float4*)&Bs[kr * 68 + c4] = b4;
        }
        __syncthreads();
        #pragma unroll
        for (int kk = 0; kk < 32; kk++) {
            float a[8], b[4];
            *(float4*)(a)     = *(float4*)&As[kk * 132 + ty * 8];
            *(float4*)(a + 4) = *(float4*)&As[kk * 132 + ty * 8 + 4];
            *(float4*)(b)     = *(float4*)&Bs[kk * 68 + tx * 4];
            #pragma unroll
            for (int i = 0; i < 8; i++)
                #pragma unroll
                for (int j = 0; j < 4; j++) acc[i][j] += a[i] * b[j];
        }
        __syncthreads();
    }
    #pragma unroll
    for (int i = 0; i < 8; i++) {
        long long o = (((long long)g * nsplit + split) * RA + gr0 + ty * 8 + i) * DHH + tx * 4;
        *(float4*)&out[o] = make_float4(acc[i][0], acc[i][1], acc[i][2], acc[i][3]);
    }
}

__global__ void reduce16_kernel() {
    long long i = (long long)blockIdx.x * 256 + threadIdx.x;  // GG*MM*DHH
    int g = (int)(i / (MM * DHH));
    int rc = (int)(i % (MM * DHH));
    float s = 0.f;
    #pragma unroll
    for (int sp = 0; sp < NSPLIT; sp++)
        s += g_part[((long long)(g * NSPLIT + sp)) * MM * DHH + rc];
    g_kv[i] = s;
}

// ---------------- depthwise conv-33 over seq + head merge ----------------
__global__ void conv_combine_kernel(const float* __restrict__ v, const float* __restrict__ o1,
                                    const float* __restrict__ cw, float* __restrict__ ao) {
    int g = blockIdx.y;
    int h = g & 7, b = g >> 3;
    int n0 = blockIdx.x * 64;
    __shared__ float sv[96 * 64];
    __shared__ float ws[33];
    int t = threadIdx.x;
    if (t < 33) ws[t] = cw[h * 33 + t];
    const float* vg = v + (size_t)g * NN * DHH;
    for (int i = t; i < 96 * 64; i += 256) {
        int r = i >> 6, d = i & 63;
        int n = n0 - 16 + r;
        sv[i] = (n >= 0 && n < NN) ? vg[(size_t)n * DHH + d] : 0.f;
    }
    __syncthreads();
    int d = t & 63, nl0 = t >> 6;
    for (int i = 0; i < 16; i++) {
        int nl = nl0 + i * 4;
        float acc = 0.f;
        #pragma unroll
        for (int kk = 0; kk < 33; kk++) acc += ws[kk] * sv[(nl + kk) * 64 + d];
        int n = n0 + nl;
        ao[((size_t)b * NN + n) * DD + h * 64 + d] =
            o1[((size_t)g * NN + n) * DHH + d] + acc;
    }
}

// ---------------- host ----------------
static float* symf(const void* s) { void* p = 0; cudaGetSymbolAddress(&p, s); return (float*)p; }

extern "C" void kernel_launch(void* const* d_in, const int* in_sizes, int n_in,
                              void* d_out, int out_size) {
    const float* x      = (const float*)d_in[0];
    const float* gamma  = (const float*)d_in[1];
    const float* beta   = (const float*)d_in[2];
    const float* w_qkv  = (const float*)d_in[3];
    const float* w_out  = (const float*)d_in[4];
    const float* b_out  = (const float*)d_in[5];
    const float* conv_w = (const float*)d_in[6];
    float* out = (float*)d_out;

    float* ln   = symf(g_ln);
    float* q    = symf(g_q);
    float* k    = symf(g_k);
    float* v    = symf(g_v);
    float* ql   = symf(g_ql);
    float* kl   = symf(g_kl);
    float* s1   = symf(g_s1);
    float* s2   = symf(g_s2);
    float* s3   = symf(g_s3);
    float* a2   = symf(g_a2);
    float* zA   = symf(g_zA);
    float* zB   = symf(g_zB);
    float* t1   = symf(g_t1);
    float* t2   = symf(g_t2);
    float* t3   = symf(g_t3);
    float* part = symf(g_part);
    float* kv   = symf(g_kv);
    float* Dm   = symf(g_Dm);
    float* o1   = symf(g_o1);
    float* ao   = symf(g_ao);
    float2* st1 = (float2*)symf(g_stat1);
    float2* st2 = (float2*)symf(g_stat2);
    float2* st3 = (float2*)symf(g_stat3);

    // 1. layernorm
    ln_kernel<<<TROWS, 256>>>(x, gamma, beta, ln);

    // 2. qkv gemm with head scatter + q scale
    sgemm128_kernel<0><<<dim3(12, 256), 256>>>(ln, w_qkv, DD, 3 * DD, 0, 0, 0, q, k, v);

    // 3. landmarks
    landmark_kernel<<<dim3(MM, GG), 64>>>(q, k, ql, kl);

    // 4. similarity scores
    gemm_nt_kernel<<<dim3(2, 64, GG), 256>>>(q, kl, s1, NN, MM);   // [n,256]
    gemm_nt_kernel<<<dim3(2, 2, GG), 256>>>(ql, kl, s2, MM, MM);   // [256,256]
    gemm_nt_kernel<<<dim3(64, 2, GG), 256>>>(ql, k, s3, MM, NN);   // [256,n]

    // 5. softmax stats
    rowstat_kernel<<<GG * NN, 256>>>(s1, st1, MM);
    rowstat_kernel<<<GG * MM, 256>>>(s2, st2, MM);
    rowstat_kernel<<<GG * MM, 256>>>(s3, st3, NN);
    apply_softmax_kernel<<<GG * MM * MM / 256, 256>>>(s2, st2, a2);

    // 6. pinv init: z = a2^T / (max rowsum * max colsum)
    zero_scale_kernel<<<1, 32>>>();
    pinv_reduce_kernel<<<GG, 256>>>();
    z_init_kernel<<<GG * MM * MM / 256, 256>>>();

    // 7. Newton-Schulz: z = 0.25 z (13I - X(15I - X(7I - X))), X = a2 z
    for (int it = 0; it < 6; it++) {
        float* zin  = (it & 1) ? zB : zA;
        float* zout = (it & 1) ? zA : zB;
        gemm_b256_kernel<<<dim3(4, 2, GG), 256>>>(a2,  zin, t1, MM, 0.f,  1.f, 0.f, 1.f);
        gemm_b256_kernel<<<dim3(4, 2, GG), 256>>>(t1,  t1,  t2, MM, 7.f, -1.f, 0.f, 1.f);
        gemm_b256_kernel<<<dim3(4, 2, GG), 256>>>(t1,  t2,  t3, MM, 15.f, -1.f, 0.f, 1.f);
        gemm_b256_kernel<<<dim3(4, 2, GG), 256>>>(zin, t3, zout, MM, 13.f, -1.f, 0.f, 0.25f);
    }
    float* zfin = zA;  // after 6 iterations result is in zA

    // 8. kv = softmax(s3) @ v  (split-K deterministic)
    gemm_ns_kernel<<<dim3(NSPLIT, 2, GG), 256>>>(s3, st3, v, part, MM, NN, NSPLIT);
    reduce16_kernel<<<GG * MM * DHH / 256, 256>>>();

    // 9. Dm = pinv @ kv
    gemm_b256_kernel<<<dim3(1, 2, GG), 256>>>(zfin, kv, Dm, DHH, 0.f, 1.f, 0.f, 1.f);

    // 10. o1 = softmax(s1) @ Dm
    gemm_ns_kernel<<<dim3(1, 64, GG), 256>>>(s1, st1, Dm, o1, NN, MM, 1);

    // 11. conv residual + merge heads
    conv_combine_kernel<<<dim3(NN / 64, GG), 256>>>(v, o1, conv_w, ao);

    // 12. final: out = ao @ w_out + b_out + x
    sgemm128_kernel<1><<<dim3(4, 256), 256>>>(ao, w_out, DD, DD, x, b_out, out, 0, 0, 0);
}

// round 5
// speedup vs baseline: 1.7146x; 1.7146x over previous
#include <cuda_runtime.h>
#include <math.h>
#include <stdint.h>

#define BB 4
#define NN 8192
#define DD 512
#define HH 8
#define DHH 64
#define MM 256
#define GG 32           // BB*HH
#define TROWS 32768     // BB*NN
#define NSPLIT 16

// ---------------- static device scratch ----------------
__device__ float g_ln[(size_t)TROWS * DD];
__device__ float g_q[(size_t)GG * NN * DHH];
__device__ float g_k[(size_t)GG * NN * DHH];
__device__ float g_v[(size_t)GG * NN * DHH];
__device__ float g_ql[GG * MM * DHH];
__device__ float g_kl[GG * MM * DHH];
__device__ float g_s1[(size_t)GG * NN * MM];   // q @ kl^T
__device__ float g_s3[(size_t)GG * MM * NN];   // ql @ k^T
__device__ float g_s2[GG * MM * MM];
__device__ float g_a2[GG * MM * MM];
__device__ float g_zA[GG * MM * MM];
__device__ float g_zB[GG * MM * MM];
__device__ float g_t1[GG * MM * MM];
__device__ float g_t2[GG * MM * MM];
__device__ float g_t3[GG * MM * MM];
__device__ float g_part[GG * NSPLIT * MM * DHH];
__device__ float g_kv[GG * MM * DHH];
__device__ float g_Dm[GG * MM * DHH];
__device__ float g_o1[(size_t)GG * NN * DHH];
__device__ float g_ao[(size_t)TROWS * DD];
__device__ float2 g_stat1[GG * NN];
__device__ float2 g_stat2[GG * MM];
__device__ float2 g_stat3[GG * MM];
__device__ int    g_scaleI[2];

// ---------------- tf32 helpers ----------------
__device__ __forceinline__ uint32_t f2tf(float x) {
    uint32_t r;
    asm("cvt.rna.tf32.f32 %0, %1;" : "=r"(r) : "f"(x));
    return r;
}

__device__ __forceinline__ void mma8(float* d, const uint32_t* a, const uint32_t* b) {
    asm volatile(
        "mma.sync.aligned.m16n8k8.row.col.f32.tf32.tf32.f32 "
        "{%0,%1,%2,%3}, {%4,%5,%6,%7}, {%8,%9}, {%0,%1,%2,%3};"
        : "+f"(d[0]), "+f"(d[1]), "+f"(d[2]), "+f"(d[3])
        : "r"(a[0]), "r"(a[1]), "r"(a[2]), "r"(a[3]), "r"(b[0]), "r"(b[1]));
}

// ---------------- layernorm ----------------
__global__ void ln_kernel(const float* __restrict__ x, const float* __restrict__ gamma,
                          const float* __restrict__ beta, float* __restrict__ out) {
    int row = blockIdx.x;
    const float* xr = x + (size_t)row * DD;
    int t = threadIdx.x;
    float v0 = xr[t], v1 = xr[t + 256];
    float s = v0 + v1, ss = v0 * v0 + v1 * v1;
    #pragma unroll
    for (int o = 16; o; o >>= 1) {
        s  += __shfl_down_sync(0xffffffffu, s, o);
        ss += __shfl_down_sync(0xffffffffu, ss, o);
    }
    __shared__ float rs[8], rss[8];
    int w = t >> 5, l = t & 31;
    if (l == 0) { rs[w] = s; rss[w] = ss; }
    __syncthreads();
    __shared__ float s_mu, s_rstd;
    if (t == 0) {
        float a = 0.f, b = 0.f;
        #pragma unroll
        for (int i = 0; i < 8; i++) { a += rs[i]; b += rss[i]; }
        float mu = a * (1.f / DD);
        float var = b * (1.f / DD) - mu * mu;
        s_mu = mu; s_rstd = rsqrtf(var + 1e-5f);
    }
    __syncthreads();
    float mu = s_mu, rstd = s_rstd;
    float* orow = out + (size_t)row * DD;
    orow[t]       = (v0 - mu) * rstd * gamma[t]       + beta[t];
    orow[t + 256] = (v1 - mu) * rstd * gamma[t + 256] + beta[t + 256];
}

// ---------------- tf32 NN gemm 128x128xK, 256 thr (8 warps 2x4, warp 64x32) --
// MODE 0: C = A@B scattered into q/k/v head layout (q scaled 0.125)
// MODE 1: out = A@B + xres + bias
template <int MODE>
__global__ void tgemm_nn(const float* __restrict__ A, const float* __restrict__ Bm,
                         int Kdim, int Ncols,
                         const float* __restrict__ xres, const float* __restrict__ bias,
                         float* __restrict__ outp,
                         float* __restrict__ oq, float* __restrict__ okk, float* __restrict__ ov) {
    __shared__ uint32_t As[128 * 20];   // [m][k] pad 4
    __shared__ uint32_t Bs[16 * 136];   // [k][n] pad 8
    int t = threadIdx.x;
    int warp = t >> 5, lane = t & 31;
    int wm = warp >> 2, wn = warp & 3;
    int g8 = lane >> 2, tg = lane & 3;
    int brow = blockIdx.y * 128, bcol = blockIdx.x * 128;
    float acc[4][4][4];
    #pragma unroll
    for (int i = 0; i < 4; i++)
        #pragma unroll
        for (int j = 0; j < 4; j++)
            #pragma unroll
            for (int r = 0; r < 4; r++) acc[i][j][r] = 0.f;

    for (int k0 = 0; k0 < Kdim; k0 += 16) {
        #pragma unroll
        for (int i = 0; i < 2; i++) {
            int s = t + i * 256;
            int r = s >> 2, kq = (s & 3) * 4;
            float4 v = *(const float4*)&A[(size_t)(brow + r) * Kdim + k0 + kq];
            As[r * 20 + kq + 0] = f2tf(v.x);
            As[r * 20 + kq + 1] = f2tf(v.y);
            As[r * 20 + kq + 2] = f2tf(v.z);
            As[r * 20 + kq + 3] = f2tf(v.w);
        }
        #pragma unroll
        for (int i = 0; i < 2; i++) {
            int s = t + i * 256;
            int kr = s >> 5, nq = (s & 31) * 4;
            float4 v = *(const float4*)&Bm[(size_t)(k0 + kr) * Ncols + bcol + nq];
            Bs[kr * 136 + nq + 0] = f2tf(v.x);
            Bs[kr * 136 + nq + 1] = f2tf(v.y);
            Bs[kr * 136 + nq + 2] = f2tf(v.z);
            Bs[kr * 136 + nq + 3] = f2tf(v.w);
        }
        __syncthreads();
        #pragma unroll
        for (int kk = 0; kk < 16; kk += 8) {
            uint32_t af[4][4], bf[4][2];
            #pragma unroll
            for (int mi = 0; mi < 4; mi++) {
                int rm = wm * 64 + mi * 16;
                af[mi][0] = As[(rm + g8)     * 20 + kk + tg];
                af[mi][1] = As[(rm + g8 + 8) * 20 + kk + tg];
                af[mi][2] = As[(rm + g8)     * 20 + kk + tg + 4];
                af[mi][3] = As[(rm + g8 + 8) * 20 + kk + tg + 4];
            }
            #pragma unroll
            for (int ni = 0; ni < 4; ni++) {
                int nb = wn * 32 + ni * 8 + g8;
                bf[ni][0] = Bs[(kk + tg)     * 136 + nb];
                bf[ni][1] = Bs[(kk + tg + 4) * 136 + nb];
            }
            #pragma unroll
            for (int mi = 0; mi < 4; mi++)
                #pragma unroll
                for (int ni = 0; ni < 4; ni++)
                    mma8(acc[mi][ni], af[mi], bf[ni]);
        }
        __syncthreads();
    }

    #pragma unroll
    for (int mi = 0; mi < 4; mi++) {
        #pragma unroll
        for (int ni = 0; ni < 4; ni++) {
            int c = bcol + wn * 32 + ni * 8 + tg * 2;
            #pragma unroll
            for (int half = 0; half < 2; half++) {
                int r = brow + wm * 64 + mi * 16 + g8 + half * 8;
                float v0 = acc[mi][ni][half * 2 + 0];
                float v1 = acc[mi][ni][half * 2 + 1];
                if (MODE == 0) {
                    int part = c >> 9, h = (c >> 6) & 7, d = c & 63;
                    int bidx = r >> 13, n = r & 8191;
                    size_t dst = (((size_t)(bidx * HH + h)) * NN + n) * DHH + d;
                    if (part == 0)      { oq[dst] = v0 * 0.125f; oq[dst + 1] = v1 * 0.125f; }
                    else if (part == 1) { okk[dst] = v0;         okk[dst + 1] = v1; }
                    else                { ov[dst] = v0;          ov[dst + 1] = v1; }
                } else {
                    size_t o = (size_t)r * Ncols + c;
                    outp[o]     = v0 + xres[o]     + bias[c];
                    outp[o + 1] = v1 + xres[o + 1] + bias[c + 1];
                }
            }
        }
    }
}

// ---------------- landmark means ----------------
__global__ void landmark_kernel(const float* __restrict__ q, const float* __restrict__ k,
                                float* __restrict__ ql, float* __restrict__ kl) {
    int g = blockIdx.y, m = blockIdx.x, d = threadIdx.x;
    const float* qp = q + ((size_t)g * NN + m * 32) * DHH + d;
    const float* kp = k + ((size_t)g * NN + m * 32) * DHH + d;
    float sq = 0.f, sk = 0.f;
    #pragma unroll
    for (int i = 0; i < 32; i++) { sq += qp[i * DHH]; sk += kp[i * DHH]; }
    ql[(g * MM + m) * DHH + d] = sq * (1.f / 32.f);
    kl[(g * MM + m) * DHH + d] = sk * (1.f / 32.f);
}

// ---------------- tf32 NT gemm over dh=64: C = A @ B^T ----------------
// A[g][RA][64], B[g][RB][64] row-major; 128x128 tile, 256 thr.
__global__ void tgemm_nt(const float* __restrict__ A, const float* __restrict__ Bm,
                         float* __restrict__ C, int RA, int RB) {
    __shared__ uint32_t As[128 * 20];   // [m][k] pad 4
    __shared__ uint32_t Bs[128 * 20];   // [n][k] pad 4
    int t = threadIdx.x, g = blockIdx.z;
    int warp = t >> 5, lane = t & 31;
    int wm = warp >> 2, wn = warp & 3;
    int g8 = lane >> 2, tg = lane & 3;
    int gr0 = blockIdx.y * 128, gc0 = blockIdx.x * 128;
    float acc[4][4][4];
    #pragma unroll
    for (int i = 0; i < 4; i++)
        #pragma unroll
        for (int j = 0; j < 4; j++)
            #pragma unroll
            for (int r = 0; r < 4; r++) acc[i][j][r] = 0.f;

    for (int k0 = 0; k0 < 64; k0 += 16) {
        #pragma unroll
        for (int i = 0; i < 2; i++) {
            int s = t + i * 256;
            int r = s >> 2, kq = (s & 3) * 4;
            float4 va = *(const float4*)&A[((size_t)g * RA + gr0 + r) * DHH + k0 + kq];
            As[r * 20 + kq + 0] = f2tf(va.x);
            As[r * 20 + kq + 1] = f2tf(va.y);
            As[r * 20 + kq + 2] = f2tf(va.z);
            As[r * 20 + kq + 3] = f2tf(va.w);
            float4 vb = *(const float4*)&Bm[((size_t)g * RB + gc0 + r) * DHH + k0 + kq];
            Bs[r * 20 + kq + 0] = f2tf(vb.x);
            Bs[r * 20 + kq + 1] = f2tf(vb.y);
            Bs[r * 20 + kq + 2] = f2tf(vb.z);
            Bs[r * 20 + kq + 3] = f2tf(vb.w);
        }
        __syncthreads();
        #pragma unroll
        for (int kk = 0; kk < 16; kk += 8) {
            uint32_t af[4][4], bf[4][2];
            #pragma unroll
            for (int mi = 0; mi < 4; mi++) {
                int rm = wm * 64 + mi * 16;
                af[mi][0] = As[(rm + g8)     * 20 + kk + tg];
                af[mi][1] = As[(rm + g8 + 8) * 20 + kk + tg];
                af[mi][2] = As[(rm + g8)     * 20 + kk + tg + 4];
                af[mi][3] = As[(rm + g8 + 8) * 20 + kk + tg + 4];
            }
            #pragma unroll
            for (int ni = 0; ni < 4; ni++) {
                int nb = wn * 32 + ni * 8 + g8;
                bf[ni][0] = Bs[nb * 20 + kk + tg];
                bf[ni][1] = Bs[nb * 20 + kk + tg + 4];
            }
            #pragma unroll
            for (int mi = 0; mi < 4; mi++)
                #pragma unroll
                for (int ni = 0; ni < 4; ni++)
                    mma8(acc[mi][ni], af[mi], bf[ni]);
        }
        __syncthreads();
    }

    #pragma unroll
    for (int mi = 0; mi < 4; mi++) {
        #pragma unroll
        for (int ni = 0; ni < 4; ni++) {
            int c = gc0 + wn * 32 + ni * 8 + tg * 2;
            #pragma unroll
            for (int half = 0; half < 2; half++) {
                int r = gr0 + wm * 64 + mi * 16 + g8 + half * 8;
                size_t o = ((size_t)g * RA + r) * RB + c;
                *(float2*)&C[o] = make_float2(acc[mi][ni][half * 2 + 0],
                                              acc[mi][ni][half * 2 + 1]);
            }
        }
    }
}

// ---------------- row softmax stats (online max / sumexp) ----------------
__global__ void rowstat_kernel(const float* __restrict__ S, float2* __restrict__ stat, int NC) {
    long long row = blockIdx.x;
    const float* p = S + row * (long long)NC;
    int t = threadIdx.x;
    float tm = -1e30f, ts = 0.f;
    for (int c = t; c < NC; c += 256) {
        float v = p[c];
        if (v > tm) { ts = ts * __expf(tm - v) + 1.f; tm = v; }
        else ts += __expf(v - tm);
    }
    #pragma unroll
    for (int o = 16; o; o >>= 1) {
        float om = __shfl_down_sync(0xffffffffu, tm, o);
        float os = __shfl_down_sync(0xffffffffu, ts, o);
        float nm = fmaxf(tm, om);
        ts = ts * __expf(tm - nm) + os * __expf(om - nm);
        tm = nm;
    }
    __shared__ float smx[8], ssm[8];
    if ((t & 31) == 0) { smx[t >> 5] = tm; ssm[t >> 5] = ts; }
    __syncthreads();
    if (t == 0) {
        tm = smx[0]; ts = ssm[0];
        #pragma unroll
        for (int w = 1; w < 8; w++) {
            float om = smx[w], os = ssm[w];
            float nm = fmaxf(tm, om);
            ts = ts * __expf(tm - nm) + os * __expf(om - nm);
            tm = nm;
        }
        stat[row] = make_float2(tm, 1.f / ts);
    }
}

// NC=256 only (sim2)
__global__ void apply_softmax_kernel(const float* __restrict__ S, const float2* __restrict__ stat,
                                     float* __restrict__ out) {
    long long i = (long long)blockIdx.x * 256 + threadIdx.x;
    float2 st = stat[i >> 8];
    out[i] = __expf(S[i] - st.x) * st.y;
}

// ---------------- pinv init ----------------
__global__ void zero_scale_kernel() { if (threadIdx.x < 2) g_scaleI[threadIdx.x] = 0; }

__global__ void pinv_reduce_kernel() {
    int g = blockIdx.x, j = threadIdx.x;
    const float* a = g_a2 + (long long)g * MM * MM;
    float rs = 0.f, cs = 0.f;
    for (int c = 0; c < MM; c++) { rs += a[j * MM + c]; cs += a[c * MM + j]; }
    __shared__ float r0[256], r1[256];
    r0[j] = rs; r1[j] = cs;
    __syncthreads();
    for (int o = 128; o; o >>= 1) {
        if (j < o) { r0[j] = fmaxf(r0[j], r0[j + o]); r1[j] = fmaxf(r1[j], r1[j + o]); }
        __syncthreads();
    }
    if (j == 0) {
        atomicMax(&g_scaleI[0], __float_as_int(r0[0]));
        atomicMax(&g_scaleI[1], __float_as_int(r1[0]));
    }
}

__global__ void z_init_kernel() {
    long long i = (long long)blockIdx.x * 256 + threadIdx.x;
    float scale = 1.f / (__int_as_float(g_scaleI[0]) * __int_as_float(g_scaleI[1]));
    int g = (int)(i >> 16), r = (int)((i >> 8) & 255), c = (int)(i & 255);
    g_zA[i] = g_a2[((long long)g << 16) + (c << 8) + r] * scale;
}

// ---------------- tf32 batched 256-K gemm, fused diag transforms -----------
// C = c0*I + c1 * ( A @ (b0*I + b1*B) );  A:[g][256][256], B:[g][256][NC]
// BM=128 BN=64, 256 thr (8 warps 2x4, warp 64x16). grid (NC/64, 2, 32)
__global__ void tgemm_b256(const float* __restrict__ A, const float* __restrict__ Bm,
                           float* __restrict__ C, int NC,
                           float b0c, float b1c, float c0c, float c1c) {
    __shared__ uint32_t As[128 * 20];   // [m][k] pad 4
    __shared__ uint32_t Bs[16 * 72];    // [k][n] pad 8
    int t = threadIdx.x, g = blockIdx.z;
    int warp = t >> 5, lane = t & 31;
    int wm = warp >> 2, wn = warp & 3;
    int g8 = lane >> 2, tg = lane & 3;
    int gr0 = blockIdx.y * 128, gc0 = blockIdx.x * 64;
    const float* Ag = A + (size_t)g * MM * MM;
    const float* Bg = Bm + (size_t)g * MM * NC;
    float acc[4][2][4];
    #pragma unroll
    for (int i = 0; i < 4; i++)
        #pragma unroll
        for (int j = 0; j < 2; j++)
            #pragma unroll
            for (int r = 0; r < 4; r++) acc[i][j][r] = 0.f;

    for (int k0 = 0; k0 < MM; k0 += 16) {
        #pragma unroll
        for (int i = 0; i < 2; i++) {
            int s = t + i * 256;
            int r = s >> 2, kq = (s & 3) * 4;
            float4 v = *(const float4*)&Ag[(size_t)(gr0 + r) * MM + k0 + kq];
            As[r * 20 + kq + 0] = f2tf(v.x);
            As[r * 20 + kq + 1] = f2tf(v.y);
            As[r * 20 + kq + 2] = f2tf(v.z);
            As[r * 20 + kq + 3] = f2tf(v.w);
        }
        {
            int kr = t >> 4, nq = (t & 15) * 4;
            float4 v = *(const float4*)&Bg[(size_t)(k0 + kr) * NC + gc0 + nq];
            int kg = k0 + kr;
            float vv[4] = {v.x, v.y, v.z, v.w};
            #pragma unroll
            for (int u = 0; u < 4; u++) {
                int c = gc0 + nq + u;
                vv[u] = b1c * vv[u] + (kg == c ? b0c : 0.f);
                Bs[kr * 72 + nq + u] = f2tf(vv[u]);
            }
        }
        __syncthreads();
        #pragma unroll
        for (int kk = 0; kk < 16; kk += 8) {
            uint32_t af[4][4], bf[2][2];
            #pragma unroll
            for (int mi = 0; mi < 4; mi++) {
                int rm = wm * 64 + mi * 16;
                af[mi][0] = As[(rm + g8)     * 20 + kk + tg];
                af[mi][1] = As[(rm + g8 + 8) * 20 + kk + tg];
                af[mi][2] = As[(rm + g8)     * 20 + kk + tg + 4];
                af[mi][3] = As[(rm + g8 + 8) * 20 + kk + tg + 4];
            }
            #pragma unroll
            for (int ni = 0; ni < 2; ni++) {
                int nb = wn * 16 + ni * 8 + g8;
                bf[ni][0] = Bs[(kk + tg)     * 72 + nb];
                bf[ni][1] = Bs[(kk + tg + 4) * 72 + nb];
            }
            #pragma unroll
            for (int mi = 0; mi < 4; mi++)
                #pragma unroll
                for (int ni = 0; ni < 2; ni++)
                    mma8(acc[mi][ni], af[mi], bf[ni]);
        }
        __syncthreads();
    }

    #pragma unroll
    for (int mi = 0; mi < 4; mi++) {
        #pragma unroll
        for (int ni = 0; ni < 2; ni++) {
            int c = gc0 + wn * 16 + ni * 8 + tg * 2;
            #pragma unroll
            for (int half = 0; half < 2; half++) {
                int r = gr0 + wm * 64 + mi * 16 + g8 + half * 8;
                float o0 = c1c * acc[mi][ni][half * 2 + 0] + (r == c     ? c0c : 0.f);
                float o1 = c1c * acc[mi][ni][half * 2 + 1] + (r == c + 1 ? c0c : 0.f);
                *(float2*)&C[((size_t)g * MM + r) * NC + c] = make_float2(o0, o1);
            }
        }
    }
}

// ---------------- exp-on-load gemm: out = softmax(S) @ Bv (split-K) ----------
__global__ void gemm_ns_kernel(const float* __restrict__ S, const float2* __restrict__ stat,
                               const float* __restrict__ Bv, float* __restrict__ out,
                               int RA, int Kfull, int nsplit) {
    __shared__ float As[32 * 132];
    __shared__ float Bs[32 * 68];
    int t = threadIdx.x, g = blockIdx.z;
    int split = blockIdx.x;
    int gr0 = blockIdx.y * 128;
    int klen = Kfull / nsplit;
    int kst = split * klen;
    int ty = t >> 4, tx = t & 15;
    float acc[8][4];
    #pragma unroll
    for (int i = 0; i < 8; i++)
        #pragma unroll
        for (int j = 0; j < 4; j++) acc[i][j] = 0.f;

    for (int k0 = 0; k0 < klen; k0 += 32) {
        #pragma unroll
        for (int i = 0; i < 4; i++) {
            int slot = t + i * 256;
            int r = slot >> 3, k4 = (slot & 7) * 4;
            long long row = (long long)g * RA + gr0 + r;
            float4 a4 = *(const float4*)&S[row * Kfull + kst + k0 + k4];
            float2 st = stat[row];
            As[(k4 + 0) * 132 + r] = __expf(a4.x - st.x) * st.y;
            As[(k4 + 1) * 132 + r] = __expf(a4.y - st.x) * st.y;
            As[(k4 + 2) * 132 + r] = __expf(a4.z - st.x) * st.y;
            As[(k4 + 3) * 132 + r] = __expf(a4.w - st.x) * st.y;
        }
        #pragma unroll
        for (int i = 0; i < 2; i++) {
            int slot = t + i * 256;
            int kr = slot >> 4, c4 = (slot & 15) * 4;
            float4 b4 = *(const float4*)&Bv[((long long)g * Kfull + kst + k0 + kr) * DHH + c4];
            *(float4*)&Bs[kr * 68 + c4] = b4;
        }
        __syncthreads();
        #pragma unroll
        for (int kk = 0; kk < 32; kk++) {
            float a[8], b[4];
            *(float4*)(a)     = *(float4*)&As[kk * 132 + ty * 8];
            *(float4*)(a + 4) = *(float4*)&As[kk * 132 + ty * 8 + 4];
            *(float4*)(b)     = *(float4*)&Bs[kk * 68 + tx * 4];
            #pragma unroll
            for (int i = 0; i < 8; i++)
                #pragma unroll
                for (int j = 0; j < 4; j++) acc[i][j] += a[i] * b[j];
        }
        __syncthreads();
    }
    #pragma unroll
    for (int i = 0; i < 8; i++) {
        long long o = (((long long)g * nsplit + split) * RA + gr0 + ty * 8 + i) * DHH + tx * 4;
        *(float4*)&out[o] = make_float4(acc[i][0], acc[i][1], acc[i][2], acc[i][3]);
    }
}

__global__ void reduce16_kernel() {
    long long i = (long long)blockIdx.x * 256 + threadIdx.x;  // GG*MM*DHH
    int g = (int)(i / (MM * DHH));
    int rc = (int)(i % (MM * DHH));
    float s = 0.f;
    #pragma unroll
    for (int sp = 0; sp < NSPLIT; sp++)
        s += g_part[((long long)(g * NSPLIT + sp)) * MM * DHH + rc];
    g_kv[i] = s;
}

// ---------------- depthwise conv-33 over seq + head merge ----------------
__global__ void conv_combine_kernel(const float* __restrict__ v, const float* __restrict__ o1,
                                    const float* __restrict__ cw, float* __restrict__ ao) {
    int g = blockIdx.y;
    int h = g & 7, b = g >> 3;
    int n0 = blockIdx.x * 64;
    __shared__ float sv[96 * 64];
    __shared__ float ws[33];
    int t = threadIdx.x;
    if (t < 33) ws[t] = cw[h * 33 + t];
    const float* vg = v + (size_t)g * NN * DHH;
    for (int i = t; i < 96 * 64; i += 256) {
        int r = i >> 6, d = i & 63;
        int n = n0 - 16 + r;
        sv[i] = (n >= 0 && n < NN) ? vg[(size_t)n * DHH + d] : 0.f;
    }
    __syncthreads();
    int d = t & 63, nl0 = t >> 6;
    for (int i = 0; i < 16; i++) {
        int nl = nl0 + i * 4;
        float acc = 0.f;
        #pragma unroll
        for (int kk = 0; kk < 33; kk++) acc += ws[kk] * sv[(nl + kk) * 64 + d];
        int n = n0 + nl;
        ao[((size_t)b * NN + n) * DD + h * 64 + d] =
            o1[((size_t)g * NN + n) * DHH + d] + acc;
    }
}

// ---------------- host ----------------
static float* symf(const void* s) { void* p = 0; cudaGetSymbolAddress(&p, s); return (float*)p; }

extern "C" void kernel_launch(void* const* d_in, const int* in_sizes, int n_in,
                              void* d_out, int out_size) {
    const float* x      = (const float*)d_in[0];
    const float* gamma  = (const float*)d_in[1];
    const float* beta   = (const float*)d_in[2];
    const float* w_qkv  = (const float*)d_in[3];
    const float* w_out  = (const float*)d_in[4];
    const float* b_out  = (const float*)d_in[5];
    const float* conv_w = (const float*)d_in[6];
    float* out = (float*)d_out;

    float* ln   = symf(g_ln);
    float* q    = symf(g_q);
    float* k    = symf(g_k);
    float* v    = symf(g_v);
    float* ql   = symf(g_ql);
    float* kl   = symf(g_kl);
    float* s1   = symf(g_s1);
    float* s2   = symf(g_s2);
    float* s3   = symf(g_s3);
    float* a2   = symf(g_a2);
    float* zA   = symf(g_zA);
    float* zB   = symf(g_zB);
    float* t1   = symf(g_t1);
    float* t2   = symf(g_t2);
    float* t3   = symf(g_t3);
    float* part = symf(g_part);
    float* kv   = symf(g_kv);
    float* Dm   = symf(g_Dm);
    float* o1   = symf(g_o1);
    float* ao   = symf(g_ao);
    float2* st1 = (float2*)symf(g_stat1);
    float2* st2 = (float2*)symf(g_stat2);
    float2* st3 = (float2*)symf(g_stat3);

    // 1. layernorm
    ln_kernel<<<TROWS, 256>>>(x, gamma, beta, ln);

    // 2. qkv gemm (tf32) with head scatter + q scale
    tgemm_nn<0><<<dim3(12, 256), 256>>>(ln, w_qkv, DD, 3 * DD, 0, 0, 0, q, k, v);

    // 3. landmarks
    landmark_kernel<<<dim3(MM, GG), 64>>>(q, k, ql, kl);

    // 4. similarity scores (tf32)
    tgemm_nt<<<dim3(2, 64, GG), 256>>>(q, kl, s1, NN, MM);
    tgemm_nt<<<dim3(2, 2, GG), 256>>>(ql, kl, s2, MM, MM);
    tgemm_nt<<<dim3(64, 2, GG), 256>>>(ql, k, s3, MM, NN);

    // 5. softmax stats
    rowstat_kernel<<<GG * NN, 256>>>(s1, st1, MM);
    rowstat_kernel<<<GG * MM, 256>>>(s2, st2, MM);
    rowstat_kernel<<<GG * MM, 256>>>(s3, st3, NN);
    apply_softmax_kernel<<<GG * MM * MM / 256, 256>>>(s2, st2, a2);

    // 6. pinv init: z = a2^T / (max rowsum * max colsum)
    zero_scale_kernel<<<1, 32>>>();
    pinv_reduce_kernel<<<GG, 256>>>();
    z_init_kernel<<<GG * MM * MM / 256, 256>>>();

    // 7. Newton-Schulz (tf32): z = 0.25 z (13I - X(15I - X(7I - X))), X = a2 z
    for (int it = 0; it < 6; it++) {
        float* zin  = (it & 1) ? zB : zA;
        float* zout = (it & 1) ? zA : zB;
        tgemm_b256<<<dim3(4, 2, GG), 256>>>(a2,  zin, t1, MM, 0.f,  1.f, 0.f, 1.f);
        tgemm_b256<<<dim3(4, 2, GG), 256>>>(t1,  t1,  t2, MM, 7.f, -1.f, 0.f, 1.f);
        tgemm_b256<<<dim3(4, 2, GG), 256>>>(t1,  t2,  t3, MM, 15.f, -1.f, 0.f, 1.f);
        tgemm_b256<<<dim3(4, 2, GG), 256>>>(zin, t3, zout, MM, 13.f, -1.f, 0.f, 0.25f);
    }
    float* zfin = zA;  // after 6 iterations result is in zA

    // 8. kv = softmax(s3) @ v  (split-K deterministic, fp32)
    gemm_ns_kernel<<<dim3(NSPLIT, 2, GG), 256>>>(s3, st3, v, part, MM, NN, NSPLIT);
    reduce16_kernel<<<GG * MM * DHH / 256, 256>>>();

    // 9. Dm = pinv @ kv  (tf32)
    tgemm_b256<<<dim3(1, 2, GG), 256>>>(zfin, kv, Dm, DHH, 0.f, 1.f, 0.f, 1.f);

    // 10. o1 = softmax(s1) @ Dm  (fp32)
    gemm_ns_kernel<<<dim3(1, 64, GG), 256>>>(s1, st1, Dm, o1, NN, MM, 1);

    // 11. conv residual + merge heads
    conv_combine_kernel<<<dim3(NN / 64, GG), 256>>>(v, o1, conv_w, ao);

    // 12. final: out = ao @ w_out + b_out + x  (tf32)
    tgemm_nn<1><<<dim3(4, 256), 256>>>(ao, w_out, DD, DD, x, b_out, out, 0, 0, 0);
}

// round 6
// speedup vs baseline: 2.4174x; 1.4099x over previous
#include <cuda_runtime.h>
#include <math.h>
#include <stdint.h>

#define BB 4
#define NN 8192
#define DD 512
#define HH 8
#define DHH 64
#define MM 256
#define GG 32           // BB*HH
#define TROWS 32768     // BB*NN
#define KSPL 4          // key splits for flash3

// ---------------- static device scratch ----------------
__device__ float g_ln[(size_t)TROWS * DD];
__device__ float g_q[(size_t)GG * NN * DHH];
__device__ float g_k[(size_t)GG * NN * DHH];
__device__ float g_v[(size_t)GG * NN * DHH];
__device__ float g_ql[GG * MM * DHH];
__device__ float g_kl[GG * MM * DHH];
__device__ float g_s2[GG * MM * MM];
__device__ float g_a2[GG * MM * MM];
__device__ float g_zA[GG * MM * MM];
__device__ float g_zB[GG * MM * MM];
__device__ float g_t1[GG * MM * MM];
__device__ float g_t2[GG * MM * MM];
__device__ float g_t3[GG * MM * MM];
__device__ float g_po[(size_t)GG * KSPL * MM * DHH];
__device__ float2 g_pms[GG * KSPL * MM];
__device__ float g_kv[GG * MM * DHH];
__device__ float g_Dm[GG * MM * DHH];
__device__ float g_o1[(size_t)GG * NN * DHH];
__device__ float g_ao[(size_t)TROWS * DD];
__device__ float2 g_stat2[GG * MM];
__device__ int    g_scaleI[2];

// ---------------- tf32 helpers ----------------
__device__ __forceinline__ uint32_t f2tf(float x) {
    uint32_t r;
    asm("cvt.rna.tf32.f32 %0, %1;" : "=r"(r) : "f"(x));
    return r;
}

__device__ __forceinline__ void mma8(float* d, const uint32_t* a, const uint32_t* b) {
    asm volatile(
        "mma.sync.aligned.m16n8k8.row.col.f32.tf32.tf32.f32 "
        "{%0,%1,%2,%3}, {%4,%5,%6,%7}, {%8,%9}, {%0,%1,%2,%3};"
        : "+f"(d[0]), "+f"(d[1]), "+f"(d[2]), "+f"(d[3])
        : "r"(a[0]), "r"(a[1]), "r"(a[2]), "r"(a[3]), "r"(b[0]), "r"(b[1]));
}

// ---------------- layernorm ----------------
__global__ void ln_kernel(const float* __restrict__ x, const float* __restrict__ gamma,
                          const float* __restrict__ beta, float* __restrict__ out) {
    int row = blockIdx.x;
    const float* xr = x + (size_t)row * DD;
    int t = threadIdx.x;
    float v0 = xr[t], v1 = xr[t + 256];
    float s = v0 + v1, ss = v0 * v0 + v1 * v1;
    #pragma unroll
    for (int o = 16; o; o >>= 1) {
        s  += __shfl_down_sync(0xffffffffu, s, o);
        ss += __shfl_down_sync(0xffffffffu, ss, o);
    }
    __shared__ float rs[8], rss[8];
    int w = t >> 5, l = t & 31;
    if (l == 0) { rs[w] = s; rss[w] = ss; }
    __syncthreads();
    __shared__ float s_mu, s_rstd;
    if (t == 0) {
        float a = 0.f, b = 0.f;
        #pragma unroll
        for (int i = 0; i < 8; i++) { a += rs[i]; b += rss[i]; }
        float mu = a * (1.f / DD);
        float var = b * (1.f / DD) - mu * mu;
        s_mu = mu; s_rstd = rsqrtf(var + 1e-5f);
    }
    __syncthreads();
    float mu = s_mu, rstd = s_rstd;
    float* orow = out + (size_t)row * DD;
    orow[t]       = (v0 - mu) * rstd * gamma[t]       + beta[t];
    orow[t + 256] = (v1 - mu) * rstd * gamma[t + 256] + beta[t + 256];
}

// ---------------- tf32 NN gemm 128x128xK, 256 thr (8 warps 2x4, warp 64x32) --
// MODE 0: C = A@B scattered into q/k/v head layout (q scaled 0.125)
// MODE 1: out = A@B + xres + bias
template <int MODE>
__global__ void __launch_bounds__(256) tgemm_nn(
        const float* __restrict__ A, const float* __restrict__ Bm,
        int Kdim, int Ncols,
        const float* __restrict__ xres, const float* __restrict__ bias,
        float* __restrict__ outp,
        float* __restrict__ oq, float* __restrict__ okk, float* __restrict__ ov) {
    __shared__ uint32_t As[128 * 20];   // [m][k] pad 4
    __shared__ uint32_t Bs[16 * 136];   // [k][n] pad 8
    int t = threadIdx.x;
    int warp = t >> 5, lane = t & 31;
    int wm = warp >> 2, wn = warp & 3;
    int g8 = lane >> 2, tg = lane & 3;
    int brow = blockIdx.y * 128, bcol = blockIdx.x * 128;
    float acc[4][4][4];
    #pragma unroll
    for (int i = 0; i < 4; i++)
        #pragma unroll
        for (int j = 0; j < 4; j++)
            #pragma unroll
            for (int r = 0; r < 4; r++) acc[i][j][r] = 0.f;

    for (int k0 = 0; k0 < Kdim; k0 += 16) {
        #pragma unroll
        for (int i = 0; i < 2; i++) {
            int s = t + i * 256;
            int r = s >> 2, kq = (s & 3) * 4;
            float4 v = *(const float4*)&A[(size_t)(brow + r) * Kdim + k0 + kq];
            As[r * 20 + kq + 0] = f2tf(v.x);
            As[r * 20 + kq + 1] = f2tf(v.y);
            As[r * 20 + kq + 2] = f2tf(v.z);
            As[r * 20 + kq + 3] = f2tf(v.w);
        }
        #pragma unroll
        for (int i = 0; i < 2; i++) {
            int s = t + i * 256;
            int kr = s >> 5, nq = (s & 31) * 4;
            float4 v = *(const float4*)&Bm[(size_t)(k0 + kr) * Ncols + bcol + nq];
            Bs[kr * 136 + nq + 0] = f2tf(v.x);
            Bs[kr * 136 + nq + 1] = f2tf(v.y);
            Bs[kr * 136 + nq + 2] = f2tf(v.z);
            Bs[kr * 136 + nq + 3] = f2tf(v.w);
        }
        __syncthreads();
        #pragma unroll
        for (int kk = 0; kk < 16; kk += 8) {
            uint32_t af[4][4], bf[4][2];
            #pragma unroll
            for (int mi = 0; mi < 4; mi++) {
                int rm = wm * 64 + mi * 16;
                af[mi][0] = As[(rm + g8)     * 20 + kk + tg];
                af[mi][1] = As[(rm + g8 + 8) * 20 + kk + tg];
                af[mi][2] = As[(rm + g8)     * 20 + kk + tg + 4];
                af[mi][3] = As[(rm + g8 + 8) * 20 + kk + tg + 4];
            }
            #pragma unroll
            for (int ni = 0; ni < 4; ni++) {
                int nb = wn * 32 + ni * 8 + g8;
                bf[ni][0] = Bs[(kk + tg)     * 136 + nb];
                bf[ni][1] = Bs[(kk + tg + 4) * 136 + nb];
            }
            #pragma unroll
            for (int mi = 0; mi < 4; mi++)
                #pragma unroll
                for (int ni = 0; ni < 4; ni++)
                    mma8(acc[mi][ni], af[mi], bf[ni]);
        }
        __syncthreads();
    }

    #pragma unroll
    for (int mi = 0; mi < 4; mi++) {
        #pragma unroll
        for (int ni = 0; ni < 4; ni++) {
            int c = bcol + wn * 32 + ni * 8 + tg * 2;
            #pragma unroll
            for (int half = 0; half < 2; half++) {
                int r = brow + wm * 64 + mi * 16 + g8 + half * 8;
                float v0 = acc[mi][ni][half * 2 + 0];
                float v1 = acc[mi][ni][half * 2 + 1];
                if (MODE == 0) {
                    int part = c >> 9, h = (c >> 6) & 7, d = c & 63;
                    int bidx = r >> 13, n = r & 8191;
                    size_t dst = (((size_t)(bidx * HH + h)) * NN + n) * DHH + d;
                    if (part == 0)      { oq[dst] = v0 * 0.125f; oq[dst + 1] = v1 * 0.125f; }
                    else if (part == 1) { okk[dst] = v0;         okk[dst + 1] = v1; }
                    else                { ov[dst] = v0;          ov[dst + 1] = v1; }
                } else {
                    size_t o = (size_t)r * Ncols + c;
                    outp[o]     = v0 + xres[o]     + bias[c];
                    outp[o + 1] = v1 + xres[o + 1] + bias[c + 1];
                }
            }
        }
    }
}

// ---------------- landmark means ----------------
__global__ void landmark_kernel(const float* __restrict__ q, const float* __restrict__ k,
                                float* __restrict__ ql, float* __restrict__ kl) {
    int g = blockIdx.y, m = blockIdx.x, d = threadIdx.x;
    const float* qp = q + ((size_t)g * NN + m * 32) * DHH + d;
    const float* kp = k + ((size_t)g * NN + m * 32) * DHH + d;
    float sq = 0.f, sk = 0.f;
    #pragma unroll
    for (int i = 0; i < 32; i++) { sq += qp[i * DHH]; sk += kp[i * DHH]; }
    ql[(g * MM + m) * DHH + d] = sq * (1.f / 32.f);
    kl[(g * MM + m) * DHH + d] = sk * (1.f / 32.f);
}

// ---------------- tf32 NT gemm over dh=64 (s2 only): C = A @ B^T -------------
__global__ void __launch_bounds__(256) tgemm_nt(
        const float* __restrict__ A, const float* __restrict__ Bm,
        float* __restrict__ C, int RA, int RB) {
    __shared__ uint32_t As[128 * 20];
    __shared__ uint32_t Bs[128 * 20];
    int t = threadIdx.x, g = blockIdx.z;
    int warp = t >> 5, lane = t & 31;
    int wm = warp >> 2, wn = warp & 3;
    int g8 = lane >> 2, tg = lane & 3;
    int gr0 = blockIdx.y * 128, gc0 = blockIdx.x * 128;
    float acc[4][4][4];
    #pragma unroll
    for (int i = 0; i < 4; i++)
        #pragma unroll
        for (int j = 0; j < 4; j++)
            #pragma unroll
            for (int r = 0; r < 4; r++) acc[i][j][r] = 0.f;

    for (int k0 = 0; k0 < 64; k0 += 16) {
        #pragma unroll
        for (int i = 0; i < 2; i++) {
            int s = t + i * 256;
            int r = s >> 2, kq = (s & 3) * 4;
            float4 va = *(const float4*)&A[((size_t)g * RA + gr0 + r) * DHH + k0 + kq];
            As[r * 20 + kq + 0] = f2tf(va.x);
            As[r * 20 + kq + 1] = f2tf(va.y);
            As[r * 20 + kq + 2] = f2tf(va.z);
            As[r * 20 + kq + 3] = f2tf(va.w);
            float4 vb = *(const float4*)&Bm[((size_t)g * RB + gc0 + r) * DHH + k0 + kq];
            Bs[r * 20 + kq + 0] = f2tf(vb.x);
            Bs[r * 20 + kq + 1] = f2tf(vb.y);
            Bs[r * 20 + kq + 2] = f2tf(vb.z);
            Bs[r * 20 + kq + 3] = f2tf(vb.w);
        }
        __syncthreads();
        #pragma unroll
        for (int kk = 0; kk < 16; kk += 8) {
            uint32_t af[4][4], bf[4][2];
            #pragma unroll
            for (int mi = 0; mi < 4; mi++) {
                int rm = wm * 64 + mi * 16;
                af[mi][0] = As[(rm + g8)     * 20 + kk + tg];
                af[mi][1] = As[(rm + g8 + 8) * 20 + kk + tg];
                af[mi][2] = As[(rm + g8)     * 20 + kk + tg + 4];
                af[mi][3] = As[(rm + g8 + 8) * 20 + kk + tg + 4];
            }
            #pragma unroll
            for (int ni = 0; ni < 4; ni++) {
                int nb = wn * 32 + ni * 8 + g8;
                bf[ni][0] = Bs[nb * 20 + kk + tg];
                bf[ni][1] = Bs[nb * 20 + kk + tg + 4];
            }
            #pragma unroll
            for (int mi = 0; mi < 4; mi++)
                #pragma unroll
                for (int ni = 0; ni < 4; ni++)
                    mma8(acc[mi][ni], af[mi], bf[ni]);
        }
        __syncthreads();
    }

    #pragma unroll
    for (int mi = 0; mi < 4; mi++) {
        #pragma unroll
        for (int ni = 0; ni < 4; ni++) {
            int c = gc0 + wn * 32 + ni * 8 + tg * 2;
            #pragma unroll
            for (int half = 0; half < 2; half++) {
                int r = gr0 + wm * 64 + mi * 16 + g8 + half * 8;
                size_t o = ((size_t)g * RA + r) * RB + c;
                *(float2*)&C[o] = make_float2(acc[mi][ni][half * 2 + 0],
                                              acc[mi][ni][half * 2 + 1]);
            }
        }
    }
}

// ---------------- fused flash: out = softmax(A@B^T) @ V ---------------------
// A:[g][RA][64], B,V:[g][RB][64]. 128-row CTA, 64-key tiles, 8 warps each
// owning 16 rows. NSPL>1 -> partial (unnormalized O, (m,l)) per key split.
template <int NSPL>
__global__ void __launch_bounds__(256) flash_kernel(
        const float* __restrict__ Aq, const float* __restrict__ Bk,
        const float* __restrict__ Vv, float* __restrict__ outp,
        float2* __restrict__ pms, int RA, int RB) {
    __shared__ uint32_t smbuf[8960];      // K:[64][68] + V:[64][72]; Q staging uses [128][68]
    uint32_t* Ks = smbuf;
    uint32_t* Vs = smbuf + 64 * 68;
    int t = threadIdx.x, g = blockIdx.z, spl = blockIdx.y;
    int brow = blockIdx.x * 128;
    int warp = t >> 5, lane = t & 31, g8 = lane >> 2, tg = lane & 3;
    size_t gA = (size_t)g * RA, gB = (size_t)g * RB;
    int klen = RB / NSPL, kst = spl * klen;

    // stage Q (128x64) -> frags
    #pragma unroll
    for (int i = 0; i < 8; i++) {
        int s = t + i * 256; int r = s >> 4, c4 = (s & 15) * 4;
        float4 v = *(const float4*)&Aq[(gA + brow + r) * DHH + c4];
        smbuf[r * 68 + c4 + 0] = f2tf(v.x);
        smbuf[r * 68 + c4 + 1] = f2tf(v.y);
        smbuf[r * 68 + c4 + 2] = f2tf(v.z);
        smbuf[r * 68 + c4 + 3] = f2tf(v.w);
    }
    __syncthreads();
    uint32_t qf[8][4];
    {
        int r0 = (warp * 16 + g8) * 68, r1 = (warp * 16 + g8 + 8) * 68;
        #pragma unroll
        for (int kc = 0; kc < 8; kc++) {
            qf[kc][0] = smbuf[r0 + kc * 8 + tg];
            qf[kc][1] = smbuf[r1 + kc * 8 + tg];
            qf[kc][2] = smbuf[r0 + kc * 8 + tg + 4];
            qf[kc][3] = smbuf[r1 + kc * 8 + tg + 4];
        }
    }
    __syncthreads();

    float o[8][4];
    #pragma unroll
    for (int i = 0; i < 8; i++)
        #pragma unroll
        for (int j = 0; j < 4; j++) o[i][j] = 0.f;
    float m0 = -1e30f, m1 = -1e30f, l0 = 0.f, l1 = 0.f;
    int srcl = (lane & ~3) | (tg >> 1);

    for (int kb = 0; kb < klen; kb += 64) {
        #pragma unroll
        for (int i = 0; i < 4; i++) {
            int s = t + i * 256; int r = s >> 4, c4 = (s & 15) * 4;
            size_t src = (gB + kst + kb + r) * DHH + c4;
            float4 vk = *(const float4*)&Bk[src];
            Ks[r * 68 + c4 + 0] = f2tf(vk.x);
            Ks[r * 68 + c4 + 1] = f2tf(vk.y);
            Ks[r * 68 + c4 + 2] = f2tf(vk.z);
            Ks[r * 68 + c4 + 3] = f2tf(vk.w);
            float4 vv = *(const float4*)&Vv[src];
            Vs[r * 72 + c4 + 0] = f2tf(vv.x);
            Vs[r * 72 + c4 + 1] = f2tf(vv.y);
            Vs[r * 72 + c4 + 2] = f2tf(vv.z);
            Vs[r * 72 + c4 + 3] = f2tf(vv.w);
        }
        __syncthreads();

        // S = Q @ K^T : 16 rows x 64 keys per warp
        float sv[8][4];
        #pragma unroll
        for (int nt = 0; nt < 8; nt++)
            #pragma unroll
            for (int j = 0; j < 4; j++) sv[nt][j] = 0.f;
        #pragma unroll
        for (int nt = 0; nt < 8; nt++) {
            #pragma unroll
            for (int kc = 0; kc < 8; kc++) {
                uint32_t bf[2];
                bf[0] = Ks[(nt * 8 + g8) * 68 + kc * 8 + tg];
                bf[1] = Ks[(nt * 8 + g8) * 68 + kc * 8 + tg + 4];
                mma8(sv[nt], qf[kc], bf);
            }
        }

        // online softmax (rows g8 and g8+8; quads share rows)
        float tm0 = -1e30f, tm1 = -1e30f;
        #pragma unroll
        for (int nt = 0; nt < 8; nt++) {
            tm0 = fmaxf(tm0, fmaxf(sv[nt][0], sv[nt][1]));
            tm1 = fmaxf(tm1, fmaxf(sv[nt][2], sv[nt][3]));
        }
        tm0 = fmaxf(tm0, __shfl_xor_sync(0xffffffffu, tm0, 1));
        tm0 = fmaxf(tm0, __shfl_xor_sync(0xffffffffu, tm0, 2));
        tm1 = fmaxf(tm1, __shfl_xor_sync(0xffffffffu, tm1, 1));
        tm1 = fmaxf(tm1, __shfl_xor_sync(0xffffffffu, tm1, 2));
        float m0n = fmaxf(m0, tm0), m1n = fmaxf(m1, tm1);
        float al0 = __expf(m0 - m0n), al1 = __expf(m1 - m1n);
        m0 = m0n; m1 = m1n;
        l0 *= al0; l1 *= al1;
        #pragma unroll
        for (int nv = 0; nv < 8; nv++) {
            o[nv][0] *= al0; o[nv][1] *= al0; o[nv][2] *= al1; o[nv][3] *= al1;
        }

        // P = exp(S - m); convert C-frag -> A-frag layout via quad shuffles
        uint32_t pf[8][4];
        #pragma unroll
        for (int nt = 0; nt < 8; nt++) {
            float p0 = __expf(sv[nt][0] - m0), p1 = __expf(sv[nt][1] - m0);
            float p2 = __expf(sv[nt][2] - m1), p3 = __expf(sv[nt][3] - m1);
            l0 += p0 + p1; l1 += p2 + p3;
            float e, od;
            e  = __shfl_sync(0xffffffffu, p0, srcl);
            od = __shfl_sync(0xffffffffu, p1, srcl);
            float a0v = (tg & 1) ? od : e;
            e  = __shfl_sync(0xffffffffu, p2, srcl);
            od = __shfl_sync(0xffffffffu, p3, srcl);
            float a1v = (tg & 1) ? od : e;
            e  = __shfl_sync(0xffffffffu, p0, srcl + 2);
            od = __shfl_sync(0xffffffffu, p1, srcl + 2);
            float a2v = (tg & 1) ? od : e;
            e  = __shfl_sync(0xffffffffu, p2, srcl + 2);
            od = __shfl_sync(0xffffffffu, p3, srcl + 2);
            float a3v = (tg & 1) ? od : e;
            pf[nt][0] = f2tf(a0v); pf[nt][1] = f2tf(a1v);
            pf[nt][2] = f2tf(a2v); pf[nt][3] = f2tf(a3v);
        }

        // O += P @ V
        #pragma unroll
        for (int nv = 0; nv < 8; nv++) {
            #pragma unroll
            for (int kc = 0; kc < 8; kc++) {
                uint32_t bf[2];
                bf[0] = Vs[(kc * 8 + tg) * 72 + nv * 8 + g8];
                bf[1] = Vs[(kc * 8 + tg + 4) * 72 + nv * 8 + g8];
                mma8(o[nv], pf[kc], bf);
            }
        }
        __syncthreads();
    }

    l0 += __shfl_xor_sync(0xffffffffu, l0, 1);
    l0 += __shfl_xor_sync(0xffffffffu, l0, 2);
    l1 += __shfl_xor_sync(0xffffffffu, l1, 1);
    l1 += __shfl_xor_sync(0xffffffffu, l1, 2);

    int lr0 = brow + warp * 16 + g8;
    if (NSPL == 1) {
        float i0 = 1.f / l0, i1 = 1.f / l1;
        #pragma unroll
        for (int nv = 0; nv < 8; nv++) {
            size_t oo = (gA + lr0) * DHH + nv * 8 + tg * 2;
            *(float2*)&outp[oo]            = make_float2(o[nv][0] * i0, o[nv][1] * i0);
            *(float2*)&outp[oo + 8 * DHH]  = make_float2(o[nv][2] * i1, o[nv][3] * i1);
        }
    } else {
        size_t pbase = (size_t)(g * NSPL + spl) * RA;
        #pragma unroll
        for (int nv = 0; nv < 8; nv++) {
            size_t oo = (pbase + lr0) * DHH + nv * 8 + tg * 2;
            *(float2*)&outp[oo]           = make_float2(o[nv][0], o[nv][1]);
            *(float2*)&outp[oo + 8 * DHH] = make_float2(o[nv][2], o[nv][3]);
        }
        if (tg == 0) {
            pms[pbase + lr0]     = make_float2(m0, l0);
            pms[pbase + lr0 + 8] = make_float2(m1, l1);
        }
    }
}

// combine KSPL flash partials -> g_kv
__global__ void flash_combine_kernel() {
    long long i = (long long)blockIdx.x * 256 + threadIdx.x;   // GG*MM*DHH
    int g = (int)(i / (MM * DHH));
    int rem = (int)(i % (MM * DHH));
    int row = rem / DHH, d = rem % DHH;
    float gm = -1e30f;
    float2 ms[KSPL];
    #pragma unroll
    for (int s = 0; s < KSPL; s++) {
        ms[s] = g_pms[(g * KSPL + s) * MM + row];
        gm = fmaxf(gm, ms[s].x);
    }
    float denom = 0.f, val = 0.f;
    #pragma unroll
    for (int s = 0; s < KSPL; s++) {
        float w = __expf(ms[s].x - gm);
        denom += ms[s].y * w;
        val += g_po[((size_t)(g * KSPL + s) * MM + row) * DHH + d] * w;
    }
    g_kv[i] = val / denom;
}

// ---------------- row softmax stats (s2 only) ----------------
__global__ void rowstat_kernel(const float* __restrict__ S, float2* __restrict__ stat, int NC) {
    long long row = blockIdx.x;
    const float* p = S + row * (long long)NC;
    int t = threadIdx.x;
    float tm = -1e30f, ts = 0.f;
    for (int c = t; c < NC; c += 256) {
        float v = p[c];
        if (v > tm) { ts = ts * __expf(tm - v) + 1.f; tm = v; }
        else ts += __expf(v - tm);
    }
    #pragma unroll
    for (int o = 16; o; o >>= 1) {
        float om = __shfl_down_sync(0xffffffffu, tm, o);
        float os = __shfl_down_sync(0xffffffffu, ts, o);
        float nm = fmaxf(tm, om);
        ts = ts * __expf(tm - nm) + os * __expf(om - nm);
        tm = nm;
    }
    __shared__ float smx[8], ssm[8];
    if ((t & 31) == 0) { smx[t >> 5] = tm; ssm[t >> 5] = ts; }
    __syncthreads();
    if (t == 0) {
        tm = smx[0]; ts = ssm[0];
        #pragma unroll
        for (int w = 1; w < 8; w++) {
            float om = smx[w], os = ssm[w];
            float nm = fmaxf(tm, om);
            ts = ts * __expf(tm - nm) + os * __expf(om - nm);
            tm = nm;
        }
        stat[row] = make_float2(tm, 1.f / ts);
    }
}

__global__ void apply_softmax_kernel(const float* __restrict__ S, const float2* __restrict__ stat,
                                     float* __restrict__ out) {
    long long i = (long long)blockIdx.x * 256 + threadIdx.x;
    float2 st = stat[i >> 8];
    out[i] = __expf(S[i] - st.x) * st.y;
}

// ---------------- pinv init ----------------
__global__ void zero_scale_kernel() { if (threadIdx.x < 2) g_scaleI[threadIdx.x] = 0; }

__global__ void pinv_reduce_kernel() {
    int g = blockIdx.x, j = threadIdx.x;
    const float* a = g_a2 + (long long)g * MM * MM;
    float rs = 0.f, cs = 0.f;
    for (int c = 0; c < MM; c++) { rs += a[j * MM + c]; cs += a[c * MM + j]; }
    __shared__ float r0[256], r1[256];
    r0[j] = rs; r1[j] = cs;
    __syncthreads();
    for (int o = 128; o; o >>= 1) {
        if (j < o) { r0[j] = fmaxf(r0[j], r0[j + o]); r1[j] = fmaxf(r1[j], r1[j + o]); }
        __syncthreads();
    }
    if (j == 0) {
        atomicMax(&g_scaleI[0], __float_as_int(r0[0]));
        atomicMax(&g_scaleI[1], __float_as_int(r1[0]));
    }
}

__global__ void z_init_kernel() {
    long long i = (long long)blockIdx.x * 256 + threadIdx.x;
    float scale = 1.f / (__int_as_float(g_scaleI[0]) * __int_as_float(g_scaleI[1]));
    int g = (int)(i >> 16), r = (int)((i >> 8) & 255), c = (int)(i & 255);
    g_zA[i] = g_a2[((long long)g << 16) + (c << 8) + r] * scale;
}

// ---------------- tf32 batched 256-K gemm, fused diag transforms -----------
// C = c0*I + c1 * ( A @ (b0*I + b1*B) );  A:[g][256][256], B:[g][256][NC]
__global__ void __launch_bounds__(256) tgemm_b256(
        const float* __restrict__ A, const float* __restrict__ Bm,
        float* __restrict__ C, int NC,
        float b0c, float b1c, float c0c, float c1c) {
    __shared__ uint32_t As[128 * 20];
    __shared__ uint32_t Bs[16 * 72];
    int t = threadIdx.x, g = blockIdx.z;
    int warp = t >> 5, lane = t & 31;
    int wm = warp >> 2, wn = warp & 3;
    int g8 = lane >> 2, tg = lane & 3;
    int gr0 = blockIdx.y * 128, gc0 = blockIdx.x * 64;
    const float* Ag = A + (size_t)g * MM * MM;
    const float* Bg = Bm + (size_t)g * MM * NC;
    float acc[4][2][4];
    #pragma unroll
    for (int i = 0; i < 4; i++)
        #pragma unroll
        for (int j = 0; j < 2; j++)
            #pragma unroll
            for (int r = 0; r < 4; r++) acc[i][j][r] = 0.f;

    for (int k0 = 0; k0 < MM; k0 += 16) {
        #pragma unroll
        for (int i = 0; i < 2; i++) {
            int s = t + i * 256;
            int r = s >> 2, kq = (s & 3) * 4;
            float4 v = *(const float4*)&Ag[(size_t)(gr0 + r) * MM + k0 + kq];
            As[r * 20 + kq + 0] = f2tf(v.x);
            As[r * 20 + kq + 1] = f2tf(v.y);
            As[r * 20 + kq + 2] = f2tf(v.z);
            As[r * 20 + kq + 3] = f2tf(v.w);
        }
        {
            int kr = t >> 4, nq = (t & 15) * 4;
            float4 v = *(const float4*)&Bg[(size_t)(k0 + kr) * NC + gc0 + nq];
            int kg = k0 + kr;
            float vv[4] = {v.x, v.y, v.z, v.w};
            #pragma unroll
            for (int u = 0; u < 4; u++) {
                int c = gc0 + nq + u;
                vv[u] = b1c * vv[u] + (kg == c ? b0c : 0.f);
                Bs[kr * 72 + nq + u] = f2tf(vv[u]);
            }
        }
        __syncthreads();
        #pragma unroll
        for (int kk = 0; kk < 16; kk += 8) {
            uint32_t af[4][4], bf[2][2];
            #pragma unroll
            for (int mi = 0; mi < 4; mi++) {
                int rm = wm * 64 + mi * 16;
                af[mi][0] = As[(rm + g8)     * 20 + kk + tg];
                af[mi][1] = As[(rm + g8 + 8) * 20 + kk + tg];
                af[mi][2] = As[(rm + g8)     * 20 + kk + tg + 4];
                af[mi][3] = As[(rm + g8 + 8) * 20 + kk + tg + 4];
            }
            #pragma unroll
            for (int ni = 0; ni < 2; ni++) {
                int nb = wn * 16 + ni * 8 + g8;
                bf[ni][0] = Bs[(kk + tg)     * 72 + nb];
                bf[ni][1] = Bs[(kk + tg + 4) * 72 + nb];
            }
            #pragma unroll
            for (int mi = 0; mi < 4; mi++)
                #pragma unroll
                for (int ni = 0; ni < 2; ni++)
                    mma8(acc[mi][ni], af[mi], bf[ni]);
        }
        __syncthreads();
    }

    #pragma unroll
    for (int mi = 0; mi < 4; mi++) {
        #pragma unroll
        for (int ni = 0; ni < 2; ni++) {
            int c = gc0 + wn * 16 + ni * 8 + tg * 2;
            #pragma unroll
            for (int half = 0; half < 2; half++) {
                int r = gr0 + wm * 64 + mi * 16 + g8 + half * 8;
                float o0 = c1c * acc[mi][ni][half * 2 + 0] + (r == c     ? c0c : 0.f);
                float o1 = c1c * acc[mi][ni][half * 2 + 1] + (r == c + 1 ? c0c : 0.f);
                *(float2*)&C[((size_t)g * MM + r) * NC + c] = make_float2(o0, o1);
            }
        }
    }
}

// ---------------- depthwise conv-33 over seq + head merge ----------------
__global__ void conv_combine_kernel(const float* __restrict__ v, const float* __restrict__ o1,
                                    const float* __restrict__ cw, float* __restrict__ ao) {
    int g = blockIdx.y;
    int h = g & 7, b = g >> 3;
    int n0 = blockIdx.x * 64;
    __shared__ float sv[96 * 64];
    __shared__ float ws[33];
    int t = threadIdx.x;
    if (t < 33) ws[t] = cw[h * 33 + t];
    const float* vg = v + (size_t)g * NN * DHH;
    for (int i = t; i < 96 * 64; i += 256) {
        int r = i >> 6, d = i & 63;
        int n = n0 - 16 + r;
        sv[i] = (n >= 0 && n < NN) ? vg[(size_t)n * DHH + d] : 0.f;
    }
    __syncthreads();
    int d = t & 63, nl0 = t >> 6;
    for (int i = 0; i < 16; i++) {
        int nl = nl0 + i * 4;
        float acc = 0.f;
        #pragma unroll
        for (int kk = 0; kk < 33; kk++) acc += ws[kk] * sv[(nl + kk) * 64 + d];
        int n = n0 + nl;
        ao[((size_t)b * NN + n) * DD + h * 64 + d] =
            o1[((size_t)g * NN + n) * DHH + d] + acc;
    }
}

// ---------------- host ----------------
static float* symf(const void* s) { void* p = 0; cudaGetSymbolAddress(&p, s); return (float*)p; }

extern "C" void kernel_launch(void* const* d_in, const int* in_sizes, int n_in,
                              void* d_out, int out_size) {
    const float* x      = (const float*)d_in[0];
    const float* gamma  = (const float*)d_in[1];
    const float* beta   = (const float*)d_in[2];
    const float* w_qkv  = (const float*)d_in[3];
    const float* w_out  = (const float*)d_in[4];
    const float* b_out  = (const float*)d_in[5];
    const float* conv_w = (const float*)d_in[6];
    float* out = (float*)d_out;

    float* ln   = symf(g_ln);
    float* q    = symf(g_q);
    float* k    = symf(g_k);
    float* v    = symf(g_v);
    float* ql   = symf(g_ql);
    float* kl   = symf(g_kl);
    float* s2   = symf(g_s2);
    float* a2   = symf(g_a2);
    float* zA   = symf(g_zA);
    float* zB   = symf(g_zB);
    float* t1   = symf(g_t1);
    float* t2   = symf(g_t2);
    float* t3   = symf(g_t3);
    float* po   = symf(g_po);
    float* kv   = symf(g_kv);
    float* Dm   = symf(g_Dm);
    float* o1   = symf(g_o1);
    float* ao   = symf(g_ao);
    float2* pms = (float2*)symf(g_pms);
    float2* st2 = (float2*)symf(g_stat2);

    // 1. layernorm
    ln_kernel<<<TROWS, 256>>>(x, gamma, beta, ln);

    // 2. qkv gemm (tf32) with head scatter + q scale
    tgemm_nn<0><<<dim3(12, 256), 256>>>(ln, w_qkv, DD, 3 * DD, 0, 0, 0, q, k, v);

    // 3. landmarks
    landmark_kernel<<<dim3(MM, GG), 64>>>(q, k, ql, kl);

    // 4. s2 = ql @ kl^T, softmax
    tgemm_nt<<<dim3(2, 2, GG), 256>>>(ql, kl, s2, MM, MM);
    rowstat_kernel<<<GG * MM, 256>>>(s2, st2, MM);
    apply_softmax_kernel<<<GG * MM * MM / 256, 256>>>(s2, st2, a2);

    // 5. pinv init: z = a2^T / (max rowsum * max colsum)
    zero_scale_kernel<<<1, 32>>>();
    pinv_reduce_kernel<<<GG, 256>>>();
    z_init_kernel<<<GG * MM * MM / 256, 256>>>();

    // 6. Newton-Schulz (tf32): z = 0.25 z (13I - X(15I - X(7I - X))), X = a2 z
    for (int it = 0; it < 6; it++) {
        float* zin  = (it & 1) ? zB : zA;
        float* zout = (it & 1) ? zA : zB;
        tgemm_b256<<<dim3(4, 2, GG), 256>>>(a2,  zin, t1, MM, 0.f,  1.f, 0.f, 1.f);
        tgemm_b256<<<dim3(4, 2, GG), 256>>>(t1,  t1,  t2, MM, 7.f, -1.f, 0.f, 1.f);
        tgemm_b256<<<dim3(4, 2, GG), 256>>>(t1,  t2,  t3, MM, 15.f, -1.f, 0.f, 1.f);
        tgemm_b256<<<dim3(4, 2, GG), 256>>>(zin, t3, zout, MM, 13.f, -1.f, 0.f, 0.25f);
    }
    float* zfin = zA;  // after 6 iterations result is in zA

    // 7. kv = softmax(ql @ k^T) @ v  — fused flash, key-split 4, then combine
    flash_kernel<KSPL><<<dim3(2, KSPL, GG), 256>>>(ql, k, v, po, pms, MM, NN);
    flash_combine_kernel<<<GG * MM * DHH / 256, 256>>>();

    // 8. Dm = pinv @ kv  (tf32)
    tgemm_b256<<<dim3(1, 2, GG), 256>>>(zfin, kv, Dm, DHH, 0.f, 1.f, 0.f, 1.f);

    // 9. o1 = softmax(q @ kl^T) @ Dm — fused flash, no split
    flash_kernel<1><<<dim3(64, 1, GG), 256>>>(q, kl, Dm, o1, 0, NN, MM);

    // 10. conv residual + merge heads
    conv_combine_kernel<<<dim3(NN / 64, GG), 256>>>(v, o1, conv_w, ao);

    // 11. final: out = ao @ w_out + b_out + x  (tf32)
    tgemm_nn<1><<<dim3(4, 256), 256>>>(ao, w_out, DD, DD, x, b_out, out, 0, 0, 0);
}

// round 7
// speedup vs baseline: 2.7269x; 1.1281x over previous
#include <cuda_runtime.h>
#include <math.h>
#include <stdint.h>

#define BB 4
#define NN 8192
#define DD 512
#define HH 8
#define DHH 64
#define MM 256
#define GG 32           // BB*HH
#define TROWS 32768     // BB*NN
#define KSPL 8          // key splits for flash kv

// ---------------- static device scratch ----------------
__device__ float g_ln[(size_t)TROWS * DD];
__device__ float g_q[(size_t)GG * NN * DHH];
__device__ float g_k[(size_t)GG * NN * DHH];
__device__ float g_v[(size_t)GG * NN * DHH];
__device__ float g_ql[GG * MM * DHH];
__device__ float g_kl[GG * MM * DHH];
__device__ float g_s2[GG * MM * MM];
__device__ float g_a2[GG * MM * MM];
__device__ float g_zA[GG * MM * MM];
__device__ float g_zB[GG * MM * MM];
__device__ float g_t1[GG * MM * MM];
__device__ float g_t2[GG * MM * MM];
__device__ float g_t3[GG * MM * MM];
__device__ float g_po[(size_t)GG * KSPL * MM * DHH];
__device__ float2 g_pms[GG * KSPL * MM];
__device__ float g_kv[GG * MM * DHH];
__device__ float g_Dm[GG * MM * DHH];
__device__ float g_o1[(size_t)GG * NN * DHH];
__device__ float g_ao[(size_t)TROWS * DD];
__device__ float2 g_stat2[GG * MM];
__device__ int    g_scaleI[2];

// ---------------- helpers ----------------
__device__ __forceinline__ void cpa16(void* s, const void* g) {
    uint32_t sa = (uint32_t)__cvta_generic_to_shared(s);
    asm volatile("cp.async.cg.shared.global [%0], [%1], 16;" :: "r"(sa), "l"(g));
}
#define CP_COMMIT() asm volatile("cp.async.commit_group;")
#define CP_WAIT(n)  asm volatile("cp.async.wait_group %0;" :: "n"(n))

// mma.tf32 consumes raw fp32 bits (HW truncates low 13 mantissa bits).
__device__ __forceinline__ void mma8(float* d, const uint32_t* a, const uint32_t* b) {
    asm volatile(
        "mma.sync.aligned.m16n8k8.row.col.f32.tf32.tf32.f32 "
        "{%0,%1,%2,%3}, {%4,%5,%6,%7}, {%8,%9}, {%0,%1,%2,%3};"
        : "+f"(d[0]), "+f"(d[1]), "+f"(d[2]), "+f"(d[3])
        : "r"(a[0]), "r"(a[1]), "r"(a[2]), "r"(a[3]), "r"(b[0]), "r"(b[1]));
}

// ---------------- layernorm ----------------
__global__ void ln_kernel(const float* __restrict__ x, const float* __restrict__ gamma,
                          const float* __restrict__ beta, float* __restrict__ out) {
    int row = blockIdx.x;
    const float* xr = x + (size_t)row * DD;
    int t = threadIdx.x;
    float v0 = xr[t], v1 = xr[t + 256];
    float s = v0 + v1, ss = v0 * v0 + v1 * v1;
    #pragma unroll
    for (int o = 16; o; o >>= 1) {
        s  += __shfl_down_sync(0xffffffffu, s, o);
        ss += __shfl_down_sync(0xffffffffu, ss, o);
    }
    __shared__ float rs[8], rss[8];
    int w = t >> 5, l = t & 31;
    if (l == 0) { rs[w] = s; rss[w] = ss; }
    __syncthreads();
    __shared__ float s_mu, s_rstd;
    if (t == 0) {
        float a = 0.f, b = 0.f;
        #pragma unroll
        for (int i = 0; i < 8; i++) { a += rs[i]; b += rss[i]; }
        float mu = a * (1.f / DD);
        float var = b * (1.f / DD) - mu * mu;
        s_mu = mu; s_rstd = rsqrtf(var + 1e-5f);
    }
    __syncthreads();
    float mu = s_mu, rstd = s_rstd;
    float* orow = out + (size_t)row * DD;
    orow[t]       = (v0 - mu) * rstd * gamma[t]       + beta[t];
    orow[t + 256] = (v1 - mu) * rstd * gamma[t + 256] + beta[t + 256];
}

// ---------------- tf32 NN gemm 128x128xK, cp.async double-buffered ----------
// MODE 0: C = A@B scattered into q/k/v head layout (q scaled 0.125)
// MODE 1: out = A@B + xres + bias
template <int MODE>
__global__ void __launch_bounds__(256) tgemm_nn(
        const float* __restrict__ A, const float* __restrict__ Bm,
        int Kdim, int Ncols,
        const float* __restrict__ xres, const float* __restrict__ bias,
        float* __restrict__ outp,
        float* __restrict__ oq, float* __restrict__ okk, float* __restrict__ ov) {
    __shared__ uint32_t As[2][128 * 20];   // [m][k] pad 4
    __shared__ uint32_t Bs[2][16 * 136];   // [k][n] pad 8
    int t = threadIdx.x;
    int warp = t >> 5, lane = t & 31;
    int wm = warp >> 2, wn = warp & 3;
    int g8 = lane >> 2, tg = lane & 3;
    int brow = blockIdx.y * 128, bcol = blockIdx.x * 128;
    float acc[4][4][4];
    #pragma unroll
    for (int i = 0; i < 4; i++)
        #pragma unroll
        for (int j = 0; j < 4; j++)
            #pragma unroll
            for (int r = 0; r < 4; r++) acc[i][j][r] = 0.f;

    int ar = t >> 2, akq = (t & 3) * 4;
    int bkr = t >> 5, bnq = (t & 31) * 4;

    // prologue: stage tile 0
    {
        #pragma unroll
        for (int i = 0; i < 2; i++) {
            int r = ar + i * 64;
            cpa16(&As[0][r * 20 + akq], &A[(size_t)(brow + r) * Kdim + akq]);
        }
        #pragma unroll
        for (int i = 0; i < 2; i++) {
            int kr = bkr + i * 8;
            cpa16(&Bs[0][kr * 136 + bnq], &Bm[(size_t)kr * Ncols + bcol + bnq]);
        }
        CP_COMMIT();
    }

    int buf = 0;
    for (int k0 = 0; k0 < Kdim; k0 += 16) {
        if (k0 + 16 < Kdim) {
            int nb = buf ^ 1, kn = k0 + 16;
            #pragma unroll
            for (int i = 0; i < 2; i++) {
                int r = ar + i * 64;
                cpa16(&As[nb][r * 20 + akq], &A[(size_t)(brow + r) * Kdim + kn + akq]);
            }
            #pragma unroll
            for (int i = 0; i < 2; i++) {
                int kr = bkr + i * 8;
                cpa16(&Bs[nb][kr * 136 + bnq], &Bm[(size_t)(kn + kr) * Ncols + bcol + bnq]);
            }
            CP_COMMIT();
            CP_WAIT(1);
        } else {
            CP_WAIT(0);
        }
        __syncthreads();
        #pragma unroll
        for (int kk = 0; kk < 16; kk += 8) {
            uint32_t af[4][4], bf[4][2];
            #pragma unroll
            for (int mi = 0; mi < 4; mi++) {
                int rm = wm * 64 + mi * 16;
                af[mi][0] = As[buf][(rm + g8)     * 20 + kk + tg];
                af[mi][1] = As[buf][(rm + g8 + 8) * 20 + kk + tg];
                af[mi][2] = As[buf][(rm + g8)     * 20 + kk + tg + 4];
                af[mi][3] = As[buf][(rm + g8 + 8) * 20 + kk + tg + 4];
            }
            #pragma unroll
            for (int ni = 0; ni < 4; ni++) {
                int nb2 = wn * 32 + ni * 8 + g8;
                bf[ni][0] = Bs[buf][(kk + tg)     * 136 + nb2];
                bf[ni][1] = Bs[buf][(kk + tg + 4) * 136 + nb2];
            }
            #pragma unroll
            for (int mi = 0; mi < 4; mi++)
                #pragma unroll
                for (int ni = 0; ni < 4; ni++)
                    mma8(acc[mi][ni], af[mi], bf[ni]);
        }
        __syncthreads();
        buf ^= 1;
    }

    #pragma unroll
    for (int mi = 0; mi < 4; mi++) {
        #pragma unroll
        for (int ni = 0; ni < 4; ni++) {
            int c = bcol + wn * 32 + ni * 8 + tg * 2;
            #pragma unroll
            for (int half = 0; half < 2; half++) {
                int r = brow + wm * 64 + mi * 16 + g8 + half * 8;
                float v0 = acc[mi][ni][half * 2 + 0];
                float v1 = acc[mi][ni][half * 2 + 1];
                if (MODE == 0) {
                    int part = c >> 9, h = (c >> 6) & 7, d = c & 63;
                    int bidx = r >> 13, n = r & 8191;
                    size_t dst = (((size_t)(bidx * HH + h)) * NN + n) * DHH + d;
                    if (part == 0)      { oq[dst] = v0 * 0.125f; oq[dst + 1] = v1 * 0.125f; }
                    else if (part == 1) { okk[dst] = v0;         okk[dst + 1] = v1; }
                    else                { ov[dst] = v0;          ov[dst + 1] = v1; }
                } else {
                    size_t o = (size_t)r * Ncols + c;
                    outp[o]     = v0 + xres[o]     + bias[c];
                    outp[o + 1] = v1 + xres[o + 1] + bias[c + 1];
                }
            }
        }
    }
}

// ---------------- landmark means ----------------
__global__ void landmark_kernel(const float* __restrict__ q, const float* __restrict__ k,
                                float* __restrict__ ql, float* __restrict__ kl) {
    int g = blockIdx.y, m = blockIdx.x, d = threadIdx.x;
    const float* qp = q + ((size_t)g * NN + m * 32) * DHH + d;
    const float* kp = k + ((size_t)g * NN + m * 32) * DHH + d;
    float sq = 0.f, sk = 0.f;
    #pragma unroll
    for (int i = 0; i < 32; i++) { sq += qp[i * DHH]; sk += kp[i * DHH]; }
    ql[(g * MM + m) * DHH + d] = sq * (1.f / 32.f);
    kl[(g * MM + m) * DHH + d] = sk * (1.f / 32.f);
}

// ---------------- tf32 NT gemm over dh=64 (s2 only): C = A @ B^T -------------
__global__ void __launch_bounds__(256) tgemm_nt(
        const float* __restrict__ A, const float* __restrict__ Bm,
        float* __restrict__ C, int RA, int RB) {
    __shared__ uint32_t As[128 * 20];
    __shared__ uint32_t Bs[128 * 20];
    int t = threadIdx.x, g = blockIdx.z;
    int warp = t >> 5, lane = t & 31;
    int wm = warp >> 2, wn = warp & 3;
    int g8 = lane >> 2, tg = lane & 3;
    int gr0 = blockIdx.y * 128, gc0 = blockIdx.x * 128;
    float acc[4][4][4];
    #pragma unroll
    for (int i = 0; i < 4; i++)
        #pragma unroll
        for (int j = 0; j < 4; j++)
            #pragma unroll
            for (int r = 0; r < 4; r++) acc[i][j][r] = 0.f;

    for (int k0 = 0; k0 < 64; k0 += 16) {
        #pragma unroll
        for (int i = 0; i < 2; i++) {
            int s = t + i * 256;
            int r = s >> 2, kq = (s & 3) * 4;
            cpa16(&As[r * 20 + kq], &A[((size_t)g * RA + gr0 + r) * DHH + k0 + kq]);
            cpa16(&Bs[r * 20 + kq], &Bm[((size_t)g * RB + gc0 + r) * DHH + k0 + kq]);
        }
        CP_COMMIT();
        CP_WAIT(0);
        __syncthreads();
        #pragma unroll
        for (int kk = 0; kk < 16; kk += 8) {
            uint32_t af[4][4], bf[4][2];
            #pragma unroll
            for (int mi = 0; mi < 4; mi++) {
                int rm = wm * 64 + mi * 16;
                af[mi][0] = As[(rm + g8)     * 20 + kk + tg];
                af[mi][1] = As[(rm + g8 + 8) * 20 + kk + tg];
                af[mi][2] = As[(rm + g8)     * 20 + kk + tg + 4];
                af[mi][3] = As[(rm + g8 + 8) * 20 + kk + tg + 4];
            }
            #pragma unroll
            for (int ni = 0; ni < 4; ni++) {
                int nb = wn * 32 + ni * 8 + g8;
                bf[ni][0] = Bs[nb * 20 + kk + tg];
                bf[ni][1] = Bs[nb * 20 + kk + tg + 4];
            }
            #pragma unroll
            for (int mi = 0; mi < 4; mi++)
                #pragma unroll
                for (int ni = 0; ni < 4; ni++)
                    mma8(acc[mi][ni], af[mi], bf[ni]);
        }
        __syncthreads();
    }

    #pragma unroll
    for (int mi = 0; mi < 4; mi++) {
        #pragma unroll
        for (int ni = 0; ni < 4; ni++) {
            int c = gc0 + wn * 32 + ni * 8 + tg * 2;
            #pragma unroll
            for (int half = 0; half < 2; half++) {
                int r = gr0 + wm * 64 + mi * 16 + g8 + half * 8;
                size_t o = ((size_t)g * RA + r) * RB + c;
                *(float2*)&C[o] = make_float2(acc[mi][ni][half * 2 + 0],
                                              acc[mi][ni][half * 2 + 1]);
            }
        }
    }
}

// ---------------- fused flash: out = softmax(A@B^T) @ V ---------------------
template <int NSPL>
__global__ void __launch_bounds__(256) flash_kernel(
        const float* __restrict__ Aq, const float* __restrict__ Bk,
        const float* __restrict__ Vv, float* __restrict__ outp,
        float2* __restrict__ pms, int RA, int RB) {
    __shared__ uint32_t smbuf[8960];      // K:[64][68] + V:[64][72]; Q staging [128][68]
    uint32_t* Ks = smbuf;
    uint32_t* Vs = smbuf + 64 * 68;
    int t = threadIdx.x, g = blockIdx.z, spl = blockIdx.y;
    int brow = blockIdx.x * 128;
    int warp = t >> 5, lane = t & 31, g8 = lane >> 2, tg = lane & 3;
    size_t gA = (size_t)g * RA, gB = (size_t)g * RB;
    int klen = RB / NSPL, kst = spl * klen;

    // stage Q (128x64) -> frags
    #pragma unroll
    for (int i = 0; i < 8; i++) {
        int s = t + i * 256; int r = s >> 4, c4 = (s & 15) * 4;
        cpa16(&smbuf[r * 68 + c4], &Aq[(gA + brow + r) * DHH + c4]);
    }
    CP_COMMIT();
    CP_WAIT(0);
    __syncthreads();
    uint32_t qf[8][4];
    {
        int r0 = (warp * 16 + g8) * 68, r1 = (warp * 16 + g8 + 8) * 68;
        #pragma unroll
        for (int kc = 0; kc < 8; kc++) {
            qf[kc][0] = smbuf[r0 + kc * 8 + tg];
            qf[kc][1] = smbuf[r1 + kc * 8 + tg];
            qf[kc][2] = smbuf[r0 + kc * 8 + tg + 4];
            qf[kc][3] = smbuf[r1 + kc * 8 + tg + 4];
        }
    }
    __syncthreads();

    float o[8][4];
    #pragma unroll
    for (int i = 0; i < 8; i++)
        #pragma unroll
        for (int j = 0; j < 4; j++) o[i][j] = 0.f;
    float m0 = -1e30f, m1 = -1e30f, l0 = 0.f, l1 = 0.f;
    int srcl = (lane & ~3) | (tg >> 1);

    for (int kb = 0; kb < klen; kb += 64) {
        #pragma unroll
        for (int i = 0; i < 4; i++) {
            int s = t + i * 256; int r = s >> 4, c4 = (s & 15) * 4;
            size_t src = (gB + kst + kb + r) * DHH + c4;
            cpa16(&Ks[r * 68 + c4], &Bk[src]);
            cpa16(&Vs[r * 72 + c4], &Vv[src]);
        }
        CP_COMMIT();
        CP_WAIT(0);
        __syncthreads();

        // S = Q @ K^T : 16 rows x 64 keys per warp
        float sv[8][4];
        #pragma unroll
        for (int nt = 0; nt < 8; nt++)
            #pragma unroll
            for (int j = 0; j < 4; j++) sv[nt][j] = 0.f;
        #pragma unroll
        for (int nt = 0; nt < 8; nt++) {
            #pragma unroll
            for (int kc = 0; kc < 8; kc++) {
                uint32_t bf[2];
                bf[0] = Ks[(nt * 8 + g8) * 68 + kc * 8 + tg];
                bf[1] = Ks[(nt * 8 + g8) * 68 + kc * 8 + tg + 4];
                mma8(sv[nt], qf[kc], bf);
            }
        }

        // online softmax (rows g8 and g8+8; quads share rows)
        float tm0 = -1e30f, tm1 = -1e30f;
        #pragma unroll
        for (int nt = 0; nt < 8; nt++) {
            tm0 = fmaxf(tm0, fmaxf(sv[nt][0], sv[nt][1]));
            tm1 = fmaxf(tm1, fmaxf(sv[nt][2], sv[nt][3]));
        }
        tm0 = fmaxf(tm0, __shfl_xor_sync(0xffffffffu, tm0, 1));
        tm0 = fmaxf(tm0, __shfl_xor_sync(0xffffffffu, tm0, 2));
        tm1 = fmaxf(tm1, __shfl_xor_sync(0xffffffffu, tm1, 1));
        tm1 = fmaxf(tm1, __shfl_xor_sync(0xffffffffu, tm1, 2));
        float m0n = fmaxf(m0, tm0), m1n = fmaxf(m1, tm1);
        float al0 = __expf(m0 - m0n), al1 = __expf(m1 - m1n);
        m0 = m0n; m1 = m1n;
        l0 *= al0; l1 *= al1;
        #pragma unroll
        for (int nv = 0; nv < 8; nv++) {
            o[nv][0] *= al0; o[nv][1] *= al0; o[nv][2] *= al1; o[nv][3] *= al1;
        }

        // P = exp(S - m); C-frag -> A-frag layout via quad shuffles
        uint32_t pf[8][4];
        #pragma unroll
        for (int nt = 0; nt < 8; nt++) {
            float p0 = __expf(sv[nt][0] - m0), p1 = __expf(sv[nt][1] - m0);
            float p2 = __expf(sv[nt][2] - m1), p3 = __expf(sv[nt][3] - m1);
            l0 += p0 + p1; l1 += p2 + p3;
            float e, od;
            e  = __shfl_sync(0xffffffffu, p0, srcl);
            od = __shfl_sync(0xffffffffu, p1, srcl);
            float a0v = (tg & 1) ? od : e;
            e  = __shfl_sync(0xffffffffu, p2, srcl);
            od = __shfl_sync(0xffffffffu, p3, srcl);
            float a1v = (tg & 1) ? od : e;
            e  = __shfl_sync(0xffffffffu, p0, srcl + 2);
            od = __shfl_sync(0xffffffffu, p1, srcl + 2);
            float a2v = (tg & 1) ? od : e;
            e  = __shfl_sync(0xffffffffu, p2, srcl + 2);
            od = __shfl_sync(0xffffffffu, p3, srcl + 2);
            float a3v = (tg & 1) ? od : e;
            pf[nt][0] = __float_as_uint(a0v); pf[nt][1] = __float_as_uint(a1v);
            pf[nt][2] = __float_as_uint(a2v); pf[nt][3] = __float_as_uint(a3v);
        }

        // O += P @ V
        #pragma unroll
        for (int nv = 0; nv < 8; nv++) {
            #pragma unroll
            for (int kc = 0; kc < 8; kc++) {
                uint32_t bf[2];
                bf[0] = Vs[(kc * 8 + tg) * 72 + nv * 8 + g8];
                bf[1] = Vs[(kc * 8 + tg + 4) * 72 + nv * 8 + g8];
                mma8(o[nv], pf[kc], bf);
            }
        }
        __syncthreads();
    }

    l0 += __shfl_xor_sync(0xffffffffu, l0, 1);
    l0 += __shfl_xor_sync(0xffffffffu, l0, 2);
    l1 += __shfl_xor_sync(0xffffffffu, l1, 1);
    l1 += __shfl_xor_sync(0xffffffffu, l1, 2);

    int lr0 = brow + warp * 16 + g8;
    if (NSPL == 1) {
        float i0 = 1.f / l0, i1 = 1.f / l1;
        #pragma unroll
        for (int nv = 0; nv < 8; nv++) {
            size_t oo = (gA + lr0) * DHH + nv * 8 + tg * 2;
            *(float2*)&outp[oo]            = make_float2(o[nv][0] * i0, o[nv][1] * i0);
            *(float2*)&outp[oo + 8 * DHH]  = make_float2(o[nv][2] * i1, o[nv][3] * i1);
        }
    } else {
        size_t pbase = (size_t)(g * NSPL + spl) * RA;
        #pragma unroll
        for (int nv = 0; nv < 8; nv++) {
            size_t oo = (pbase + lr0) * DHH + nv * 8 + tg * 2;
            *(float2*)&outp[oo]           = make_float2(o[nv][0], o[nv][1]);
            *(float2*)&outp[oo + 8 * DHH] = make_float2(o[nv][2], o[nv][3]);
        }
        if (tg == 0) {
            pms[pbase + lr0]     = make_float2(m0, l0);
            pms[pbase + lr0 + 8] = make_float2(m1, l1);
        }
    }
}

// combine KSPL flash partials -> g_kv
__global__ void flash_combine_kernel() {
    long long i = (long long)blockIdx.x * 256 + threadIdx.x;   // GG*MM*DHH
    int g = (int)(i / (MM * DHH));
    int rem = (int)(i % (MM * DHH));
    int row = rem / DHH, d = rem % DHH;
    float gm = -1e30f;
    float2 ms[KSPL];
    #pragma unroll
    for (int s = 0; s < KSPL; s++) {
        ms[s] = g_pms[(g * KSPL + s) * MM + row];
        gm = fmaxf(gm, ms[s].x);
    }
    float denom = 0.f, val = 0.f;
    #pragma unroll
    for (int s = 0; s < KSPL; s++) {
        float w = __expf(ms[s].x - gm);
        denom += ms[s].y * w;
        val += g_po[((size_t)(g * KSPL + s) * MM + row) * DHH + d] * w;
    }
    g_kv[i] = val / denom;
}

// ---------------- row softmax stats (s2 only) ----------------
__global__ void rowstat_kernel(const float* __restrict__ S, float2* __restrict__ stat, int NC) {
    long long row = blockIdx.x;
    const float* p = S + row * (long long)NC;
    int t = threadIdx.x;
    float tm = -1e30f, ts = 0.f;
    for (int c = t; c < NC; c += 256) {
        float v = p[c];
        if (v > tm) { ts = ts * __expf(tm - v) + 1.f; tm = v; }
        else ts += __expf(v - tm);
    }
    #pragma unroll
    for (int o = 16; o; o >>= 1) {
        float om = __shfl_down_sync(0xffffffffu, tm, o);
        float os = __shfl_down_sync(0xffffffffu, ts, o);
        float nm = fmaxf(tm, om);
        ts = ts * __expf(tm - nm) + os * __expf(om - nm);
        tm = nm;
    }
    __shared__ float smx[8], ssm[8];
    if ((t & 31) == 0) { smx[t >> 5] = tm; ssm[t >> 5] = ts; }
    __syncthreads();
    if (t == 0) {
        tm = smx[0]; ts = ssm[0];
        #pragma unroll
        for (int w = 1; w < 8; w++) {
            float om = smx[w], os = ssm[w];
            float nm = fmaxf(tm, om);
            ts = ts * __expf(tm - nm) + os * __expf(om - nm);
            tm = nm;
        }
        stat[row] = make_float2(tm, 1.f / ts);
    }
}

__global__ void apply_softmax_kernel(const float* __restrict__ S, const float2* __restrict__ stat,
                                     float* __restrict__ out) {
    long long i = (long long)blockIdx.x * 256 + threadIdx.x;
    float2 st = stat[i >> 8];
    out[i] = __expf(S[i] - st.x) * st.y;
}

// ---------------- pinv init ----------------
__global__ void zero_scale_kernel() { if (threadIdx.x < 2) g_scaleI[threadIdx.x] = 0; }

__global__ void pinv_reduce_kernel() {
    int g = blockIdx.x, j = threadIdx.x;
    const float* a = g_a2 + (long long)g * MM * MM;
    float rs = 0.f, cs = 0.f;
    for (int c = 0; c < MM; c++) { rs += a[j * MM + c]; cs += a[c * MM + j]; }
    __shared__ float r0[256], r1[256];
    r0[j] = rs; r1[j] = cs;
    __syncthreads();
    for (int o = 128; o; o >>= 1) {
        if (j < o) { r0[j] = fmaxf(r0[j], r0[j + o]); r1[j] = fmaxf(r1[j], r1[j + o]); }
        __syncthreads();
    }
    if (j == 0) {
        atomicMax(&g_scaleI[0], __float_as_int(r0[0]));
        atomicMax(&g_scaleI[1], __float_as_int(r1[0]));
    }
}

__global__ void z_init_kernel() {
    long long i = (long long)blockIdx.x * 256 + threadIdx.x;
    float scale = 1.f / (__int_as_float(g_scaleI[0]) * __int_as_float(g_scaleI[1]));
    int g = (int)(i >> 16), r = (int)((i >> 8) & 255), c = (int)(i & 255);
    g_zA[i] = g_a2[((long long)g << 16) + (c << 8) + r] * scale;
}

// ---------------- tf32 batched 256-K gemm, cp.async double-buffered ---------
// C = c0*I + c1 * ( A @ (b0*I + b1*B) );  A:[g][256][256], B:[g][256][NC]
__global__ void __launch_bounds__(256) tgemm_b256(
        const float* __restrict__ A, const float* __restrict__ Bm,
        float* __restrict__ C, int NC,
        float b0c, float b1c, float c0c, float c1c) {
    __shared__ uint32_t As[2][128 * 20];
    __shared__ uint32_t Bs[2][16 * 72];
    int t = threadIdx.x, g = blockIdx.z;
    int warp = t >> 5, lane = t & 31;
    int wm = warp >> 2, wn = warp & 3;
    int g8 = lane >> 2, tg = lane & 3;
    int gr0 = blockIdx.y * 128, gc0 = blockIdx.x * 64;
    const float* Ag = A + (size_t)g * MM * MM;
    const float* Bg = Bm + (size_t)g * MM * NC;
    float acc[4][2][4];
    #pragma unroll
    for (int i = 0; i < 4; i++)
        #pragma unroll
        for (int j = 0; j < 2; j++)
            #pragma unroll
            for (int r = 0; r < 4; r++) acc[i][j][r] = 0.f;

    int ar = t >> 2, akq = (t & 3) * 4;
    int bkr = t >> 4, bnq = (t & 15) * 4;

    {
        #pragma unroll
        for (int i = 0; i < 2; i++) {
            int r = ar + i * 64;
            cpa16(&As[0][r * 20 + akq], &Ag[(size_t)(gr0 + r) * MM + akq]);
        }
        cpa16(&Bs[0][bkr * 72 + bnq], &Bg[(size_t)bkr * NC + gc0 + bnq]);
        CP_COMMIT();
    }

    int buf = 0;
    for (int k0 = 0; k0 < MM; k0 += 16) {
        if (k0 + 16 < MM) {
            int nb = buf ^ 1, kn = k0 + 16;
            #pragma unroll
            for (int i = 0; i < 2; i++) {
                int r = ar + i * 64;
                cpa16(&As[nb][r * 20 + akq], &Ag[(size_t)(gr0 + r) * MM + kn + akq]);
            }
            cpa16(&Bs[nb][bkr * 72 + bnq], &Bg[(size_t)(kn + bkr) * NC + gc0 + bnq]);
            CP_COMMIT();
            CP_WAIT(1);
        } else {
            CP_WAIT(0);
        }
        __syncthreads();
        #pragma unroll
        for (int kk = 0; kk < 16; kk += 8) {
            uint32_t af[4][4], bf[2][2];
            #pragma unroll
            for (int mi = 0; mi < 4; mi++) {
                int rm = wm * 64 + mi * 16;
                af[mi][0] = As[buf][(rm + g8)     * 20 + kk + tg];
                af[mi][1] = As[buf][(rm + g8 + 8) * 20 + kk + tg];
                af[mi][2] = As[buf][(rm + g8)     * 20 + kk + tg + 4];
                af[mi][3] = As[buf][(rm + g8 + 8) * 20 + kk + tg + 4];
            }
            #pragma unroll
            for (int ni = 0; ni < 2; ni++) {
                int nb2 = wn * 16 + ni * 8 + g8;
                // fused B transform: b1*B + b0*I  (diag in global k/col coords)
                float r0v = __uint_as_float(Bs[buf][(kk + tg)     * 72 + nb2]);
                float r1v = __uint_as_float(Bs[buf][(kk + tg + 4) * 72 + nb2]);
                int kg = k0 + kk + tg, cg = gc0 + nb2;
                float f0 = b1c * r0v + ((kg     == cg) ? b0c : 0.f);
                float f1 = b1c * r1v + ((kg + 4 == cg) ? b0c : 0.f);
                bf[ni][0] = __float_as_uint(f0);
                bf[ni][1] = __float_as_uint(f1);
            }
            #pragma unroll
            for (int mi = 0; mi < 4; mi++)
                #pragma unroll
                for (int ni = 0; ni < 2; ni++)
                    mma8(acc[mi][ni], af[mi], bf[ni]);
        }
        __syncthreads();
        buf ^= 1;
    }

    #pragma unroll
    for (int mi = 0; mi < 4; mi++) {
        #pragma unroll
        for (int ni = 0; ni < 2; ni++) {
            int c = gc0 + wn * 16 + ni * 8 + tg * 2;
            #pragma unroll
            for (int half = 0; half < 2; half++) {
                int r = gr0 + wm * 64 + mi * 16 + g8 + half * 8;
                float o0 = c1c * acc[mi][ni][half * 2 + 0] + (r == c     ? c0c : 0.f);
                float o1 = c1c * acc[mi][ni][half * 2 + 1] + (r == c + 1 ? c0c : 0.f);
                *(float2*)&C[((size_t)g * MM + r) * NC + c] = make_float2(o0, o1);
            }
        }
    }
}

// ---------------- depthwise conv-33 over seq + head merge ----------------
__global__ void conv_combine_kernel(const float* __restrict__ v, const float* __restrict__ o1,
                                    const float* __restrict__ cw, float* __restrict__ ao) {
    int g = blockIdx.y;
    int h = g & 7, b = g >> 3;
    int n0 = blockIdx.x * 64;
    __shared__ float sv[96 * 64];
    __shared__ float ws[33];
    int t = threadIdx.x;
    if (t < 33) ws[t] = cw[h * 33 + t];
    const float* vg = v + (size_t)g * NN * DHH;
    for (int i = t; i < 96 * 64; i += 256) {
        int r = i >> 6, d = i & 63;
        int n = n0 - 16 + r;
        sv[i] = (n >= 0 && n < NN) ? vg[(size_t)n * DHH + d] : 0.f;
    }
    __syncthreads();
    int d = t & 63, nl0 = t >> 6;
    for (int i = 0; i < 16; i++) {
        int nl = nl0 + i * 4;
        float acc = 0.f;
        #pragma unroll
        for (int kk = 0; kk < 33; kk++) acc += ws[kk] * sv[(nl + kk) * 64 + d];
        int n = n0 + nl;
        ao[((size_t)b * NN + n) * DD + h * 64 + d] =
            o1[((size_t)g * NN + n) * DHH + d] + acc;
    }
}

// ---------------- host ----------------
static float* symf(const void* s) { void* p = 0; cudaGetSymbolAddress(&p, s); return (float*)p; }

extern "C" void kernel_launch(void* const* d_in, const int* in_sizes, int n_in,
                              void* d_out, int out_size) {
    const float* x      = (const float*)d_in[0];
    const float* gamma  = (const float*)d_in[1];
    const float* beta   = (const float*)d_in[2];
    const float* w_qkv  = (const float*)d_in[3];
    const float* w_out  = (const float*)d_in[4];
    const float* b_out  = (const float*)d_in[5];
    const float* conv_w = (const float*)d_in[6];
    float* out = (float*)d_out;

    float* ln   = symf(g_ln);
    float* q    = symf(g_q);
    float* k    = symf(g_k);
    float* v    = symf(g_v);
    float* ql   = symf(g_ql);
    float* kl   = symf(g_kl);
    float* s2   = symf(g_s2);
    float* a2   = symf(g_a2);
    float* zA   = symf(g_zA);
    float* zB   = symf(g_zB);
    float* t1   = symf(g_t1);
    float* t2   = symf(g_t2);
    float* t3   = symf(g_t3);
    float* po   = symf(g_po);
    float* kv   = symf(g_kv);
    float* Dm   = symf(g_Dm);
    float* o1   = symf(g_o1);
    float* ao   = symf(g_ao);
    float2* pms = (float2*)symf(g_pms);
    float2* st2 = (float2*)symf(g_stat2);

    // 1. layernorm
    ln_kernel<<<TROWS, 256>>>(x, gamma, beta, ln);

    // 2. qkv gemm (tf32, cp.async) with head scatter + q scale
    tgemm_nn<0><<<dim3(12, 256), 256>>>(ln, w_qkv, DD, 3 * DD, 0, 0, 0, q, k, v);

    // 3. landmarks
    landmark_kernel<<<dim3(MM, GG), 64>>>(q, k, ql, kl);

    // 4. s2 = ql @ kl^T, softmax
    tgemm_nt<<<dim3(2, 2, GG), 256>>>(ql, kl, s2, MM, MM);
    rowstat_kernel<<<GG * MM, 256>>>(s2, st2, MM);
    apply_softmax_kernel<<<GG * MM * MM / 256, 256>>>(s2, st2, a2);

    // 5. pinv init: z = a2^T / (max rowsum * max colsum)
    zero_scale_kernel<<<1, 32>>>();
    pinv_reduce_kernel<<<GG, 256>>>();
    z_init_kernel<<<GG * MM * MM / 256, 256>>>();

    // 6. Newton-Schulz (tf32): z = 0.25 z (13I - X(15I - X(7I - X))), X = a2 z
    for (int it = 0; it < 6; it++) {
        float* zin  = (it & 1) ? zB : zA;
        float* zout = (it & 1) ? zA : zB;
        tgemm_b256<<<dim3(4, 2, GG), 256>>>(a2,  zin, t1, MM, 0.f,  1.f, 0.f, 1.f);
        tgemm_b256<<<dim3(4, 2, GG), 256>>>(t1,  t1,  t2, MM, 7.f, -1.f, 0.f, 1.f);
        tgemm_b256<<<dim3(4, 2, GG), 256>>>(t1,  t2,  t3, MM, 15.f, -1.f, 0.f, 1.f);
        tgemm_b256<<<dim3(4, 2, GG), 256>>>(zin, t3, zout, MM, 13.f, -1.f, 0.f, 0.25f);
    }
    float* zfin = zA;  // after 6 iterations result is in zA

    // 7. kv = softmax(ql @ k^T) @ v  — fused flash, key-split 8, then combine
    flash_kernel<KSPL><<<dim3(2, KSPL, GG), 256>>>(ql, k, v, po, pms, MM, NN);
    flash_combine_kernel<<<GG * MM * DHH / 256, 256>>>();

    // 8. Dm = pinv @ kv  (tf32)
    tgemm_b256<<<dim3(1, 2, GG), 256>>>(zfin, kv, Dm, DHH, 0.f, 1.f, 0.f, 1.f);

    // 9. o1 = softmax(q @ kl^T) @ Dm — fused flash, no split
    flash_kernel<1><<<dim3(64, 1, GG), 256>>>(q, kl, Dm, o1, 0, NN, MM);

    // 10. conv residual + merge heads
    conv_combine_kernel<<<dim3(NN / 64, GG), 256>>>(v, o1, conv_w, ao);

    // 11. final: out = ao @ w_out + b_out + x  (tf32)
    tgemm_nn<1><<<dim3(4, 256), 256>>>(ao, w_out, DD, DD, x, b_out, out, 0, 0, 0);
}

// round 8
// speedup vs baseline: 3.0036x; 1.1015x over previous
#include <cuda_runtime.h>
#include <math.h>
#include <stdint.h>

#define BB 4
#define NN 8192
#define DD 512
#define HH 8
#define DHH 64
#define MM 256
#define GG 32           // BB*HH
#define TROWS 32768     // BB*NN
#define KSPL 8          // key splits for flash kv

#define FLASH_BUF (64 * 68 + 64 * 72)           // u32 per buffer
#define FLASH_SMEM (2 * FLASH_BUF * 4)          // bytes (71680)

// ---------------- static device scratch ----------------
__device__ float g_ln[(size_t)TROWS * DD];
__device__ float g_q[(size_t)GG * NN * DHH];
__device__ float g_k[(size_t)GG * NN * DHH];
__device__ float g_v[(size_t)GG * NN * DHH];
__device__ float g_ql[GG * MM * DHH];
__device__ float g_kl[GG * MM * DHH];
__device__ float g_s2[GG * MM * MM];
__device__ float g_a2[GG * MM * MM];
__device__ float g_zA[GG * MM * MM];
__device__ float g_zB[GG * MM * MM];
__device__ float g_t1[GG * MM * MM];
__device__ float g_t2[GG * MM * MM];
__device__ float g_t3[GG * MM * MM];
__device__ float g_po[(size_t)GG * KSPL * MM * DHH];
__device__ float2 g_pms[GG * KSPL * MM];
__device__ float g_kv[GG * MM * DHH];
__device__ float g_Dm[GG * MM * DHH];
__device__ float g_o1[(size_t)GG * NN * DHH];
__device__ float g_ao[(size_t)TROWS * DD];
__device__ float2 g_stat2[GG * MM];
__device__ int    g_scaleI[2];

// ---------------- helpers ----------------
__device__ __forceinline__ void cpa16(void* s, const void* g) {
    uint32_t sa = (uint32_t)__cvta_generic_to_shared(s);
    asm volatile("cp.async.cg.shared.global [%0], [%1], 16;" :: "r"(sa), "l"(g));
}
#define CP_COMMIT() asm volatile("cp.async.commit_group;")
#define CP_WAIT(n)  asm volatile("cp.async.wait_group %0;" :: "n"(n))

// mma.tf32 consumes raw fp32 bits (HW truncates low mantissa bits).
__device__ __forceinline__ void mma8(float* d, const uint32_t* a, const uint32_t* b) {
    asm volatile(
        "mma.sync.aligned.m16n8k8.row.col.f32.tf32.tf32.f32 "
        "{%0,%1,%2,%3}, {%4,%5,%6,%7}, {%8,%9}, {%0,%1,%2,%3};"
        : "+f"(d[0]), "+f"(d[1]), "+f"(d[2]), "+f"(d[3])
        : "r"(a[0]), "r"(a[1]), "r"(a[2]), "r"(a[3]), "r"(b[0]), "r"(b[1]));
}

// ---------------- layernorm ----------------
__global__ void ln_kernel(const float* __restrict__ x, const float* __restrict__ gamma,
                          const float* __restrict__ beta, float* __restrict__ out) {
    int row = blockIdx.x;
    const float* xr = x + (size_t)row * DD;
    int t = threadIdx.x;
    float v0 = xr[t], v1 = xr[t + 256];
    float s = v0 + v1, ss = v0 * v0 + v1 * v1;
    #pragma unroll
    for (int o = 16; o; o >>= 1) {
        s  += __shfl_down_sync(0xffffffffu, s, o);
        ss += __shfl_down_sync(0xffffffffu, ss, o);
    }
    __shared__ float rs[8], rss[8];
    int w = t >> 5, l = t & 31;
    if (l == 0) { rs[w] = s; rss[w] = ss; }
    __syncthreads();
    __shared__ float s_mu, s_rstd;
    if (t == 0) {
        float a = 0.f, b = 0.f;
        #pragma unroll
        for (int i = 0; i < 8; i++) { a += rs[i]; b += rss[i]; }
        float mu = a * (1.f / DD);
        float var = b * (1.f / DD) - mu * mu;
        s_mu = mu; s_rstd = rsqrtf(var + 1e-5f);
    }
    __syncthreads();
    float mu = s_mu, rstd = s_rstd;
    float* orow = out + (size_t)row * DD;
    orow[t]       = (v0 - mu) * rstd * gamma[t]       + beta[t];
    orow[t + 256] = (v1 - mu) * rstd * gamma[t + 256] + beta[t + 256];
}

// ---------------- tf32 NN gemm 128x128xK, cp.async double-buffered ----------
// MODE 0: C = A@B scattered into q/k/v head layout (q scaled 0.125)
// MODE 1: out = A@B + xres + bias
template <int MODE>
__global__ void __launch_bounds__(256) tgemm_nn(
        const float* __restrict__ A, const float* __restrict__ Bm,
        int Kdim, int Ncols,
        const float* __restrict__ xres, const float* __restrict__ bias,
        float* __restrict__ outp,
        float* __restrict__ oq, float* __restrict__ okk, float* __restrict__ ov) {
    __shared__ uint32_t As[2][128 * 20];   // [m][k] pad 4
    __shared__ uint32_t Bs[2][16 * 136];   // [k][n] pad 8
    int t = threadIdx.x;
    int warp = t >> 5, lane = t & 31;
    int wm = warp >> 2, wn = warp & 3;
    int g8 = lane >> 2, tg = lane & 3;
    int brow = blockIdx.y * 128, bcol = blockIdx.x * 128;
    float acc[4][4][4];
    #pragma unroll
    for (int i = 0; i < 4; i++)
        #pragma unroll
        for (int j = 0; j < 4; j++)
            #pragma unroll
            for (int r = 0; r < 4; r++) acc[i][j][r] = 0.f;

    int ar = t >> 2, akq = (t & 3) * 4;
    int bkr = t >> 5, bnq = (t & 31) * 4;

    {
        #pragma unroll
        for (int i = 0; i < 2; i++) {
            int r = ar + i * 64;
            cpa16(&As[0][r * 20 + akq], &A[(size_t)(brow + r) * Kdim + akq]);
        }
        #pragma unroll
        for (int i = 0; i < 2; i++) {
            int kr = bkr + i * 8;
            cpa16(&Bs[0][kr * 136 + bnq], &Bm[(size_t)kr * Ncols + bcol + bnq]);
        }
        CP_COMMIT();
    }

    int buf = 0;
    for (int k0 = 0; k0 < Kdim; k0 += 16) {
        if (k0 + 16 < Kdim) {
            int nb = buf ^ 1, kn = k0 + 16;
            #pragma unroll
            for (int i = 0; i < 2; i++) {
                int r = ar + i * 64;
                cpa16(&As[nb][r * 20 + akq], &A[(size_t)(brow + r) * Kdim + kn + akq]);
            }
            #pragma unroll
            for (int i = 0; i < 2; i++) {
                int kr = bkr + i * 8;
                cpa16(&Bs[nb][kr * 136 + bnq], &Bm[(size_t)(kn + kr) * Ncols + bcol + bnq]);
            }
            CP_COMMIT();
            CP_WAIT(1);
        } else {
            CP_WAIT(0);
        }
        __syncthreads();
        #pragma unroll
        for (int kk = 0; kk < 16; kk += 8) {
            uint32_t af[4][4], bf[4][2];
            #pragma unroll
            for (int mi = 0; mi < 4; mi++) {
                int rm = wm * 64 + mi * 16;
                af[mi][0] = As[buf][(rm + g8)     * 20 + kk + tg];
                af[mi][1] = As[buf][(rm + g8 + 8) * 20 + kk + tg];
                af[mi][2] = As[buf][(rm + g8)     * 20 + kk + tg + 4];
                af[mi][3] = As[buf][(rm + g8 + 8) * 20 + kk + tg + 4];
            }
            #pragma unroll
            for (int ni = 0; ni < 4; ni++) {
                int nb2 = wn * 32 + ni * 8 + g8;
                bf[ni][0] = Bs[buf][(kk + tg)     * 136 + nb2];
                bf[ni][1] = Bs[buf][(kk + tg + 4) * 136 + nb2];
            }
            #pragma unroll
            for (int mi = 0; mi < 4; mi++)
                #pragma unroll
                for (int ni = 0; ni < 4; ni++)
                    mma8(acc[mi][ni], af[mi], bf[ni]);
        }
        __syncthreads();
        buf ^= 1;
    }

    #pragma unroll
    for (int mi = 0; mi < 4; mi++) {
        #pragma unroll
        for (int ni = 0; ni < 4; ni++) {
            int c = bcol + wn * 32 + ni * 8 + tg * 2;
            #pragma unroll
            for (int half = 0; half < 2; half++) {
                int r = brow + wm * 64 + mi * 16 + g8 + half * 8;
                float v0 = acc[mi][ni][half * 2 + 0];
                float v1 = acc[mi][ni][half * 2 + 1];
                if (MODE == 0) {
                    int part = c >> 9, h = (c >> 6) & 7, d = c & 63;
                    int bidx = r >> 13, n = r & 8191;
                    size_t dst = (((size_t)(bidx * HH + h)) * NN + n) * DHH + d;
                    if (part == 0)      { oq[dst] = v0 * 0.125f; oq[dst + 1] = v1 * 0.125f; }
                    else if (part == 1) { okk[dst] = v0;         okk[dst + 1] = v1; }
                    else                { ov[dst] = v0;          ov[dst + 1] = v1; }
                } else {
                    size_t o = (size_t)r * Ncols + c;
                    outp[o]     = v0 + xres[o]     + bias[c];
                    outp[o + 1] = v1 + xres[o + 1] + bias[c + 1];
                }
            }
        }
    }
}

// ---------------- landmark means ----------------
__global__ void landmark_kernel(const float* __restrict__ q, const float* __restrict__ k,
                                float* __restrict__ ql, float* __restrict__ kl) {
    int g = blockIdx.y, m = blockIdx.x, d = threadIdx.x;
    const float* qp = q + ((size_t)g * NN + m * 32) * DHH + d;
    const float* kp = k + ((size_t)g * NN + m * 32) * DHH + d;
    float sq = 0.f, sk = 0.f;
    #pragma unroll
    for (int i = 0; i < 32; i++) { sq += qp[i * DHH]; sk += kp[i * DHH]; }
    ql[(g * MM + m) * DHH + d] = sq * (1.f / 32.f);
    kl[(g * MM + m) * DHH + d] = sk * (1.f / 32.f);
}

// ---------------- tf32 NT gemm over dh=64 (s2 only): C = A @ B^T -------------
__global__ void __launch_bounds__(256) tgemm_nt(
        const float* __restrict__ A, const float* __restrict__ Bm,
        float* __restrict__ C, int RA, int RB) {
    __shared__ uint32_t As[128 * 20];
    __shared__ uint32_t Bs[128 * 20];
    int t = threadIdx.x, g = blockIdx.z;
    int warp = t >> 5, lane = t & 31;
    int wm = warp >> 2, wn = warp & 3;
    int g8 = lane >> 2, tg = lane & 3;
    int gr0 = blockIdx.y * 128, gc0 = blockIdx.x * 128;
    float acc[4][4][4];
    #pragma unroll
    for (int i = 0; i < 4; i++)
        #pragma unroll
        for (int j = 0; j < 4; j++)
            #pragma unroll
            for (int r = 0; r < 4; r++) acc[i][j][r] = 0.f;

    for (int k0 = 0; k0 < 64; k0 += 16) {
        #pragma unroll
        for (int i = 0; i < 2; i++) {
            int s = t + i * 256;
            int r = s >> 2, kq = (s & 3) * 4;
            cpa16(&As[r * 20 + kq], &A[((size_t)g * RA + gr0 + r) * DHH + k0 + kq]);
            cpa16(&Bs[r * 20 + kq], &Bm[((size_t)g * RB + gc0 + r) * DHH + k0 + kq]);
        }
        CP_COMMIT();
        CP_WAIT(0);
        __syncthreads();
        #pragma unroll
        for (int kk = 0; kk < 16; kk += 8) {
            uint32_t af[4][4], bf[4][2];
            #pragma unroll
            for (int mi = 0; mi < 4; mi++) {
                int rm = wm * 64 + mi * 16;
                af[mi][0] = As[(rm + g8)     * 20 + kk + tg];
                af[mi][1] = As[(rm + g8 + 8) * 20 + kk + tg];
                af[mi][2] = As[(rm + g8)     * 20 + kk + tg + 4];
                af[mi][3] = As[(rm + g8 + 8) * 20 + kk + tg + 4];
            }
            #pragma unroll
            for (int ni = 0; ni < 4; ni++) {
                int nb = wn * 32 + ni * 8 + g8;
                bf[ni][0] = Bs[nb * 20 + kk + tg];
                bf[ni][1] = Bs[nb * 20 + kk + tg + 4];
            }
            #pragma unroll
            for (int mi = 0; mi < 4; mi++)
                #pragma unroll
                for (int ni = 0; ni < 4; ni++)
                    mma8(acc[mi][ni], af[mi], bf[ni]);
        }
        __syncthreads();
    }

    #pragma unroll
    for (int mi = 0; mi < 4; mi++) {
        #pragma unroll
        for (int ni = 0; ni < 4; ni++) {
            int c = gc0 + wn * 32 + ni * 8 + tg * 2;
            #pragma unroll
            for (int half = 0; half < 2; half++) {
                int r = gr0 + wm * 64 + mi * 16 + g8 + half * 8;
                size_t o = ((size_t)g * RA + r) * RB + c;
                *(float2*)&C[o] = make_float2(acc[mi][ni][half * 2 + 0],
                                              acc[mi][ni][half * 2 + 1]);
            }
        }
    }
}

// ---------------- fused flash: out = softmax(A@B^T) @ V, double-buffered ----
template <int NSPL>
__global__ void __launch_bounds__(256) flash_kernel(
        const float* __restrict__ Aq, const float* __restrict__ Bk,
        const float* __restrict__ Vv, float* __restrict__ outp,
        float2* __restrict__ pms, int RA, int RB) {
    extern __shared__ uint32_t smbuf[];   // 2 x (K:[64][68] + V:[64][72])
    int t = threadIdx.x, g = blockIdx.z, spl = blockIdx.y;
    int brow = blockIdx.x * 128;
    int warp = t >> 5, lane = t & 31, g8 = lane >> 2, tg = lane & 3;
    size_t gA = (size_t)g * RA, gB = (size_t)g * RB;
    int klen = RB / NSPL, kst = spl * klen;

    // stage Q (128x64) -> frags (uses start of buffer region)
    #pragma unroll
    for (int i = 0; i < 8; i++) {
        int s = t + i * 256; int r = s >> 4, c4 = (s & 15) * 4;
        cpa16(&smbuf[r * 68 + c4], &Aq[(gA + brow + r) * DHH + c4]);
    }
    CP_COMMIT();
    CP_WAIT(0);
    __syncthreads();
    uint32_t qf[8][4];
    {
        int r0 = (warp * 16 + g8) * 68, r1 = (warp * 16 + g8 + 8) * 68;
        #pragma unroll
        for (int kc = 0; kc < 8; kc++) {
            qf[kc][0] = smbuf[r0 + kc * 8 + tg];
            qf[kc][1] = smbuf[r1 + kc * 8 + tg];
            qf[kc][2] = smbuf[r0 + kc * 8 + tg + 4];
            qf[kc][3] = smbuf[r1 + kc * 8 + tg + 4];
        }
    }
    __syncthreads();

    int ldr = t >> 4, ldc4 = (t & 15) * 4;   // KV loader coords (4 iters of 16 rows)

    // prologue: stage KV tile 0 into buffer 0
    {
        uint32_t* Ks = smbuf;
        uint32_t* Vs = smbuf + 64 * 68;
        #pragma unroll
        for (int i = 0; i < 4; i++) {
            int r = ldr + i * 16;
            size_t src = (gB + kst + r) * DHH + ldc4;
            cpa16(&Ks[r * 68 + ldc4], &Bk[src]);
            cpa16(&Vs[r * 72 + ldc4], &Vv[src]);
        }
        CP_COMMIT();
    }

    float o[8][4];
    #pragma unroll
    for (int i = 0; i < 8; i++)
        #pragma unroll
        for (int j = 0; j < 4; j++) o[i][j] = 0.f;
    float m0 = -1e30f, m1 = -1e30f, l0 = 0.f, l1 = 0.f;
    int srcl = (lane & ~3) | (tg >> 1);

    int buf = 0;
    for (int kb = 0; kb < klen; kb += 64) {
        if (kb + 64 < klen) {
            uint32_t* Kn = smbuf + (buf ^ 1) * FLASH_BUF;
            uint32_t* Vn = Kn + 64 * 68;
            #pragma unroll
            for (int i = 0; i < 4; i++) {
                int r = ldr + i * 16;
                size_t src = (gB + kst + kb + 64 + r) * DHH + ldc4;
                cpa16(&Kn[r * 68 + ldc4], &Bk[src]);
                cpa16(&Vn[r * 72 + ldc4], &Vv[src]);
            }
            CP_COMMIT();
            CP_WAIT(1);
        } else {
            CP_WAIT(0);
        }
        __syncthreads();
        uint32_t* Ks = smbuf + buf * FLASH_BUF;
        uint32_t* Vs = Ks + 64 * 68;

        // S = Q @ K^T : 16 rows x 64 keys per warp
        float sv[8][4];
        #pragma unroll
        for (int nt = 0; nt < 8; nt++)
            #pragma unroll
            for (int j = 0; j < 4; j++) sv[nt][j] = 0.f;
        #pragma unroll
        for (int nt = 0; nt < 8; nt++) {
            #pragma unroll
            for (int kc = 0; kc < 8; kc++) {
                uint32_t bf[2];
                bf[0] = Ks[(nt * 8 + g8) * 68 + kc * 8 + tg];
                bf[1] = Ks[(nt * 8 + g8) * 68 + kc * 8 + tg + 4];
                mma8(sv[nt], qf[kc], bf);
            }
        }

        // online softmax (rows g8 and g8+8; quads share rows)
        float tm0 = -1e30f, tm1 = -1e30f;
        #pragma unroll
        for (int nt = 0; nt < 8; nt++) {
            tm0 = fmaxf(tm0, fmaxf(sv[nt][0], sv[nt][1]));
            tm1 = fmaxf(tm1, fmaxf(sv[nt][2], sv[nt][3]));
        }
        tm0 = fmaxf(tm0, __shfl_xor_sync(0xffffffffu, tm0, 1));
        tm0 = fmaxf(tm0, __shfl_xor_sync(0xffffffffu, tm0, 2));
        tm1 = fmaxf(tm1, __shfl_xor_sync(0xffffffffu, tm1, 1));
        tm1 = fmaxf(tm1, __shfl_xor_sync(0xffffffffu, tm1, 2));
        float m0n = fmaxf(m0, tm0), m1n = fmaxf(m1, tm1);
        float al0 = __expf(m0 - m0n), al1 = __expf(m1 - m1n);
        m0 = m0n; m1 = m1n;
        l0 *= al0; l1 *= al1;
        #pragma unroll
        for (int nv = 0; nv < 8; nv++) {
            o[nv][0] *= al0; o[nv][1] *= al0; o[nv][2] *= al1; o[nv][3] *= al1;
        }

        // P = exp(S - m); C-frag -> A-frag layout via quad shuffles
        uint32_t pf[8][4];
        #pragma unroll
        for (int nt = 0; nt < 8; nt++) {
            float p0 = __expf(sv[nt][0] - m0), p1 = __expf(sv[nt][1] - m0);
            float p2 = __expf(sv[nt][2] - m1), p3 = __expf(sv[nt][3] - m1);
            l0 += p0 + p1; l1 += p2 + p3;
            float e, od;
            e  = __shfl_sync(0xffffffffu, p0, srcl);
            od = __shfl_sync(0xffffffffu, p1, srcl);
            float a0v = (tg & 1) ? od : e;
            e  = __shfl_sync(0xffffffffu, p2, srcl);
            od = __shfl_sync(0xffffffffu, p3, srcl);
            float a1v = (tg & 1) ? od : e;
            e  = __shfl_sync(0xffffffffu, p0, srcl + 2);
            od = __shfl_sync(0xffffffffu, p1, srcl + 2);
            float a2v = (tg & 1) ? od : e;
            e  = __shfl_sync(0xffffffffu, p2, srcl + 2);
            od = __shfl_sync(0xffffffffu, p3, srcl + 2);
            float a3v = (tg & 1) ? od : e;
            pf[nt][0] = __float_as_uint(a0v); pf[nt][1] = __float_as_uint(a1v);
            pf[nt][2] = __float_as_uint(a2v); pf[nt][3] = __float_as_uint(a3v);
        }

        // O += P @ V
        #pragma unroll
        for (int nv = 0; nv < 8; nv++) {
            #pragma unroll
            for (int kc = 0; kc < 8; kc++) {
                uint32_t bf[2];
                bf[0] = Vs[(kc * 8 + tg) * 72 + nv * 8 + g8];
                bf[1] = Vs[(kc * 8 + tg + 4) * 72 + nv * 8 + g8];
                mma8(o[nv], pf[kc], bf);
            }
        }
        __syncthreads();
        buf ^= 1;
    }

    l0 += __shfl_xor_sync(0xffffffffu, l0, 1);
    l0 += __shfl_xor_sync(0xffffffffu, l0, 2);
    l1 += __shfl_xor_sync(0xffffffffu, l1, 1);
    l1 += __shfl_xor_sync(0xffffffffu, l1, 2);

    int lr0 = brow + warp * 16 + g8;
    if (NSPL == 1) {
        float i0 = 1.f / l0, i1 = 1.f / l1;
        #pragma unroll
        for (int nv = 0; nv < 8; nv++) {
            size_t oo = (gA + lr0) * DHH + nv * 8 + tg * 2;
            *(float2*)&outp[oo]            = make_float2(o[nv][0] * i0, o[nv][1] * i0);
            *(float2*)&outp[oo + 8 * DHH]  = make_float2(o[nv][2] * i1, o[nv][3] * i1);
        }
    } else {
        size_t pbase = (size_t)(g * NSPL + spl) * RA;
        #pragma unroll
        for (int nv = 0; nv < 8; nv++) {
            size_t oo = (pbase + lr0) * DHH + nv * 8 + tg * 2;
            *(float2*)&outp[oo]           = make_float2(o[nv][0], o[nv][1]);
            *(float2*)&outp[oo + 8 * DHH] = make_float2(o[nv][2], o[nv][3]);
        }
        if (tg == 0) {
            pms[pbase + lr0]     = make_float2(m0, l0);
            pms[pbase + lr0 + 8] = make_float2(m1, l1);
        }
    }
}

// combine KSPL flash partials -> g_kv
__global__ void flash_combine_kernel() {
    long long i = (long long)blockIdx.x * 256 + threadIdx.x;   // GG*MM*DHH
    int g = (int)(i / (MM * DHH));
    int rem = (int)(i % (MM * DHH));
    int row = rem / DHH, d = rem % DHH;
    float gm = -1e30f;
    float2 ms[KSPL];
    #pragma unroll
    for (int s = 0; s < KSPL; s++) {
        ms[s] = g_pms[(g * KSPL + s) * MM + row];
        gm = fmaxf(gm, ms[s].x);
    }
    float denom = 0.f, val = 0.f;
    #pragma unroll
    for (int s = 0; s < KSPL; s++) {
        float w = __expf(ms[s].x - gm);
        denom += ms[s].y * w;
        val += g_po[((size_t)(g * KSPL + s) * MM + row) * DHH + d] * w;
    }
    g_kv[i] = val / denom;
}

// ---------------- row softmax stats (s2 only) ----------------
__global__ void rowstat_kernel(const float* __restrict__ S, float2* __restrict__ stat, int NC) {
    long long row = blockIdx.x;
    const float* p = S + row * (long long)NC;
    int t = threadIdx.x;
    float tm = -1e30f, ts = 0.f;
    for (int c = t; c < NC; c += 256) {
        float v = p[c];
        if (v > tm) { ts = ts * __expf(tm - v) + 1.f; tm = v; }
        else ts += __expf(v - tm);
    }
    #pragma unroll
    for (int o = 16; o; o >>= 1) {
        float om = __shfl_down_sync(0xffffffffu, tm, o);
        float os = __shfl_down_sync(0xffffffffu, ts, o);
        float nm = fmaxf(tm, om);
        ts = ts * __expf(tm - nm) + os * __expf(om - nm);
        tm = nm;
    }
    __shared__ float smx[8], ssm[8];
    if ((t & 31) == 0) { smx[t >> 5] = tm; ssm[t >> 5] = ts; }
    __syncthreads();
    if (t == 0) {
        tm = smx[0]; ts = ssm[0];
        #pragma unroll
        for (int w = 1; w < 8; w++) {
            float om = smx[w], os = ssm[w];
            float nm = fmaxf(tm, om);
            ts = ts * __expf(tm - nm) + os * __expf(om - nm);
            tm = nm;
        }
        stat[row] = make_float2(tm, 1.f / ts);
    }
}

__global__ void apply_softmax_kernel(const float* __restrict__ S, const float2* __restrict__ stat,
                                     float* __restrict__ out) {
    long long i = (long long)blockIdx.x * 256 + threadIdx.x;
    float2 st = stat[i >> 8];
    out[i] = __expf(S[i] - st.x) * st.y;
}

// ---------------- pinv init ----------------
__global__ void zero_scale_kernel() { if (threadIdx.x < 2) g_scaleI[threadIdx.x] = 0; }

__global__ void pinv_reduce_kernel() {
    int g = blockIdx.x, j = threadIdx.x;
    const float* a = g_a2 + (long long)g * MM * MM;
    float rs = 0.f, cs = 0.f;
    for (int c = 0; c < MM; c++) { rs += a[j * MM + c]; cs += a[c * MM + j]; }
    __shared__ float r0[256], r1[256];
    r0[j] = rs; r1[j] = cs;
    __syncthreads();
    for (int o = 128; o; o >>= 1) {
        if (j < o) { r0[j] = fmaxf(r0[j], r0[j + o]); r1[j] = fmaxf(r1[j], r1[j + o]); }
        __syncthreads();
    }
    if (j == 0) {
        atomicMax(&g_scaleI[0], __float_as_int(r0[0]));
        atomicMax(&g_scaleI[1], __float_as_int(r1[0]));
    }
}

__global__ void z_init_kernel() {
    long long i = (long long)blockIdx.x * 256 + threadIdx.x;
    float scale = 1.f / (__int_as_float(g_scaleI[0]) * __int_as_float(g_scaleI[1]));
    int g = (int)(i >> 16), r = (int)((i >> 8) & 255), c = (int)(i & 255);
    g_zA[i] = g_a2[((long long)g << 16) + (c << 8) + r] * scale;
}

// ---------------- tf32 batched NS gemm: 128x128 tile, single wave -----------
// C = c0*I + c1 * ( A @ (b0*I + b1*B) );  A,B,C: [g][256][256]. grid (2,2,32)
__global__ void __launch_bounds__(256) tgemm_ns256(
        const float* __restrict__ A, const float* __restrict__ Bm,
        float* __restrict__ C,
        float b0c, float b1c, float c0c, float c1c) {
    __shared__ uint32_t As[2][128 * 20];
    __shared__ uint32_t Bs[2][16 * 136];
    int t = threadIdx.x, g = blockIdx.z;
    int warp = t >> 5, lane = t & 31;
    int wm = warp >> 2, wn = warp & 3;
    int g8 = lane >> 2, tg = lane & 3;
    int gr0 = blockIdx.y * 128, gc0 = blockIdx.x * 128;
    const float* Ag = A + (size_t)g * MM * MM;
    const float* Bg = Bm + (size_t)g * MM * MM;
    float acc[4][4][4];
    #pragma unroll
    for (int i = 0; i < 4; i++)
        #pragma unroll
        for (int j = 0; j < 4; j++)
            #pragma unroll
            for (int r = 0; r < 4; r++) acc[i][j][r] = 0.f;

    int ar = t >> 2, akq = (t & 3) * 4;
    int bkr = t >> 5, bnq = (t & 31) * 4;

    {
        #pragma unroll
        for (int i = 0; i < 2; i++) {
            int r = ar + i * 64;
            cpa16(&As[0][r * 20 + akq], &Ag[(size_t)(gr0 + r) * MM + akq]);
        }
        #pragma unroll
        for (int i = 0; i < 2; i++) {
            int kr = bkr + i * 8;
            cpa16(&Bs[0][kr * 136 + bnq], &Bg[(size_t)kr * MM + gc0 + bnq]);
        }
        CP_COMMIT();
    }

    int buf = 0;
    for (int k0 = 0; k0 < MM; k0 += 16) {
        if (k0 + 16 < MM) {
            int nb = buf ^ 1, kn = k0 + 16;
            #pragma unroll
            for (int i = 0; i < 2; i++) {
                int r = ar + i * 64;
                cpa16(&As[nb][r * 20 + akq], &Ag[(size_t)(gr0 + r) * MM + kn + akq]);
            }
            #pragma unroll
            for (int i = 0; i < 2; i++) {
                int kr = bkr + i * 8;
                cpa16(&Bs[nb][kr * 136 + bnq], &Bg[(size_t)(kn + kr) * MM + gc0 + bnq]);
            }
            CP_COMMIT();
            CP_WAIT(1);
        } else {
            CP_WAIT(0);
        }
        __syncthreads();
        #pragma unroll
        for (int kk = 0; kk < 16; kk += 8) {
            uint32_t af[4][4], bf[4][2];
            #pragma unroll
            for (int mi = 0; mi < 4; mi++) {
                int rm = wm * 64 + mi * 16;
                af[mi][0] = As[buf][(rm + g8)     * 20 + kk + tg];
                af[mi][1] = As[buf][(rm + g8 + 8) * 20 + kk + tg];
                af[mi][2] = As[buf][(rm + g8)     * 20 + kk + tg + 4];
                af[mi][3] = As[buf][(rm + g8 + 8) * 20 + kk + tg + 4];
            }
            #pragma unroll
            for (int ni = 0; ni < 4; ni++) {
                int nb2 = wn * 32 + ni * 8 + g8;
                float r0v = __uint_as_float(Bs[buf][(kk + tg)     * 136 + nb2]);
                float r1v = __uint_as_float(Bs[buf][(kk + tg + 4) * 136 + nb2]);
                int kg = k0 + kk + tg, cg = gc0 + nb2;
                float f0 = b1c * r0v + ((kg     == cg) ? b0c : 0.f);
                float f1 = b1c * r1v + ((kg + 4 == cg) ? b0c : 0.f);
                bf[ni][0] = __float_as_uint(f0);
                bf[ni][1] = __float_as_uint(f1);
            }
            #pragma unroll
            for (int mi = 0; mi < 4; mi++)
                #pragma unroll
                for (int ni = 0; ni < 4; ni++)
                    mma8(acc[mi][ni], af[mi], bf[ni]);
        }
        __syncthreads();
        buf ^= 1;
    }

    #pragma unroll
    for (int mi = 0; mi < 4; mi++) {
        #pragma unroll
        for (int ni = 0; ni < 4; ni++) {
            int c = gc0 + wn * 32 + ni * 8 + tg * 2;
            #pragma unroll
            for (int half = 0; half < 2; half++) {
                int r = gr0 + wm * 64 + mi * 16 + g8 + half * 8;
                float o0 = c1c * acc[mi][ni][half * 2 + 0] + (r == c     ? c0c : 0.f);
                float o1 = c1c * acc[mi][ni][half * 2 + 1] + (r == c + 1 ? c0c : 0.f);
                *(float2*)&C[((size_t)g * MM + r) * MM + c] = make_float2(o0, o1);
            }
        }
    }
}

// ---------------- tf32 batched 256-K gemm, BN=64 (Dm only) ------------------
__global__ void __launch_bounds__(256) tgemm_b256(
        const float* __restrict__ A, const float* __restrict__ Bm,
        float* __restrict__ C, int NC,
        float b0c, float b1c, float c0c, float c1c) {
    __shared__ uint32_t As[2][128 * 20];
    __shared__ uint32_t Bs[2][16 * 72];
    int t = threadIdx.x, g = blockIdx.z;
    int warp = t >> 5, lane = t & 31;
    int wm = warp >> 2, wn = warp & 3;
    int g8 = lane >> 2, tg = lane & 3;
    int gr0 = blockIdx.y * 128, gc0 = blockIdx.x * 64;
    const float* Ag = A + (size_t)g * MM * MM;
    const float* Bg = Bm + (size_t)g * MM * NC;
    float acc[4][2][4];
    #pragma unroll
    for (int i = 0; i < 4; i++)
        #pragma unroll
        for (int j = 0; j < 2; j++)
            #pragma unroll
            for (int r = 0; r < 4; r++) acc[i][j][r] = 0.f;

    int ar = t >> 2, akq = (t & 3) * 4;
    int bkr = t >> 4, bnq = (t & 15) * 4;

    {
        #pragma unroll
        for (int i = 0; i < 2; i++) {
            int r = ar + i * 64;
            cpa16(&As[0][r * 20 + akq], &Ag[(size_t)(gr0 + r) * MM + akq]);
        }
        cpa16(&Bs[0][bkr * 72 + bnq], &Bg[(size_t)bkr * NC + gc0 + bnq]);
        CP_COMMIT();
    }

    int buf = 0;
    for (int k0 = 0; k0 < MM; k0 += 16) {
        if (k0 + 16 < MM) {
            int nb = buf ^ 1, kn = k0 + 16;
            #pragma unroll
            for (int i = 0; i < 2; i++) {
                int r = ar + i * 64;
                cpa16(&As[nb][r * 20 + akq], &Ag[(size_t)(gr0 + r) * MM + kn + akq]);
            }
            cpa16(&Bs[nb][bkr * 72 + bnq], &Bg[(size_t)(kn + bkr) * NC + gc0 + bnq]);
            CP_COMMIT();
            CP_WAIT(1);
        } else {
            CP_WAIT(0);
        }
        __syncthreads();
        #pragma unroll
        for (int kk = 0; kk < 16; kk += 8) {
            uint32_t af[4][4], bf[2][2];
            #pragma unroll
            for (int mi = 0; mi < 4; mi++) {
                int rm = wm * 64 + mi * 16;
                af[mi][0] = As[buf][(rm + g8)     * 20 + kk + tg];
                af[mi][1] = As[buf][(rm + g8 + 8) * 20 + kk + tg];
                af[mi][2] = As[buf][(rm + g8)     * 20 + kk + tg + 4];
                af[mi][3] = As[buf][(rm + g8 + 8) * 20 + kk + tg + 4];
            }
            #pragma unroll
            for (int ni = 0; ni < 2; ni++) {
                int nb2 = wn * 16 + ni * 8 + g8;
                float r0v = __uint_as_float(Bs[buf][(kk + tg)     * 72 + nb2]);
                float r1v = __uint_as_float(Bs[buf][(kk + tg + 4) * 72 + nb2]);
                int kg = k0 + kk + tg, cg = gc0 + nb2;
                float f0 = b1c * r0v + ((kg     == cg) ? b0c : 0.f);
                float f1 = b1c * r1v + ((kg + 4 == cg) ? b0c : 0.f);
                bf[ni][0] = __float_as_uint(f0);
                bf[ni][1] = __float_as_uint(f1);
            }
            #pragma unroll
            for (int mi = 0; mi < 4; mi++)
                #pragma unroll
                for (int ni = 0; ni < 2; ni++)
                    mma8(acc[mi][ni], af[mi], bf[ni]);
        }
        __syncthreads();
        buf ^= 1;
    }

    #pragma unroll
    for (int mi = 0; mi < 4; mi++) {
        #pragma unroll
        for (int ni = 0; ni < 2; ni++) {
            int c = gc0 + wn * 16 + ni * 8 + tg * 2;
            #pragma unroll
            for (int half = 0; half < 2; half++) {
                int r = gr0 + wm * 64 + mi * 16 + g8 + half * 8;
                float o0 = c1c * acc[mi][ni][half * 2 + 0] + (r == c     ? c0c : 0.f);
                float o1 = c1c * acc[mi][ni][half * 2 + 1] + (r == c + 1 ? c0c : 0.f);
                *(float2*)&C[((size_t)g * MM + r) * NC + c] = make_float2(o0, o1);
            }
        }
    }
}

// ---------------- depthwise conv-33 over seq + head merge ----------------
__global__ void conv_combine_kernel(const float* __restrict__ v, const float* __restrict__ o1,
                                    const float* __restrict__ cw, float* __restrict__ ao) {
    int g = blockIdx.y;
    int h = g & 7, b = g >> 3;
    int n0 = blockIdx.x * 64;
    __shared__ float sv[96 * 64];
    __shared__ float ws[33];
    int t = threadIdx.x;
    if (t < 33) ws[t] = cw[h * 33 + t];
    const float* vg = v + (size_t)g * NN * DHH;
    for (int i = t; i < 96 * 64; i += 256) {
        int r = i >> 6, d = i & 63;
        int n = n0 - 16 + r;
        sv[i] = (n >= 0 && n < NN) ? vg[(size_t)n * DHH + d] : 0.f;
    }
    __syncthreads();
    int d = t & 63, nl0 = t >> 6;
    for (int i = 0; i < 16; i++) {
        int nl = nl0 + i * 4;
        float acc = 0.f;
        #pragma unroll
        for (int kk = 0; kk < 33; kk++) acc += ws[kk] * sv[(nl + kk) * 64 + d];
        int n = n0 + nl;
        ao[((size_t)b * NN + n) * DD + h * 64 + d] =
            o1[((size_t)g * NN + n) * DHH + d] + acc;
    }
}

// ---------------- host ----------------
static float* symf(const void* s) { void* p = 0; cudaGetSymbolAddress(&p, s); return (float*)p; }

extern "C" void kernel_launch(void* const* d_in, const int* in_sizes, int n_in,
                              void* d_out, int out_size) {
    const float* x      = (const float*)d_in[0];
    const float* gamma  = (const float*)d_in[1];
    const float* beta   = (const float*)d_in[2];
    const float* w_qkv  = (const float*)d_in[3];
    const float* w_out  = (const float*)d_in[4];
    const float* b_out  = (const float*)d_in[5];
    const float* conv_w = (const float*)d_in[6];
    float* out = (float*)d_out;

    float* ln   = symf(g_ln);
    float* q    = symf(g_q);
    float* k    = symf(g_k);
    float* v    = symf(g_v);
    float* ql   = symf(g_ql);
    float* kl   = symf(g_kl);
    float* s2   = symf(g_s2);
    float* a2   = symf(g_a2);
    float* zA   = symf(g_zA);
    float* zB   = symf(g_zB);
    float* t1   = symf(g_t1);
    float* t2   = symf(g_t2);
    float* t3   = symf(g_t3);
    float* po   = symf(g_po);
    float* kv   = symf(g_kv);
    float* Dm   = symf(g_Dm);
    float* o1   = symf(g_o1);
    float* ao   = symf(g_ao);
    float2* pms = (float2*)symf(g_pms);
    float2* st2 = (float2*)symf(g_stat2);

    // allow 70KB dynamic smem on flash kernels (attribute set is capture-safe)
    cudaFuncSetAttribute(flash_kernel<KSPL>, cudaFuncAttributeMaxDynamicSharedMemorySize, FLASH_SMEM);
    cudaFuncSetAttribute(flash_kernel<1>,    cudaFuncAttributeMaxDynamicSharedMemorySize, FLASH_SMEM);

    // 1. layernorm
    ln_kernel<<<TROWS, 256>>>(x, gamma, beta, ln);

    // 2. qkv gemm (tf32, cp.async) with head scatter + q scale
    tgemm_nn<0><<<dim3(12, 256), 256>>>(ln, w_qkv, DD, 3 * DD, 0, 0, 0, q, k, v);

    // 3. landmarks
    landmark_kernel<<<dim3(MM, GG), 64>>>(q, k, ql, kl);

    // 4. s2 = ql @ kl^T, softmax
    tgemm_nt<<<dim3(2, 2, GG), 256>>>(ql, kl, s2, MM, MM);
    rowstat_kernel<<<GG * MM, 256>>>(s2, st2, MM);
    apply_softmax_kernel<<<GG * MM * MM / 256, 256>>>(s2, st2, a2);

    // 5. pinv init: z = a2^T / (max rowsum * max colsum)
    zero_scale_kernel<<<1, 32>>>();
    pinv_reduce_kernel<<<GG, 256>>>();
    z_init_kernel<<<GG * MM * MM / 256, 256>>>();

    // 6. Newton-Schulz (tf32, 128 CTAs single wave per launch)
    for (int it = 0; it < 6; it++) {
        float* zin  = (it & 1) ? zB : zA;
        float* zout = (it & 1) ? zA : zB;
        tgemm_ns256<<<dim3(2, 2, GG), 256>>>(a2,  zin, t1, 0.f,  1.f, 0.f, 1.f);
        tgemm_ns256<<<dim3(2, 2, GG), 256>>>(t1,  t1,  t2, 7.f, -1.f, 0.f, 1.f);
        tgemm_ns256<<<dim3(2, 2, GG), 256>>>(t1,  t2,  t3, 15.f, -1.f, 0.f, 1.f);
        tgemm_ns256<<<dim3(2, 2, GG), 256>>>(zin, t3, zout, 13.f, -1.f, 0.f, 0.25f);
    }
    float* zfin = zA;  // after 6 iterations result is in zA

    // 7. kv = softmax(ql @ k^T) @ v  — fused flash, key-split 8, then combine
    flash_kernel<KSPL><<<dim3(2, KSPL, GG), 256, FLASH_SMEM>>>(ql, k, v, po, pms, MM, NN);
    flash_combine_kernel<<<GG * MM * DHH / 256, 256>>>();

    // 8. Dm = pinv @ kv  (tf32)
    tgemm_b256<<<dim3(1, 2, GG), 256>>>(zfin, kv, Dm, DHH, 0.f, 1.f, 0.f, 1.f);

    // 9. o1 = softmax(q @ kl^T) @ Dm — fused flash, no split
    flash_kernel<1><<<dim3(64, 1, GG), 256, FLASH_SMEM>>>(q, kl, Dm, o1, 0, NN, MM);

    // 10. conv residual + merge heads
    conv_combine_kernel<<<dim3(NN / 64, GG), 256>>>(v, o1, conv_w, ao);

    // 11. final: out = ao @ w_out + b_out + x  (tf32)
    tgemm_nn<1><<<dim3(4, 256), 256>>>(ao, w_out, DD, DD, x, b_out, out, 0, 0, 0);
}

// round 10
// speedup vs baseline: 3.7959x; 1.2638x over previous
#include <cuda_runtime.h>
#include <cuda_bf16.h>
#include <math.h>
#include <stdint.h>

#define BB 4
#define NN 8192
#define DD 512
#define HH 8
#define DHH 64
#define MM 256
#define GG 32           // BB*HH
#define TROWS 32768     // BB*NN
#define KSPL 8          // key splits for flash kv

#define ST 36                       // u32 stride for [row][32+4u32] bf16 tiles
#define FB (64 * ST)                // u32 per K or V flash buffer
#define FLASH_BUF (2 * FB)          // K+V per stage
#define FLASH_SMEM (2 * FLASH_BUF * 4)   // 36864 B (< 48K, no attribute needed)

// ---------------- static device scratch ----------------
__device__ __nv_bfloat16 g_lnb[(size_t)TROWS * DD];
__device__ __nv_bfloat16 g_qb[(size_t)GG * NN * DHH];
__device__ __nv_bfloat16 g_kb[(size_t)GG * NN * DHH];
__device__ __nv_bfloat16 g_vb[(size_t)GG * NN * DHH];
__device__ __nv_bfloat16 g_vTb[(size_t)GG * DHH * NN];
__device__ __nv_bfloat16 g_qlb[GG * MM * DHH];
__device__ __nv_bfloat16 g_klb[GG * MM * DHH];
__device__ __nv_bfloat16 g_aob[(size_t)TROWS * DD];
__device__ __nv_bfloat16 g_wqkvT[3 * DD * DD];
__device__ __nv_bfloat16 g_woutT[DD * DD];
__device__ __nv_bfloat16 g_DmT[GG * DHH * MM];

__device__ float g_s2[GG * MM * MM];
__device__ float g_a2[GG * MM * MM];
__device__ float g_zA[GG * MM * MM];
__device__ float g_zB[GG * MM * MM];
__device__ float g_t1[GG * MM * MM];
__device__ float g_t2[GG * MM * MM];
__device__ float g_t3[GG * MM * MM];
__device__ float g_po[(size_t)GG * KSPL * MM * DHH];
__device__ float2 g_pms[GG * KSPL * MM];
__device__ float g_kv[GG * MM * DHH];
__device__ float g_Dm[GG * MM * DHH];
__device__ float g_o1[(size_t)GG * NN * DHH];
__device__ float2 g_stat2[GG * MM];
__device__ int    g_scaleI[2];

// ---------------- helpers ----------------
__device__ __forceinline__ void cpa16(void* s, const void* g) {
    uint32_t sa = (uint32_t)__cvta_generic_to_shared(s);
    asm volatile("cp.async.cg.shared.global [%0], [%1], 16;" :: "r"(sa), "l"(g));
}
#define CP_COMMIT() asm volatile("cp.async.commit_group;")
#define CP_WAIT(n)  asm volatile("cp.async.wait_group %0;" :: "n"(n))

__device__ __forceinline__ void mma16(float* d, const uint32_t* a, const uint32_t* b) {
    asm volatile(
        "mma.sync.aligned.m16n8k16.row.col.f32.bf16.bf16.f32 "
        "{%0,%1,%2,%3}, {%4,%5,%6,%7}, {%8,%9}, {%0,%1,%2,%3};"
        : "+f"(d[0]), "+f"(d[1]), "+f"(d[2]), "+f"(d[3])
        : "r"(a[0]), "r"(a[1]), "r"(a[2]), "r"(a[3]), "r"(b[0]), "r"(b[1]));
}

// tf32 mma for Newton-Schulz path (raw fp32 bits; HW truncates)
__device__ __forceinline__ void mma8(float* d, const uint32_t* a, const uint32_t* b) {
    asm volatile(
        "mma.sync.aligned.m16n8k8.row.col.f32.tf32.tf32.f32 "
        "{%0,%1,%2,%3}, {%4,%5,%6,%7}, {%8,%9}, {%0,%1,%2,%3};"
        : "+f"(d[0]), "+f"(d[1]), "+f"(d[2]), "+f"(d[3])
        : "r"(a[0]), "r"(a[1]), "r"(a[2]), "r"(a[3]), "r"(b[0]), "r"(b[1]));
}

__device__ __forceinline__ uint32_t bpack(float lo, float hi) {
    __nv_bfloat162 h = __float22bfloat162_rn(make_float2(lo, hi));
    return *(uint32_t*)&h;
}

// ---------------- weight transpose+convert (bf16 [n][k]) ----------------
__global__ void convert_w_kernel(const float* __restrict__ wqkv, const float* __restrict__ wout) {
    int i = blockIdx.x * 256 + threadIdx.x;          // 4096*256 = 1048576
    if (i < 3 * DD * DD) {
        int n = i / DD, kk = i % DD;
        g_wqkvT[i] = __float2bfloat16(wqkv[kk * (3 * DD) + n]);
    } else {
        int j = i - 3 * DD * DD;
        int n = j / DD, kk = j % DD;
        g_woutT[j] = __float2bfloat16(wout[kk * DD + n]);
    }
}

// ---------------- layernorm -> bf16 ----------------
__global__ void ln_kernel(const float* __restrict__ x, const float* __restrict__ gamma,
                          const float* __restrict__ beta, __nv_bfloat16* __restrict__ out) {
    int row = blockIdx.x;
    const float* xr = x + (size_t)row * DD;
    int t = threadIdx.x;
    float v0 = xr[t], v1 = xr[t + 256];
    float s = v0 + v1, ss = v0 * v0 + v1 * v1;
    #pragma unroll
    for (int o = 16; o; o >>= 1) {
        s  += __shfl_down_sync(0xffffffffu, s, o);
        ss += __shfl_down_sync(0xffffffffu, ss, o);
    }
    __shared__ float rs[8], rss[8];
    int w = t >> 5, l = t & 31;
    if (l == 0) { rs[w] = s; rss[w] = ss; }
    __syncthreads();
    __shared__ float s_mu, s_rstd;
    if (t == 0) {
        float a = 0.f, b = 0.f;
        #pragma unroll
        for (int i = 0; i < 8; i++) { a += rs[i]; b += rss[i]; }
        float mu = a * (1.f / DD);
        float var = b * (1.f / DD) - mu * mu;
        s_mu = mu; s_rstd = rsqrtf(var + 1e-5f);
    }
    __syncthreads();
    float mu = s_mu, rstd = s_rstd;
    __nv_bfloat16* orow = out + (size_t)row * DD;
    orow[t]       = __float2bfloat16((v0 - mu) * rstd * gamma[t]       + beta[t]);
    orow[t + 256] = __float2bfloat16((v1 - mu) * rstd * gamma[t + 256] + beta[t + 256]);
}

// ---------------- bf16 NN gemm 128x128xK, A:[m][k], B(T):[n][k] -------------
// MODE 0: qkv scatter (q*0.125, k, v + vT). MODE 1: out = A@B + xres + bias.
template <int MODE>
__global__ void __launch_bounds__(256) tgemm_bnn(
        const __nv_bfloat16* __restrict__ A, const __nv_bfloat16* __restrict__ Bt,
        int Kdim, int Ncols,
        const float* __restrict__ xres, const float* __restrict__ bias,
        float* __restrict__ outp,
        __nv_bfloat16* __restrict__ oq, __nv_bfloat16* __restrict__ okk,
        __nv_bfloat16* __restrict__ ov, __nv_bfloat16* __restrict__ ovT) {
    __shared__ uint32_t As[2][128 * 12];     // [m][8 u32 = 16 bf16] + 4 pad
    __shared__ uint32_t Bs[2][128 * 12];     // [n][8 u32] + pad
    int t = threadIdx.x;
    int warp = t >> 5, lane = t & 31;
    int wm = warp >> 2, wn = warp & 3;
    int g8 = lane >> 2, tg = lane & 3;
    int brow = blockIdx.y * 128, bcol = blockIdx.x * 128;
    float acc[4][4][4];
    #pragma unroll
    for (int i = 0; i < 4; i++)
        #pragma unroll
        for (int j = 0; j < 4; j++)
            #pragma unroll
            for (int r = 0; r < 4; r++) acc[i][j][r] = 0.f;

    int lrow = t >> 1, lch = t & 1;          // 1 cpa per array per thread

    {
        cpa16(&As[0][lrow * 12 + lch * 4], &A[(size_t)(brow + lrow) * Kdim + lch * 8]);
        cpa16(&Bs[0][lrow * 12 + lch * 4], &Bt[(size_t)(bcol + lrow) * Kdim + lch * 8]);
        CP_COMMIT();
    }

    int buf = 0;
    for (int k0 = 0; k0 < Kdim; k0 += 16) {
        if (k0 + 16 < Kdim) {
            int nb = buf ^ 1, kn = k0 + 16;
            cpa16(&As[nb][lrow * 12 + lch * 4], &A[(size_t)(brow + lrow) * Kdim + kn + lch * 8]);
            cpa16(&Bs[nb][lrow * 12 + lch * 4], &Bt[(size_t)(bcol + lrow) * Kdim + kn + lch * 8]);
            CP_COMMIT();
            CP_WAIT(1);
        } else {
            CP_WAIT(0);
        }
        __syncthreads();
        uint32_t af[4][4], bf[4][2];
        #pragma unroll
        for (int mi = 0; mi < 4; mi++) {
            int rm = wm * 64 + mi * 16;
            af[mi][0] = As[buf][(rm + g8)     * 12 + tg];
            af[mi][1] = As[buf][(rm + g8 + 8) * 12 + tg];
            af[mi][2] = As[buf][(rm + g8)     * 12 + tg + 4];
            af[mi][3] = As[buf][(rm + g8 + 8) * 12 + tg + 4];
        }
        #pragma unroll
        for (int ni = 0; ni < 4; ni++) {
            int nb2 = wn * 32 + ni * 8 + g8;
            bf[ni][0] = Bs[buf][nb2 * 12 + tg];
            bf[ni][1] = Bs[buf][nb2 * 12 + tg + 4];
        }
        #pragma unroll
        for (int mi = 0; mi < 4; mi++)
            #pragma unroll
            for (int ni = 0; ni < 4; ni++)
                mma16(acc[mi][ni], af[mi], bf[ni]);
        __syncthreads();
        buf ^= 1;
    }

    #pragma unroll
    for (int mi = 0; mi < 4; mi++) {
        #pragma unroll
        for (int ni = 0; ni < 4; ni++) {
            int c = bcol + wn * 32 + ni * 8 + tg * 2;
            #pragma unroll
            for (int half = 0; half < 2; half++) {
                int r = brow + wm * 64 + mi * 16 + g8 + half * 8;
                float v0 = acc[mi][ni][half * 2 + 0];
                float v1 = acc[mi][ni][half * 2 + 1];
                if (MODE == 0) {
                    int part = c >> 9, h = (c >> 6) & 7, d = c & 63;
                    int bidx = r >> 13, n = r & 8191;
                    size_t dst = (((size_t)(bidx * HH + h)) * NN + n) * DHH + d;
                    if (part == 0) {
                        __nv_bfloat162 pr = __float22bfloat162_rn(make_float2(v0 * 0.125f, v1 * 0.125f));
                        *(__nv_bfloat162*)&oq[dst] = pr;
                    } else if (part == 1) {
                        __nv_bfloat162 pr = __float22bfloat162_rn(make_float2(v0, v1));
                        *(__nv_bfloat162*)&okk[dst] = pr;
                    } else {
                        __nv_bfloat162 pr = __float22bfloat162_rn(make_float2(v0, v1));
                        *(__nv_bfloat162*)&ov[dst] = pr;
                        size_t tb = ((size_t)(bidx * HH + h) * DHH + d) * NN + n;
                        ovT[tb]      = __float2bfloat16(v0);
                        ovT[tb + NN] = __float2bfloat16(v1);
                    }
                } else {
                    size_t o = (size_t)r * Ncols + c;
                    outp[o]     = v0 + xres[o]     + bias[c];
                    outp[o + 1] = v1 + xres[o + 1] + bias[c + 1];
                }
            }
        }
    }
}

// ---------------- landmark means (bf16 in/out) ----------------
__global__ void landmark_kernel(const __nv_bfloat16* __restrict__ q,
                                const __nv_bfloat16* __restrict__ k,
                                __nv_bfloat16* __restrict__ ql, __nv_bfloat16* __restrict__ kl) {
    int g = blockIdx.y, m = blockIdx.x, d = threadIdx.x;
    const __nv_bfloat16* qp = q + ((size_t)g * NN + m * 32) * DHH + d;
    const __nv_bfloat16* kp = k + ((size_t)g * NN + m * 32) * DHH + d;
    float sq = 0.f, sk = 0.f;
    #pragma unroll
    for (int i = 0; i < 32; i++) {
        sq += __bfloat162float(qp[i * DHH]);
        sk += __bfloat162float(kp[i * DHH]);
    }
    ql[(g * MM + m) * DHH + d] = __float2bfloat16(sq * (1.f / 32.f));
    kl[(g * MM + m) * DHH + d] = __float2bfloat16(sk * (1.f / 32.f));
}

// ---------------- bf16 NT gemm over d=64 (s2): C = A @ B^T ------------------
__global__ void __launch_bounds__(256) tgemm_ntb(
        const __nv_bfloat16* __restrict__ A, const __nv_bfloat16* __restrict__ Bm,
        float* __restrict__ C, int RA, int RB) {
    __shared__ uint32_t As[128 * ST];
    __shared__ uint32_t Bs[128 * ST];
    int t = threadIdx.x, g = blockIdx.z;
    int warp = t >> 5, lane = t & 31;
    int wm = warp >> 2, wn = warp & 3;
    int g8 = lane >> 2, tg = lane & 3;
    int gr0 = blockIdx.y * 128, gc0 = blockIdx.x * 128;
    float acc[4][4][4];
    #pragma unroll
    for (int i = 0; i < 4; i++)
        #pragma unroll
        for (int j = 0; j < 4; j++)
            #pragma unroll
            for (int r = 0; r < 4; r++) acc[i][j][r] = 0.f;

    #pragma unroll
    for (int i = 0; i < 4; i++) {
        int slot = t + i * 256;                       // 1024 chunks each
        int r = slot >> 3, ch = slot & 7;
        cpa16(&As[r * ST + ch * 4], &A[((size_t)g * RA + gr0 + r) * DHH + ch * 8]);
        cpa16(&Bs[r * ST + ch * 4], &Bm[((size_t)g * RB + gc0 + r) * DHH + ch * 8]);
    }
    CP_COMMIT();
    CP_WAIT(0);
    __syncthreads();

    #pragma unroll
    for (int kc = 0; kc < 4; kc++) {
        uint32_t af[4][4], bf[4][2];
        #pragma unroll
        for (int mi = 0; mi < 4; mi++) {
            int rm = wm * 64 + mi * 16;
            af[mi][0] = As[(rm + g8)     * ST + kc * 8 + tg];
            af[mi][1] = As[(rm + g8 + 8) * ST + kc * 8 + tg];
            af[mi][2] = As[(rm + g8)     * ST + kc * 8 + tg + 4];
            af[mi][3] = As[(rm + g8 + 8) * ST + kc * 8 + tg + 4];
        }
        #pragma unroll
        for (int ni = 0; ni < 4; ni++) {
            int nb = wn * 32 + ni * 8 + g8;
            bf[ni][0] = Bs[nb * ST + kc * 8 + tg];
            bf[ni][1] = Bs[nb * ST + kc * 8 + tg + 4];
        }
        #pragma unroll
        for (int mi = 0; mi < 4; mi++)
            #pragma unroll
            for (int ni = 0; ni < 4; ni++)
                mma16(acc[mi][ni], af[mi], bf[ni]);
    }

    #pragma unroll
    for (int mi = 0; mi < 4; mi++) {
        #pragma unroll
        for (int ni = 0; ni < 4; ni++) {
            int c = gc0 + wn * 32 + ni * 8 + tg * 2;
            #pragma unroll
            for (int half = 0; half < 2; half++) {
                int r = gr0 + wm * 64 + mi * 16 + g8 + half * 8;
                size_t o = ((size_t)g * RA + r) * RB + c;
                *(float2*)&C[o] = make_float2(acc[mi][ni][half * 2 + 0],
                                              acc[mi][ni][half * 2 + 1]);
            }
        }
    }
}

// ---------------- bf16 fused flash: out = softmax(A@B^T) @ V ---------------
// Aq:[g][RA][64], Bk:[g][RB][64] bf16; Vt: transposed V [g][64][RB] bf16.
template <int NSPL>
__global__ void __launch_bounds__(256) flashb_kernel(
        const __nv_bfloat16* __restrict__ Aq, const __nv_bfloat16* __restrict__ Bk,
        const __nv_bfloat16* __restrict__ Vt, float* __restrict__ outp,
        float2* __restrict__ pms, int RA, int RB) {
    extern __shared__ uint32_t smbuf[];        // 2 x (K [64][ST] + V [64][ST])
    int t = threadIdx.x, g = blockIdx.z, spl = blockIdx.y;
    int brow = blockIdx.x * 128;
    int warp = t >> 5, lane = t & 31, g8 = lane >> 2, tg = lane & 3;
    size_t gA = (size_t)g * RA, gB = (size_t)g * RB;
    size_t gV = (size_t)g * DHH;
    int klen = RB / NSPL, kst = spl * klen;

    // stage Q (128x64 bf16) -> frags
    #pragma unroll
    for (int i = 0; i < 4; i++) {
        int slot = t + i * 256;                // 1024 chunks
        int r = slot >> 3, ch = slot & 7;
        cpa16(&smbuf[r * ST + ch * 4], &Aq[(gA + brow + r) * DHH + ch * 8]);
    }
    CP_COMMIT();
    CP_WAIT(0);
    __syncthreads();
    uint32_t qf[4][4];
    {
        int r0 = (warp * 16 + g8) * ST, r1 = (warp * 16 + g8 + 8) * ST;
        #pragma unroll
        for (int kc = 0; kc < 4; kc++) {
            qf[kc][0] = smbuf[r0 + kc * 8 + tg];
            qf[kc][1] = smbuf[r1 + kc * 8 + tg];
            qf[kc][2] = smbuf[r0 + kc * 8 + tg + 4];
            qf[kc][3] = smbuf[r1 + kc * 8 + tg + 4];
        }
    }
    __syncthreads();

    // prologue: KV tile 0 -> buffer 0
    {
        uint32_t* Ks = smbuf;
        uint32_t* Vs = smbuf + FB;
        #pragma unroll
        for (int i = 0; i < 2; i++) {
            int slot = t + i * 256;            // 512 chunks each
            int r = slot >> 3, ch = slot & 7;
            cpa16(&Ks[r * ST + ch * 4], &Bk[(gB + kst + r) * DHH + ch * 8]);
            cpa16(&Vs[r * ST + ch * 4], &Vt[(gV + r) * RB + kst + ch * 8]);
        }
        CP_COMMIT();
    }

    float o[8][4];
    #pragma unroll
    for (int i = 0; i < 8; i++)
        #pragma unroll
        for (int j = 0; j < 4; j++) o[i][j] = 0.f;
    float m0 = -1e30f, m1 = -1e30f, l0 = 0.f, l1 = 0.f;

    int buf = 0;
    for (int kb = 0; kb < klen; kb += 64) {
        if (kb + 64 < klen) {
            uint32_t* Kn = smbuf + (buf ^ 1) * FLASH_BUF;
            uint32_t* Vn = Kn + FB;
            #pragma unroll
            for (int i = 0; i < 2; i++) {
                int slot = t + i * 256;
                int r = slot >> 3, ch = slot & 7;
                cpa16(&Kn[r * ST + ch * 4], &Bk[(gB + kst + kb + 64 + r) * DHH + ch * 8]);
                cpa16(&Vn[r * ST + ch * 4], &Vt[(gV + r) * RB + kst + kb + 64 + ch * 8]);
            }
            CP_COMMIT();
            CP_WAIT(1);
        } else {
            CP_WAIT(0);
        }
        __syncthreads();
        uint32_t* Ks = smbuf + buf * FLASH_BUF;
        uint32_t* Vs = Ks + FB;

        // S = Q @ K^T : 16 q-rows x 64 keys per warp (8 n-groups, 4 k16 steps)
        float sv[8][4];
        #pragma unroll
        for (int nt = 0; nt < 8; nt++)
            #pragma unroll
            for (int j = 0; j < 4; j++) sv[nt][j] = 0.f;
        #pragma unroll
        for (int nt = 0; nt < 8; nt++) {
            int kr = (nt * 8 + g8) * ST;
            #pragma unroll
            for (int kc = 0; kc < 4; kc++) {
                uint32_t b[2];
                b[0] = Ks[kr + kc * 8 + tg];
                b[1] = Ks[kr + kc * 8 + tg + 4];
                mma16(sv[nt], qf[kc], b);
            }
        }

        // online softmax
        float tm0 = -1e30f, tm1 = -1e30f;
        #pragma unroll
        for (int nt = 0; nt < 8; nt++) {
            tm0 = fmaxf(tm0, fmaxf(sv[nt][0], sv[nt][1]));
            tm1 = fmaxf(tm1, fmaxf(sv[nt][2], sv[nt][3]));
        }
        tm0 = fmaxf(tm0, __shfl_xor_sync(0xffffffffu, tm0, 1));
        tm0 = fmaxf(tm0, __shfl_xor_sync(0xffffffffu, tm0, 2));
        tm1 = fmaxf(tm1, __shfl_xor_sync(0xffffffffu, tm1, 1));
        tm1 = fmaxf(tm1, __shfl_xor_sync(0xffffffffu, tm1, 2));
        float m0n = fmaxf(m0, tm0), m1n = fmaxf(m1, tm1);
        float al0 = __expf(m0 - m0n), al1 = __expf(m1 - m1n);
        m0 = m0n; m1 = m1n;
        l0 *= al0; l1 *= al1;
        #pragma unroll
        for (int nv = 0; nv < 8; nv++) {
            o[nv][0] *= al0; o[nv][1] *= al0; o[nv][2] *= al1; o[nv][3] *= al1;
        }

        // P = exp(S - m) packed straight into bf16 A-frags (no shuffles)
        #pragma unroll
        for (int nt = 0; nt < 8; nt++) {
            sv[nt][0] = __expf(sv[nt][0] - m0);
            sv[nt][1] = __expf(sv[nt][1] - m0);
            sv[nt][2] = __expf(sv[nt][2] - m1);
            sv[nt][3] = __expf(sv[nt][3] - m1);
            l0 += sv[nt][0] + sv[nt][1];
            l1 += sv[nt][2] + sv[nt][3];
        }
        uint32_t pf[4][4];
        #pragma unroll
        for (int kc = 0; kc < 4; kc++) {
            pf[kc][0] = bpack(sv[2 * kc][0],     sv[2 * kc][1]);
            pf[kc][1] = bpack(sv[2 * kc][2],     sv[2 * kc][3]);
            pf[kc][2] = bpack(sv[2 * kc + 1][0], sv[2 * kc + 1][1]);
            pf[kc][3] = bpack(sv[2 * kc + 1][2], sv[2 * kc + 1][3]);
        }

        // O += P @ V  (V transposed in smem: rows d, cols keys)
        #pragma unroll
        for (int nv = 0; nv < 8; nv++) {
            int vr = (nv * 8 + g8) * ST;
            #pragma unroll
            for (int kc = 0; kc < 4; kc++) {
                uint32_t b[2];
                b[0] = Vs[vr + kc * 8 + tg];
                b[1] = Vs[vr + kc * 8 + tg + 4];
                mma16(o[nv], pf[kc], b);
            }
        }
        __syncthreads();
        buf ^= 1;
    }

    l0 += __shfl_xor_sync(0xffffffffu, l0, 1);
    l0 += __shfl_xor_sync(0xffffffffu, l0, 2);
    l1 += __shfl_xor_sync(0xffffffffu, l1, 1);
    l1 += __shfl_xor_sync(0xffffffffu, l1, 2);

    int lr0 = brow + warp * 16 + g8;
    if (NSPL == 1) {
        float i0 = 1.f / l0, i1 = 1.f / l1;
        #pragma unroll
        for (int nv = 0; nv < 8; nv++) {
            size_t oo = (gA + lr0) * DHH + nv * 8 + tg * 2;
            *(float2*)&outp[oo]           = make_float2(o[nv][0] * i0, o[nv][1] * i0);
            *(float2*)&outp[oo + 8 * DHH] = make_float2(o[nv][2] * i1, o[nv][3] * i1);
        }
    } else {
        size_t pbase = (size_t)(g * NSPL + spl) * RA;
        #pragma unroll
        for (int nv = 0; nv < 8; nv++) {
            size_t oo = (pbase + lr0) * DHH + nv * 8 + tg * 2;
            *(float2*)&outp[oo]           = make_float2(o[nv][0], o[nv][1]);
            *(float2*)&outp[oo + 8 * DHH] = make_float2(o[nv][2], o[nv][3]);
        }
        if (tg == 0) {
            pms[pbase + lr0]     = make_float2(m0, l0);
            pms[pbase + lr0 + 8] = make_float2(m1, l1);
        }
    }
}

// combine KSPL flash partials -> g_kv
__global__ void flash_combine_kernel() {
    long long i = (long long)blockIdx.x * 256 + threadIdx.x;   // GG*MM*DHH
    int g = (int)(i / (MM * DHH));
    int rem = (int)(i % (MM * DHH));
    int row = rem / DHH, d = rem % DHH;
    float gm = -1e30f;
    float2 ms[KSPL];
    #pragma unroll
    for (int s = 0; s < KSPL; s++) {
        ms[s] = g_pms[(g * KSPL + s) * MM + row];
        gm = fmaxf(gm, ms[s].x);
    }
    float denom = 0.f, val = 0.f;
    #pragma unroll
    for (int s = 0; s < KSPL; s++) {
        float w = __expf(ms[s].x - gm);
        denom += ms[s].y * w;
        val += g_po[((size_t)(g * KSPL + s) * MM + row) * DHH + d] * w;
    }
    g_kv[i] = val / denom;
}

// ---------------- row softmax stats (s2 only) ----------------
__global__ void rowstat_kernel(const float* __restrict__ S, float2* __restrict__ stat, int NC) {
    long long row = blockIdx.x;
    const float* p = S + row * (long long)NC;
    int t = threadIdx.x;
    float tm = -1e30f, ts = 0.f;
    for (int c = t; c < NC; c += 256) {
        float v = p[c];
        if (v > tm) { ts = ts * __expf(tm - v) + 1.f; tm = v; }
        else ts += __expf(v - tm);
    }
    #pragma unroll
    for (int o = 16; o; o >>= 1) {
        float om = __shfl_down_sync(0xffffffffu, tm, o);
        float os = __shfl_down_sync(0xffffffffu, ts, o);
        float nm = fmaxf(tm, om);
        ts = ts * __expf(tm - nm) + os * __expf(om - nm);
        tm = nm;
    }
    __shared__ float smx[8], ssm[8];
    if ((t & 31) == 0) { smx[t >> 5] = tm; ssm[t >> 5] = ts; }
    __syncthreads();
    if (t == 0) {
        tm = smx[0]; ts = ssm[0];
        #pragma unroll
        for (int w = 1; w < 8; w++) {
            float om = smx[w], os = ssm[w];
            float nm = fmaxf(tm, om);
            ts = ts * __expf(tm - nm) + os * __expf(om - nm);
            tm = nm;
        }
        stat[row] = make_float2(tm, 1.f / ts);
    }
}

__global__ void apply_softmax_kernel(const float* __restrict__ S, const float2* __restrict__ stat,
                                     float* __restrict__ out) {
    long long i = (long long)blockIdx.x * 256 + threadIdx.x;
    float2 st = stat[i >> 8];
    out[i] = __expf(S[i] - st.x) * st.y;
}

// ---------------- pinv init ----------------
__global__ void zero_scale_kernel() { if (threadIdx.x < 2) g_scaleI[threadIdx.x] = 0; }

__global__ void pinv_reduce_kernel() {
    int g = blockIdx.x, j = threadIdx.x;
    const float* a = g_a2 + (long long)g * MM * MM;
    float rs = 0.f, cs = 0.f;
    for (int c = 0; c < MM; c++) { rs += a[j * MM + c]; cs += a[c * MM + j]; }
    __shared__ float r0[256], r1[256];
    r0[j] = rs; r1[j] = cs;
    __syncthreads();
    for (int o = 128; o; o >>= 1) {
        if (j < o) { r0[j] = fmaxf(r0[j], r0[j + o]); r1[j] = fmaxf(r1[j], r1[j + o]); }
        __syncthreads();
    }
    if (j == 0) {
        atomicMax(&g_scaleI[0], __float_as_int(r0[0]));
        atomicMax(&g_scaleI[1], __float_as_int(r1[0]));
    }
}

__global__ void z_init_kernel() {
    long long i = (long long)blockIdx.x * 256 + threadIdx.x;
    float scale = 1.f / (__int_as_float(g_scaleI[0]) * __int_as_float(g_scaleI[1]));
    int g = (int)(i >> 16), r = (int)((i >> 8) & 255), c = (int)(i & 255);
    g_zA[i] = g_a2[((long long)g << 16) + (c << 8) + r] * scale;
}

// ---------------- tf32 batched NS gemm: 128x128, single wave ----------------
__global__ void __launch_bounds__(256) tgemm_ns256(
        const float* __restrict__ A, const float* __restrict__ Bm,
        float* __restrict__ C,
        float b0c, float b1c, float c0c, float c1c) {
    __shared__ uint32_t As[2][128 * 20];
    __shared__ uint32_t Bs[2][16 * 136];
    int t = threadIdx.x, g = blockIdx.z;
    int warp = t >> 5, lane = t & 31;
    int wm = warp >> 2, wn = warp & 3;
    int g8 = lane >> 2, tg = lane & 3;
    int gr0 = blockIdx.y * 128, gc0 = blockIdx.x * 128;
    const float* Ag = A + (size_t)g * MM * MM;
    const float* Bg = Bm + (size_t)g * MM * MM;
    float acc[4][4][4];
    #pragma unroll
    for (int i = 0; i < 4; i++)
        #pragma unroll
        for (int j = 0; j < 4; j++)
            #pragma unroll
            for (int r = 0; r < 4; r++) acc[i][j][r] = 0.f;

    int ar = t >> 2, akq = (t & 3) * 4;
    int bkr = t >> 5, bnq = (t & 31) * 4;

    {
        #pragma unroll
        for (int i = 0; i < 2; i++) {
            int r = ar + i * 64;
            cpa16(&As[0][r * 20 + akq], &Ag[(size_t)(gr0 + r) * MM + akq]);
        }
        #pragma unroll
        for (int i = 0; i < 2; i++) {
            int kr = bkr + i * 8;
            cpa16(&Bs[0][kr * 136 + bnq], &Bg[(size_t)kr * MM + gc0 + bnq]);
        }
        CP_COMMIT();
    }

    int buf = 0;
    for (int k0 = 0; k0 < MM; k0 += 16) {
        if (k0 + 16 < MM) {
            int nb = buf ^ 1, kn = k0 + 16;
            #pragma unroll
            for (int i = 0; i < 2; i++) {
                int r = ar + i * 64;
                cpa16(&As[nb][r * 20 + akq], &Ag[(size_t)(gr0 + r) * MM + kn + akq]);
            }
            #pragma unroll
            for (int i = 0; i < 2; i++) {
                int kr = bkr + i * 8;
                cpa16(&Bs[nb][kr * 136 + bnq], &Bg[(size_t)(kn + kr) * MM + gc0 + bnq]);
            }
            CP_COMMIT();
            CP_WAIT(1);
        } else {
            CP_WAIT(0);
        }
        __syncthreads();
        #pragma unroll
        for (int kk = 0; kk < 16; kk += 8) {
            uint32_t af[4][4], bf[4][2];
            #pragma unroll
            for (int mi = 0; mi < 4; mi++) {
                int rm = wm * 64 + mi * 16;
                af[mi][0] = As[buf][(rm + g8)     * 20 + kk + tg];
                af[mi][1] = As[buf][(rm + g8 + 8) * 20 + kk + tg];
                af[mi][2] = As[buf][(rm + g8)     * 20 + kk + tg + 4];
                af[mi][3] = As[buf][(rm + g8 + 8) * 20 + kk + tg + 4];
            }
            #pragma unroll
            for (int ni = 0; ni < 4; ni++) {
                int nb2 = wn * 32 + ni * 8 + g8;
                float r0v = __uint_as_float(Bs[buf][(kk + tg)     * 136 + nb2]);
                float r1v = __uint_as_float(Bs[buf][(kk + tg + 4) * 136 + nb2]);
                int kg = k0 + kk + tg, cg = gc0 + nb2;
                float f0 = b1c * r0v + ((kg     == cg) ? b0c : 0.f);
                float f1 = b1c * r1v + ((kg + 4 == cg) ? b0c : 0.f);
                bf[ni][0] = __float_as_uint(f0);
                bf[ni][1] = __float_as_uint(f1);
            }
            #pragma unroll
            for (int mi = 0; mi < 4; mi++)
                #pragma unroll
                for (int ni = 0; ni < 4; ni++)
                    mma8(acc[mi][ni], af[mi], bf[ni]);
        }
        __syncthreads();
        buf ^= 1;
    }

    #pragma unroll
    for (int mi = 0; mi < 4; mi++) {
        #pragma unroll
        for (int ni = 0; ni < 4; ni++) {
            int c = gc0 + wn * 32 + ni * 8 + tg * 2;
            #pragma unroll
            for (int half = 0; half < 2; half++) {
                int r = gr0 + wm * 64 + mi * 16 + g8 + half * 8;
                float o0 = c1c * acc[mi][ni][half * 2 + 0] + (r == c     ? c0c : 0.f);
                float o1 = c1c * acc[mi][ni][half * 2 + 1] + (r == c + 1 ? c0c : 0.f);
                *(float2*)&C[((size_t)g * MM + r) * MM + c] = make_float2(o0, o1);
            }
        }
    }
}

// ---------------- tf32 Dm gemm (z @ kv), writes Dm fp32 + DmT bf16 ----------
__global__ void __launch_bounds__(256) tgemm_b256(
        const float* __restrict__ A, const float* __restrict__ Bm,
        float* __restrict__ C, __nv_bfloat16* __restrict__ cT, int NC) {
    __shared__ uint32_t As[2][128 * 20];
    __shared__ uint32_t Bs[2][16 * 72];
    int t = threadIdx.x, g = blockIdx.z;
    int warp = t >> 5, lane = t & 31;
    int wm = warp >> 2, wn = warp & 3;
    int g8 = lane >> 2, tg = lane & 3;
    int gr0 = blockIdx.y * 128, gc0 = blockIdx.x * 64;
    const float* Ag = A + (size_t)g * MM * MM;
    const float* Bg = Bm + (size_t)g * MM * NC;
    float acc[4][2][4];
    #pragma unroll
    for (int i = 0; i < 4; i++)
        #pragma unroll
        for (int j = 0; j < 2; j++)
            #pragma unroll
            for (int r = 0; r < 4; r++) acc[i][j][r] = 0.f;

    int ar = t >> 2, akq = (t & 3) * 4;
    int bkr = t >> 4, bnq = (t & 15) * 4;

    {
        #pragma unroll
        for (int i = 0; i < 2; i++) {
            int r = ar + i * 64;
            cpa16(&As[0][r * 20 + akq], &Ag[(size_t)(gr0 + r) * MM + akq]);
        }
        cpa16(&Bs[0][bkr * 72 + bnq], &Bg[(size_t)bkr * NC + gc0 + bnq]);
        CP_COMMIT();
    }

    int buf = 0;
    for (int k0 = 0; k0 < MM; k0 += 16) {
        if (k0 + 16 < MM) {
            int nb = buf ^ 1, kn = k0 + 16;
            #pragma unroll
            for (int i = 0; i < 2; i++) {
                int r = ar + i * 64;
                cpa16(&As[nb][r * 20 + akq], &Ag[(size_t)(gr0 + r) * MM + kn + akq]);
            }
            cpa16(&Bs[nb][bkr * 72 + bnq], &Bg[(size_t)(kn + bkr) * NC + gc0 + bnq]);
            CP_COMMIT();
            CP_WAIT(1);
        } else {
            CP_WAIT(0);
        }
        __syncthreads();
        #pragma unroll
        for (int kk = 0; kk < 16; kk += 8) {
            uint32_t af[4][4], bf[2][2];
            #pragma unroll
            for (int mi = 0; mi < 4; mi++) {
                int rm = wm * 64 + mi * 16;
                af[mi][0] = As[buf][(rm + g8)     * 20 + kk + tg];
                af[mi][1] = As[buf][(rm + g8 + 8) * 20 + kk + tg];
                af[mi][2] = As[buf][(rm + g8)     * 20 + kk + tg + 4];
                af[mi][3] = As[buf][(rm + g8 + 8) * 20 + kk + tg + 4];
            }
            #pragma unroll
            for (int ni = 0; ni < 2; ni++) {
                int nb2 = wn * 16 + ni * 8 + g8;
                bf[ni][0] = Bs[buf][(kk + tg)     * 72 + nb2];
                bf[ni][1] = Bs[buf][(kk + tg + 4) * 72 + nb2];
            }
            #pragma unroll
            for (int mi = 0; mi < 4; mi++)
                #pragma unroll
                for (int ni = 0; ni < 2; ni++)
                    mma8(acc[mi][ni], af[mi], bf[ni]);
        }
        __syncthreads();
        buf ^= 1;
    }

    #pragma unroll
    for (int mi = 0; mi < 4; mi++) {
        #pragma unroll
        for (int ni = 0; ni < 2; ni++) {
            int c = gc0 + wn * 16 + ni * 8 + tg * 2;
            #pragma unroll
            for (int half = 0; half < 2; half++) {
                int r = gr0 + wm * 64 + mi * 16 + g8 + half * 8;
                float o0 = acc[mi][ni][half * 2 + 0];
                float o1 = acc[mi][ni][half * 2 + 1];
                *(float2*)&C[((size_t)g * MM + r) * NC + c] = make_float2(o0, o1);
                size_t tb = ((size_t)g * DHH + c) * MM + r;
                cT[tb]      = __float2bfloat16(o0);
                cT[tb + MM] = __float2bfloat16(o1);
            }
        }
    }
}

// ---------------- depthwise conv-33 + head merge (bf16 v, bf16 ao) ----------
__global__ void conv_combine_kernel(const __nv_bfloat16* __restrict__ v,
                                    const float* __restrict__ o1,
                                    const float* __restrict__ cw,
                                    __nv_bfloat16* __restrict__ ao) {
    int g = blockIdx.y;
    int h = g & 7, b = g >> 3;
    int n0 = blockIdx.x * 64;
    __shared__ float sv[96 * 64];
    __shared__ float ws[33];
    int t = threadIdx.x;
    if (t < 33) ws[t] = cw[h * 33 + t];
    const __nv_bfloat16* vg = v + (size_t)g * NN * DHH;
    for (int i = t; i < 96 * 64; i += 256) {
        int r = i >> 6, d = i & 63;
        int n = n0 - 16 + r;
        sv[i] = (n >= 0 && n < NN) ? __bfloat162float(vg[(size_t)n * DHH + d]) : 0.f;
    }
    __syncthreads();
    int d = t & 63, nl0 = t >> 6;
    for (int i = 0; i < 16; i++) {
        int nl = nl0 + i * 4;
        float acc = 0.f;
        #pragma unroll
        for (int kk = 0; kk < 33; kk++) acc += ws[kk] * sv[(nl + kk) * 64 + d];
        int n = n0 + nl;
        ao[((size_t)b * NN + n) * DD + h * 64 + d] =
            __float2bfloat16(o1[((size_t)g * NN + n) * DHH + d] + acc);
    }
}

// ---------------- host ----------------
static void* symp(const void* s) { void* p = 0; cudaGetSymbolAddress(&p, s); return p; }

extern "C" void kernel_launch(void* const* d_in, const int* in_sizes, int n_in,
                              void* d_out, int out_size) {
    const float* x      = (const float*)d_in[0];
    const float* gamma  = (const float*)d_in[1];
    const float* beta   = (const float*)d_in[2];
    const float* w_qkv  = (const float*)d_in[3];
    const float* w_out  = (const float*)d_in[4];
    const float* b_out  = (const float*)d_in[5];
    const float* conv_w = (const float*)d_in[6];
    float* out = (float*)d_out;

    __nv_bfloat16* lnb  = (__nv_bfloat16*)symp(g_lnb);
    __nv_bfloat16* qb   = (__nv_bfloat16*)symp(g_qb);
    __nv_bfloat16* kb   = (__nv_bfloat16*)symp(g_kb);
    __nv_bfloat16* vb   = (__nv_bfloat16*)symp(g_vb);
    __nv_bfloat16* vTb  = (__nv_bfloat16*)symp(g_vTb);
    __nv_bfloat16* qlb  = (__nv_bfloat16*)symp(g_qlb);
    __nv_bfloat16* klb  = (__nv_bfloat16*)symp(g_klb);
    __nv_bfloat16* aob  = (__nv_bfloat16*)symp(g_aob);
    __nv_bfloat16* wqT  = (__nv_bfloat16*)symp(g_wqkvT);
    __nv_bfloat16* woT  = (__nv_bfloat16*)symp(g_woutT);
    __nv_bfloat16* dmT  = (__nv_bfloat16*)symp(g_DmT);
    float* s2   = (float*)symp(g_s2);
    float* a2   = (float*)symp(g_a2);
    float* zA   = (float*)symp(g_zA);
    float* zB   = (float*)symp(g_zB);
    float* t1   = (float*)symp(g_t1);
    float* t2   = (float*)symp(g_t2);
    float* t3   = (float*)symp(g_t3);
    float* po   = (float*)symp(g_po);
    float* kv   = (float*)symp(g_kv);
    float* Dm   = (float*)symp(g_Dm);
    float* o1   = (float*)symp(g_o1);
    float2* pms = (float2*)symp(g_pms);
    float2* st2 = (float2*)symp(g_stat2);

    // 0. weights -> bf16 transposed
    convert_w_kernel<<<4096, 256>>>(w_qkv, w_out);

    // 1. layernorm -> bf16
    ln_kernel<<<TROWS, 256>>>(x, gamma, beta, lnb);

    // 2. qkv gemm (bf16) with head scatter + q scale + vT
    tgemm_bnn<0><<<dim3(12, 256), 256>>>(lnb, wqT, DD, 3 * DD, 0, 0, 0, qb, kb, vb, vTb);

    // 3. landmarks
    landmark_kernel<<<dim3(MM, GG), 64>>>(qb, kb, qlb, klb);

    // 4. s2 = ql @ kl^T (bf16), softmax
    tgemm_ntb<<<dim3(2, 2, GG), 256>>>(qlb, klb, s2, MM, MM);
    rowstat_kernel<<<GG * MM, 256>>>(s2, st2, MM);
    apply_softmax_kernel<<<GG * MM * MM / 256, 256>>>(s2, st2, a2);

    // 5. pinv init
    zero_scale_kernel<<<1, 32>>>();
    pinv_reduce_kernel<<<GG, 256>>>();
    z_init_kernel<<<GG * MM * MM / 256, 256>>>();

    // 6. Newton-Schulz (tf32, single-wave launches)
    for (int it = 0; it < 6; it++) {
        float* zin  = (it & 1) ? zB : zA;
        float* zout = (it & 1) ? zA : zB;
        tgemm_ns256<<<dim3(2, 2, GG), 256>>>(a2,  zin, t1, 0.f,  1.f, 0.f, 1.f);
        tgemm_ns256<<<dim3(2, 2, GG), 256>>>(t1,  t1,  t2, 7.f, -1.f, 0.f, 1.f);
        tgemm_ns256<<<dim3(2, 2, GG), 256>>>(t1,  t2,  t3, 15.f, -1.f, 0.f, 1.f);
        tgemm_ns256<<<dim3(2, 2, GG), 256>>>(zin, t3, zout, 13.f, -1.f, 0.f, 0.25f);
    }
    float* zfin = zA;

    // 7. kv = softmax(ql @ k^T) @ v  — bf16 flash, key-split 8, combine
    flashb_kernel<KSPL><<<dim3(2, KSPL, GG), 256, FLASH_SMEM>>>(qlb, kb, vTb, po, pms, MM, NN);
    flash_combine_kernel<<<GG * MM * DHH / 256, 256>>>();

    // 8. Dm = pinv @ kv (tf32), also DmT bf16
    tgemm_b256<<<dim3(1, 2, GG), 256>>>(zfin, kv, Dm, dmT, DHH);

    // 9. o1 = softmax(q @ kl^T) @ Dm — bf16 flash
    flashb_kernel<1><<<dim3(64, 1, GG), 256, FLASH_SMEM>>>(qb, klb, dmT, o1, 0, NN, MM);

    // 10. conv residual + merge heads -> bf16 ao
    conv_combine_kernel<<<dim3(NN / 64, GG), 256>>>(vb, o1, conv_w, aob);

    // 11. final: out = ao @ w_out + b_out + x (bf16 gemm, fp32 epilogue)
    tgemm_bnn<1><<<dim3(4, 256), 256>>>(aob, woT, DD, DD, x, b_out, out, 0, 0, 0, 0);
}